// round 7
// baseline (speedup 1.0000x reference)
#include <cuda_runtime.h>
#include <cuda_bf16.h>
#include <math.h>
#include <stdint.h>

#define S_LEN 2048
#define HID   2048
#define NH    32
#define NKV   8
#define HD    64
#define KVW   1024
#define NQKV  3072

// ---------------- scratch ----------------
__device__ float g_q [S_LEN * HID];
__device__ float g_kv[S_LEN * KVW];

// int8 quantized operands for QKV projection
__device__ int8_t g_Xh8[S_LEN * HID], g_Xl8[S_LEN * HID];
__device__ float  g_sx[S_LEN];
__device__ int8_t g_Wh8[NQKV * HID], g_Wl8[NQKV * HID];   // [N][K] transposed
__device__ float  g_ts[NQKV];
__device__ float  g_pmax[16 * NQKV];

// bf16 operands for O-proj
__device__ __nv_bfloat16 g_Wohi[HID * HID], g_Wolo[HID * HID];
__device__ __nv_bfloat16 g_Ahi [S_LEN * HID], g_Alo [S_LEN * HID];

// attention operands (bf16 hi/lo after RoPE)
__device__ __nv_bfloat16 g_qh[S_LEN * HID], g_ql[S_LEN * HID];
__device__ __nv_bfloat16 g_kh[S_LEN * 512], g_kl[S_LEN * 512];
__device__ __nv_bfloat16 g_vh[S_LEN * 512], g_vl[S_LEN * 512];

// ---------------- helpers ----------------
__device__ __forceinline__ uint32_t sptr(const void* p) {
    return (uint32_t)__cvta_generic_to_shared(p);
}
__device__ __forceinline__ void cp16(uint32_t dst, const void* src) {
    asm volatile("cp.async.cg.shared.global [%0], [%1], 16;\n" :: "r"(dst), "l"(src));
}
__device__ __forceinline__ void ldsm_x4(uint32_t* r, uint32_t addr) {
    asm volatile("ldmatrix.sync.aligned.m8n8.x4.shared.b16 {%0,%1,%2,%3}, [%4];\n"
        : "=r"(r[0]), "=r"(r[1]), "=r"(r[2]), "=r"(r[3]) : "r"(addr));
}
__device__ __forceinline__ void ldsm_x4_t(uint32_t* r, uint32_t addr) {
    asm volatile("ldmatrix.sync.aligned.m8n8.x4.trans.shared.b16 {%0,%1,%2,%3}, [%4];\n"
        : "=r"(r[0]), "=r"(r[1]), "=r"(r[2]), "=r"(r[3]) : "r"(addr));
}
__device__ __forceinline__ void mma16816(float* c, const uint32_t* a, const uint32_t* b) {
    asm volatile(
        "mma.sync.aligned.m16n8k16.row.col.f32.bf16.bf16.f32 "
        "{%0,%1,%2,%3}, {%4,%5,%6,%7}, {%8,%9}, {%0,%1,%2,%3};\n"
        : "+f"(c[0]), "+f"(c[1]), "+f"(c[2]), "+f"(c[3])
        : "r"(a[0]), "r"(a[1]), "r"(a[2]), "r"(a[3]), "r"(b[0]), "r"(b[1]));
}
__device__ __forceinline__ void imma16832(int* c, const uint32_t* a, const uint32_t* b) {
    asm volatile(
        "mma.sync.aligned.m16n8k32.row.col.s32.s8.s8.s32 "
        "{%0,%1,%2,%3}, {%4,%5,%6,%7}, {%8,%9}, {%0,%1,%2,%3};\n"
        : "+r"(c[0]), "+r"(c[1]), "+r"(c[2]), "+r"(c[3])
        : "r"(a[0]), "r"(a[1]), "r"(a[2]), "r"(a[3]), "r"(b[0]), "r"(b[1]));
}
__device__ __forceinline__ uint32_t packbf2(float x, float y) {
    __nv_bfloat162 h = __floats2bfloat162_rn(x, y);
    return *(uint32_t*)&h;
}
__device__ __forceinline__ void q16(float x, float inv, int& h, int& l) {
    float af = fminf(fmaxf(rintf(x * inv), -32512.f), 32512.f);
    int a = (int)af;
    l = (a << 24) >> 24;            // sign-extended low byte
    h = (a - l) >> 8;
}

// ---------------- quantization kernels ----------------
__global__ __launch_bounds__(256) void xquant_k(
    const float* __restrict__ X, int8_t* __restrict__ h8,
    int8_t* __restrict__ l8, float* __restrict__ sx)
{
    __shared__ float red[256];
    const int row = blockIdx.x, t = threadIdx.x;
    const float* p = X + (size_t)row * HID;
    float4 f0 = *(const float4*)(p + t * 8);
    float4 f1 = *(const float4*)(p + t * 8 + 4);
    float mx = fmaxf(fmaxf(fmaxf(fabsf(f0.x), fabsf(f0.y)), fmaxf(fabsf(f0.z), fabsf(f0.w))),
                     fmaxf(fmaxf(fabsf(f1.x), fabsf(f1.y)), fmaxf(fabsf(f1.z), fabsf(f1.w))));
    red[t] = mx;
    __syncthreads();
    #pragma unroll
    for (int s = 128; s > 0; s >>= 1) {
        if (t < s) red[t] = fmaxf(red[t], red[t + s]);
        __syncthreads();
    }
    float rmax = fmaxf(red[0], 1e-20f);
    float inv = 32512.f / rmax;
    if (t == 0) sx[row] = rmax * (1.f / 32512.f);

    float v[8] = {f0.x, f0.y, f0.z, f0.w, f1.x, f1.y, f1.z, f1.w};
    unsigned long long uh = 0, ul = 0;
    #pragma unroll
    for (int i = 0; i < 8; i++) {
        int h, l;
        q16(v[i], inv, h, l);
        uh |= (unsigned long long)(uint8_t)h << (8 * i);
        ul |= (unsigned long long)(uint8_t)l << (8 * i);
    }
    ((unsigned long long*)h8)[(size_t)row * 256 + t] = uh;
    ((unsigned long long*)l8)[(size_t)row * 256 + t] = ul;
}

__global__ __launch_bounds__(256) void colmax_k(
    const float* __restrict__ W, float* __restrict__ pmax, int N, int coloff)
{
    int n = blockIdx.x * 256 + threadIdx.x;
    int k0 = blockIdx.y * (HID / 16);
    float m = 0.f;
    for (int k = k0; k < k0 + HID / 16; k++)
        m = fmaxf(m, fabsf(W[(size_t)k * N + n]));
    pmax[blockIdx.y * NQKV + coloff + n] = m;
}

// transpose + quantize: W [K,N] -> h8/l8 rows at coloff (layout [NQKV][K])
__global__ __launch_bounds__(256) void wquant_t(
    const float* __restrict__ W, const float* __restrict__ pmax,
    int8_t* __restrict__ h8, int8_t* __restrict__ l8, float* __restrict__ ts,
    int N, int coloff)
{
    __shared__ float sT[32][33];
    __shared__ float sInv[32];
    const int t = threadIdx.x;
    const int n0 = blockIdx.x * 32, k0 = blockIdx.y * 32;
    #pragma unroll
    for (int i = 0; i < 4; i++) {
        int idx = i * 256 + t, r = idx >> 5, c = idx & 31;
        sT[r][c] = W[(size_t)(k0 + r) * N + n0 + c];
    }
    if (t < 32) {
        float m = 0.f;
        #pragma unroll
        for (int j = 0; j < 16; j++)
            m = fmaxf(m, pmax[j * NQKV + coloff + n0 + t]);
        m = fmaxf(m, 1e-20f);
        sInv[t] = 32512.f / m;
        if (blockIdx.y == 0) ts[coloff + n0 + t] = m * (1.f / 32512.f);
    }
    __syncthreads();
    #pragma unroll
    for (int i = 0; i < 4; i++) {
        int idx = i * 256 + t, r = idx >> 5, c = idx & 31;
        float x = sT[c][r];
        int h, l;
        q16(x, sInv[r], h, l);
        size_t o = (size_t)(coloff + n0 + r) * HID + k0 + c;
        h8[o] = (int8_t)h;
        l8[o] = (int8_t)l;
    }
}

// ---------------- IMMA GEMM: 64x64 CTA, 4 warps (32x32), BK=64, 2-stage ----------------
#define IROW 80                          // 64B data + 16B pad
#define IA_H 0
#define IA_L (64 * IROW)                 // 5120
#define IB_H (2 * 64 * IROW)             // 10240
#define IB_L (3 * 64 * IROW)             // 15360
#define ISTAGE (4 * 64 * IROW)           // 20480
#define IMMA_SMEM (2 * ISTAGE)           // 40960

__device__ __forceinline__ void iload_tile(
    uint32_t sb, const int8_t* __restrict__ Xh, const int8_t* __restrict__ Xl,
    const int8_t* __restrict__ Wh, const int8_t* __restrict__ Wl,
    int m0, int n0, int k0, int t)
{
    #pragma unroll
    for (int i = 0; i < 2; i++) {            // A: 64 rows x 4 chunks
        int idx = i * 128 + t;
        int row = idx >> 2, ch = idx & 3;
        uint32_t so = (uint32_t)(row * IROW + ch * 16);
        size_t g = (size_t)(m0 + row) * HID + k0 + ch * 16;
        cp16(sb + IA_H + so, Xh + g);
        cp16(sb + IA_L + so, Xl + g);
    }
    #pragma unroll
    for (int i = 0; i < 2; i++) {            // B: 64 rows x 4 chunks
        int idx = i * 128 + t;
        int row = idx >> 2, ch = idx & 3;
        uint32_t so = (uint32_t)(row * IROW + ch * 16);
        size_t g = (size_t)(n0 + row) * HID + k0 + ch * 16;
        cp16(sb + IB_H + so, Wh + g);
        cp16(sb + IB_L + so, Wl + g);
    }
}

__global__ __launch_bounds__(128, 2) void imma_gemm(
    const int8_t* __restrict__ Xh, const int8_t* __restrict__ Xl,
    const int8_t* __restrict__ Wh, const int8_t* __restrict__ Wl,
    const float* __restrict__ sx, const float* __restrict__ ts,
    float* __restrict__ Cq, float* __restrict__ Ckv)
{
    extern __shared__ __align__(128) char ism[];
    const uint32_t sb = sptr(ism);
    const int t = threadIdx.x, lane = t & 31, w = t >> 5;
    const int wm = w >> 1, wn = w & 1;          // 2x2 warps, 32x32 tiles
    const int m0 = blockIdx.y * 64, n0 = blockIdx.x * 64;
    const int l8 = lane & 7;

    int acc_hh[2][4][4], acc_x[2][4][4];
    #pragma unroll
    for (int i = 0; i < 2; i++)
        #pragma unroll
        for (int j = 0; j < 4; j++)
            #pragma unroll
            for (int r = 0; r < 4; r++) { acc_hh[i][j][r] = 0; acc_x[i][j][r] = 0; }

    iload_tile(sb, Xh, Xl, Wh, Wl, m0, n0, 0, t);
    asm volatile("cp.async.commit_group;\n");

    const int nk = HID / 64;
    for (int kt = 0; kt < nk; kt++) {
        const uint32_t buf = sb + (uint32_t)(kt & 1) * ISTAGE;
        if (kt + 1 < nk) {
            iload_tile(sb + (uint32_t)((kt + 1) & 1) * ISTAGE,
                       Xh, Xl, Wh, Wl, m0, n0, (kt + 1) * 64, t);
            asm volatile("cp.async.commit_group;\n");
            asm volatile("cp.async.wait_group 1;\n");
        } else {
            asm volatile("cp.async.wait_group 0;\n");
        }
        __syncthreads();

        #pragma unroll
        for (int kc = 0; kc < 2; kc++) {
            uint32_t ah[2][4], al[2][4], bh[4][2], bl[4][2];
            // A frags: m-groups 0..1, full k32 per ldsm.x4
            #pragma unroll
            for (int mg = 0; mg < 2; mg++) {
                uint32_t off = (uint32_t)((wm * 32 + mg * 16 + ((lane >> 3) & 1) * 8 + l8) * IROW
                                          + kc * 32 + (lane >> 4) * 16);
                ldsm_x4(ah[mg], buf + IA_H + off);
                ldsm_x4(al[mg], buf + IA_L + off);
            }
            // B frags: each ldsm.x4 covers 2 n-groups for one k32
            #pragma unroll
            for (int bg = 0; bg < 2; bg++) {
                uint32_t off = (uint32_t)((wn * 32 + bg * 16 + ((lane >> 4) & 1) * 8 + l8) * IROW
                                          + kc * 32 + ((lane >> 3) & 1) * 16);
                uint32_t r4[4];
                ldsm_x4(r4, buf + IB_H + off);
                bh[2 * bg][0] = r4[0]; bh[2 * bg][1] = r4[1];
                bh[2 * bg + 1][0] = r4[2]; bh[2 * bg + 1][1] = r4[3];
                ldsm_x4(r4, buf + IB_L + off);
                bl[2 * bg][0] = r4[0]; bl[2 * bg][1] = r4[1];
                bl[2 * bg + 1][0] = r4[2]; bl[2 * bg + 1][1] = r4[3];
            }
            #pragma unroll
            for (int mg = 0; mg < 2; mg++)
                #pragma unroll
                for (int ng = 0; ng < 4; ng++) {
                    imma16832(acc_hh[mg][ng], ah[mg], bh[ng]);
                    imma16832(acc_x [mg][ng], ah[mg], bl[ng]);
                    imma16832(acc_x [mg][ng], al[mg], bh[ng]);
                }
        }
        __syncthreads();
    }

    // epilogue: C = sx[m] * ts[n] * (65536*hh + 256*x)
    #pragma unroll
    for (int mg = 0; mg < 2; mg++) {
        int row = m0 + wm * 32 + mg * 16 + (lane >> 2);
        float sm0 = sx[row], sm1 = sx[row + 8];
        #pragma unroll
        for (int ng = 0; ng < 4; ng++) {
            int cg = n0 + wn * 32 + ng * 8 + (lane & 3) * 2;
            float t0 = ts[cg], t1 = ts[cg + 1];
            float v00 = sm0 * t0 * (65536.f * (float)acc_hh[mg][ng][0] + 256.f * (float)acc_x[mg][ng][0]);
            float v01 = sm0 * t1 * (65536.f * (float)acc_hh[mg][ng][1] + 256.f * (float)acc_x[mg][ng][1]);
            float v10 = sm1 * t0 * (65536.f * (float)acc_hh[mg][ng][2] + 256.f * (float)acc_x[mg][ng][2]);
            float v11 = sm1 * t1 * (65536.f * (float)acc_hh[mg][ng][3] + 256.f * (float)acc_x[mg][ng][3]);
            float* Cp; int ldc, cb;
            if (cg < 2048) { Cp = Cq;  ldc = HID; cb = cg; }
            else           { Cp = Ckv; ldc = KVW; cb = cg - 2048; }
            *(float2*)&Cp[(size_t)row * ldc + cb]       = make_float2(v00, v01);
            *(float2*)&Cp[(size_t)(row + 8) * ldc + cb] = make_float2(v10, v11);
        }
    }
}

// ---------------- bf16 splits (Wo only) ----------------
__global__ void split_k(const float* __restrict__ in,
                        __nv_bfloat16* __restrict__ hi,
                        __nv_bfloat16* __restrict__ lo, int n)
{
    int i = blockIdx.x * 256 + threadIdx.x;
    if (i >= n) return;
    float x = in[i];
    __nv_bfloat16 h = __float2bfloat16(x);
    hi[i] = h;
    lo[i] = __float2bfloat16(x - __bfloat162float(h));
}

// ---------------- bf16x3 GEMM (O-proj; round-6 proven) ----------------
#define BM 128
#define BN 128
#define BK 32
#define ASTRIDE 40
#define BSTRIDE 136
#define A_T (BM * ASTRIDE)
#define B_T (BK * BSTRIDE)
#define STAGE_ELEMS (2 * A_T + 2 * B_T)
#define GEMM_SMEM_BYTES (2 * STAGE_ELEMS * 2)

__device__ __forceinline__ void load_tile(
    __nv_bfloat16* sm,
    const __nv_bfloat16* __restrict__ Ah, const __nv_bfloat16* __restrict__ Al,
    const __nv_bfloat16* __restrict__ Bh, const __nv_bfloat16* __restrict__ Bl,
    int K, int NB, int m0, int n0, int k0, int t)
{
    #pragma unroll
    for (int c = t; c < 512; c += 128) {
        int row = c >> 2, col = (c & 3) * 8;
        size_t g = (size_t)(m0 + row) * K + k0 + col;
        uint32_t s = (uint32_t)(row * ASTRIDE + col);
        cp16(sptr(sm + s),       Ah + g);
        cp16(sptr(sm + A_T + s), Al + g);
    }
    #pragma unroll
    for (int c = t; c < 512; c += 128) {
        int row = c >> 4, col = (c & 15) * 8;
        size_t g = (size_t)(k0 + row) * NB + n0 + col;
        uint32_t s = (uint32_t)(row * BSTRIDE + col);
        cp16(sptr(sm + 2 * A_T + s),       Bh + g);
        cp16(sptr(sm + 2 * A_T + B_T + s), Bl + g);
    }
}

__global__ __launch_bounds__(128, 2) void mma_gemm(
    const __nv_bfloat16* __restrict__ Ah, const __nv_bfloat16* __restrict__ Al,
    const __nv_bfloat16* __restrict__ Bh, const __nv_bfloat16* __restrict__ Bl,
    float* __restrict__ C, int NB, int K)
{
    extern __shared__ __nv_bfloat16 sm[];
    const int t = threadIdx.x, lane = t & 31, w = t >> 5;
    const int wm = w >> 1, wn = w & 1;
    const int m0 = blockIdx.y * BM, n0 = blockIdx.x * BN;

    float acc[4][8][4];
    #pragma unroll
    for (int i = 0; i < 4; i++)
        #pragma unroll
        for (int j = 0; j < 8; j++)
            #pragma unroll
            for (int r = 0; r < 4; r++) acc[i][j][r] = 0.f;

    const int g8 = lane >> 3;
    const int l8 = lane & 7;

    load_tile(sm, Ah, Al, Bh, Bl, K, NB, m0, n0, 0, t);
    asm volatile("cp.async.commit_group;\n");

    const int nk = K / BK;
    for (int kt = 0; kt < nk; kt++) {
        __nv_bfloat16* buf = sm + (kt & 1) * STAGE_ELEMS;
        if (kt + 1 < nk) {
            load_tile(sm + ((kt + 1) & 1) * STAGE_ELEMS, Ah, Al, Bh, Bl,
                      K, NB, m0, n0, (kt + 1) * BK, t);
            asm volatile("cp.async.commit_group;\n");
            asm volatile("cp.async.wait_group 1;\n");
        } else {
            asm volatile("cp.async.wait_group 0;\n");
        }
        __syncthreads();

        #pragma unroll
        for (int ks = 0; ks < 2; ks++) {
            uint32_t ah[4][4], al[4][4], bh[8][2], bl[8][2];
            #pragma unroll
            for (int i = 0; i < 4; i++) {
                int row = wm * 64 + i * 16 + (g8 & 1) * 8 + l8;
                int col = ks * 16 + (g8 >> 1) * 8;
                ldsm_x4(ah[i], sptr(buf + row * ASTRIDE + col));
                ldsm_x4(al[i], sptr(buf + A_T + row * ASTRIDE + col));
            }
            #pragma unroll
            for (int jj = 0; jj < 4; jj++) {
                int krow = ks * 16 + (g8 & 1) * 8 + l8;
                int ncol = wn * 64 + jj * 16 + (g8 >> 1) * 8;
                uint32_t r4[4];
                ldsm_x4_t(r4, sptr(buf + 2 * A_T + krow * BSTRIDE + ncol));
                bh[2 * jj][0] = r4[0]; bh[2 * jj][1] = r4[1];
                bh[2 * jj + 1][0] = r4[2]; bh[2 * jj + 1][1] = r4[3];
                ldsm_x4_t(r4, sptr(buf + 2 * A_T + B_T + krow * BSTRIDE + ncol));
                bl[2 * jj][0] = r4[0]; bl[2 * jj][1] = r4[1];
                bl[2 * jj + 1][0] = r4[2]; bl[2 * jj + 1][1] = r4[3];
            }
            #pragma unroll
            for (int i = 0; i < 4; i++)
                #pragma unroll
                for (int j = 0; j < 8; j++) {
                    mma16816(acc[i][j], ah[i], bh[j]);
                    mma16816(acc[i][j], ah[i], bl[j]);
                    mma16816(acc[i][j], al[i], bh[j]);
                }
        }
        __syncthreads();
    }

    #pragma unroll
    for (int i = 0; i < 4; i++)
        #pragma unroll
        for (int j = 0; j < 8; j++) {
            int row = m0 + wm * 64 + i * 16 + (lane >> 2);
            int col = n0 + wn * 64 + j * 8 + (lane & 3) * 2;
            *(float2*)&C[(size_t)row * NB + col] =
                make_float2(acc[i][j][0], acc[i][j][1]);
            *(float2*)&C[(size_t)(row + 8) * NB + col] =
                make_float2(acc[i][j][2], acc[i][j][3]);
        }
}

// ---------------- fused RoPE + bf16 hi/lo split ----------------
__global__ void rope_split_k(const float* __restrict__ q,
                             const float* __restrict__ kv,
                             const int* __restrict__ pos_ids,
                             __nv_bfloat16* __restrict__ qh, __nv_bfloat16* __restrict__ ql,
                             __nv_bfloat16* __restrict__ kh, __nv_bfloat16* __restrict__ kl,
                             __nv_bfloat16* __restrict__ vh, __nv_bfloat16* __restrict__ vl)
{
    int idx = blockIdx.x * blockDim.x + threadIdx.x;
    const int total = S_LEN * 48 * 32;
    if (idx >= total) return;

    int d    = idx & 31;
    int rest = idx >> 5;
    int hh   = rest % 48;
    int s    = rest / 48;

    if (hh < 40) {
        float pos = (float)pos_ids[s];
        float inv = __powf(10000.0f, -(float)d * (1.0f / 32.0f));
        float ang = pos * inv;
        float c, sn;
        __sincosf(ang, &sn, &c);
        if (hh < 32) {
            const float* p = q + (size_t)s * HID + hh * HD;
            float x1 = p[d], x2 = p[d + 32];
            size_t o1 = (size_t)s * HID + hh * HD + d, o2 = o1 + 32;
            float y1 = (x1 * c - x2 * sn) * 0.125f;
            float y2 = (x2 * c + x1 * sn) * 0.125f;
            __nv_bfloat16 h1 = __float2bfloat16(y1), h2 = __float2bfloat16(y2);
            qh[o1] = h1; ql[o1] = __float2bfloat16(y1 - __bfloat162float(h1));
            qh[o2] = h2; ql[o2] = __float2bfloat16(y2 - __bfloat162float(h2));
        } else {
            const float* p = kv + (size_t)s * KVW + (hh - 32) * HD;
            float x1 = p[d], x2 = p[d + 32];
            size_t o1 = (size_t)s * 512 + (hh - 32) * HD + d, o2 = o1 + 32;
            float y1 = x1 * c - x2 * sn;
            float y2 = x2 * c + x1 * sn;
            __nv_bfloat16 h1 = __float2bfloat16(y1), h2 = __float2bfloat16(y2);
            kh[o1] = h1; kl[o1] = __float2bfloat16(y1 - __bfloat162float(h1));
            kh[o2] = h2; kl[o2] = __float2bfloat16(y2 - __bfloat162float(h2));
        }
    } else {
        const float* p = kv + (size_t)s * KVW + 512 + (hh - 40) * HD;
        float x1 = p[d], x2 = p[d + 32];
        size_t o1 = (size_t)s * 512 + (hh - 40) * HD + d, o2 = o1 + 32;
        __nv_bfloat16 h1 = __float2bfloat16(x1), h2 = __float2bfloat16(x2);
        vh[o1] = h1; vl[o1] = __float2bfloat16(x1 - __bfloat162float(h1));
        vh[o2] = h2; vl[o2] = __float2bfloat16(x2 - __bfloat162float(h2));
    }
}

// ---------------- tensor-core flash attention (causal) ----------------
#define QHI_OFF 0
#define QLO_OFF (128 * 144)
#define BUF_OFF (2 * 128 * 144)
#define KVBUF   (4 * 64 * 144)
#define ATTN_SMEM (BUF_OFF + 2 * KVBUF)

__device__ __forceinline__ void attn_load_kv(
    uint32_t bufb,
    const __nv_bfloat16* __restrict__ kh, const __nv_bfloat16* __restrict__ kl,
    const __nv_bfloat16* __restrict__ vh, const __nv_bfloat16* __restrict__ vl,
    int k0, int kvh, int t)
{
    #pragma unroll
    for (int i = 0; i < 2; i++) {
        int idx = i * 256 + t;
        int row = idx >> 3, cc = idx & 7;
        uint32_t off = (uint32_t)(row * 144 + cc * 16);
        size_t g = (size_t)(k0 + row) * 512 + kvh * HD + cc * 8;
        cp16(bufb + off,         kh + g);
        cp16(bufb + 9216 + off,  kl + g);
        cp16(bufb + 18432 + off, vh + g);
        cp16(bufb + 27648 + off, vl + g);
    }
}

__global__ __launch_bounds__(256) void attn_tc(
    const __nv_bfloat16* __restrict__ qh, const __nv_bfloat16* __restrict__ ql,
    const __nv_bfloat16* __restrict__ kh, const __nv_bfloat16* __restrict__ kl,
    const __nv_bfloat16* __restrict__ vh, const __nv_bfloat16* __restrict__ vl,
    __nv_bfloat16* __restrict__ Oh, __nv_bfloat16* __restrict__ Ol)
{
    extern __shared__ __align__(1024) char asmem[];
    const uint32_t sb = sptr(asmem);
    const int qt  = 15 - blockIdx.x;
    const int h   = blockIdx.y;
    const int kvh = h >> 2;
    const int t = threadIdx.x, w = t >> 5, lane = t & 31;
    const int g8 = lane >> 3, l8 = lane & 7, tig = lane & 3, g = lane >> 2;
    const int q0 = qt * 128;

    #pragma unroll
    for (int i = 0; i < 4; i++) {
        int idx = i * 256 + t;
        int row = idx >> 3, cc = idx & 7;
        uint32_t off = (uint32_t)(row * 144 + cc * 16);
        size_t gg = (size_t)(q0 + row) * HID + h * HD + cc * 8;
        cp16(sb + QHI_OFF + off, qh + gg);
        cp16(sb + QLO_OFF + off, ql + gg);
    }
    attn_load_kv(sb + BUF_OFF, kh, kl, vh, vl, 0, kvh, t);
    asm volatile("cp.async.commit_group;\n");
    asm volatile("cp.async.wait_group 0;\n");
    __syncthreads();

    uint32_t qah[4][4], qal[4][4];
    #pragma unroll
    for (int kc = 0; kc < 4; kc++) {
        uint32_t off = (uint32_t)((w * 16 + (g8 & 1) * 8 + l8) * 144 +
                                  (kc * 16 + (g8 >> 1) * 8) * 2);
        ldsm_x4(qah[kc], sb + QHI_OFF + off);
        ldsm_x4(qal[kc], sb + QLO_OFF + off);
    }

    float oacc[8][4];
    #pragma unroll
    for (int j = 0; j < 8; j++)
        #pragma unroll
        for (int r = 0; r < 4; r++) oacc[j][r] = 0.f;
    float m0 = -1e30f, m1 = -1e30f, l0 = 0.f, l1 = 0.f;

    const int row0 = q0 + w * 16 + g;
    const int row1 = row0 + 8;
    const int nkt = 2 * qt + 2;

    for (int kt = 0; kt < nkt; kt++) {
        const uint32_t buf = sb + BUF_OFF + (uint32_t)(kt & 1) * KVBUF;
        if (kt + 1 < nkt) {
            attn_load_kv(sb + BUF_OFF + (uint32_t)((kt + 1) & 1) * KVBUF,
                         kh, kl, vh, vl, (kt + 1) * 64, kvh, t);
            asm volatile("cp.async.commit_group;\n");
            asm volatile("cp.async.wait_group 1;\n");
        } else {
            asm volatile("cp.async.wait_group 0;\n");
        }
        __syncthreads();

        float sacc[8][4];
        #pragma unroll
        for (int j = 0; j < 8; j++)
            #pragma unroll
            for (int r = 0; r < 4; r++) sacc[j][r] = 0.f;

        #pragma unroll
        for (int kg = 0; kg < 4; kg++) {
            #pragma unroll
            for (int kc = 0; kc < 4; kc++) {
                uint32_t off = (uint32_t)((kg * 16 + (g8 & 1) * 8 + l8) * 144 +
                                          (kc * 16 + (g8 >> 1) * 8) * 2);
                uint32_t kbh[4], kbl[4];
                ldsm_x4(kbh, buf + off);
                ldsm_x4(kbl, buf + 9216 + off);
                uint32_t b0h[2] = {kbh[0], kbh[2]}, b1h[2] = {kbh[1], kbh[3]};
                uint32_t b0l[2] = {kbl[0], kbl[2]}, b1l[2] = {kbl[1], kbl[3]};
                mma16816(sacc[2 * kg],     qah[kc], b0h);
                mma16816(sacc[2 * kg],     qah[kc], b0l);
                mma16816(sacc[2 * kg],     qal[kc], b0h);
                mma16816(sacc[2 * kg + 1], qah[kc], b1h);
                mma16816(sacc[2 * kg + 1], qah[kc], b1l);
                mma16816(sacc[2 * kg + 1], qal[kc], b1h);
            }
        }

        if (kt >= 2 * qt) {
            #pragma unroll
            for (int j = 0; j < 8; j++) {
                int col = kt * 64 + j * 8 + tig * 2;
                if (col > row0)     sacc[j][0] = -1e30f;
                if (col + 1 > row0) sacc[j][1] = -1e30f;
                if (col > row1)     sacc[j][2] = -1e30f;
                if (col + 1 > row1) sacc[j][3] = -1e30f;
            }
        }

        float mx0 = -1e30f, mx1 = -1e30f;
        #pragma unroll
        for (int j = 0; j < 8; j++) {
            mx0 = fmaxf(mx0, fmaxf(sacc[j][0], sacc[j][1]));
            mx1 = fmaxf(mx1, fmaxf(sacc[j][2], sacc[j][3]));
        }
        mx0 = fmaxf(mx0, __shfl_xor_sync(0xffffffffu, mx0, 1));
        mx0 = fmaxf(mx0, __shfl_xor_sync(0xffffffffu, mx0, 2));
        mx1 = fmaxf(mx1, __shfl_xor_sync(0xffffffffu, mx1, 1));
        mx1 = fmaxf(mx1, __shfl_xor_sync(0xffffffffu, mx1, 2));

        float nm0 = fmaxf(m0, mx0), nm1 = fmaxf(m1, mx1);
        float al0 = __expf(m0 - nm0), al1 = __expf(m1 - nm1);
        m0 = nm0; m1 = nm1;

        float rs0 = 0.f, rs1 = 0.f;
        #pragma unroll
        for (int j = 0; j < 8; j++) {
            sacc[j][0] = __expf(sacc[j][0] - nm0);
            sacc[j][1] = __expf(sacc[j][1] - nm0);
            sacc[j][2] = __expf(sacc[j][2] - nm1);
            sacc[j][3] = __expf(sacc[j][3] - nm1);
            rs0 += sacc[j][0] + sacc[j][1];
            rs1 += sacc[j][2] + sacc[j][3];
        }
        rs0 += __shfl_xor_sync(0xffffffffu, rs0, 1);
        rs0 += __shfl_xor_sync(0xffffffffu, rs0, 2);
        rs1 += __shfl_xor_sync(0xffffffffu, rs1, 1);
        rs1 += __shfl_xor_sync(0xffffffffu, rs1, 2);
        l0 = l0 * al0 + rs0;
        l1 = l1 * al1 + rs1;
        #pragma unroll
        for (int j = 0; j < 8; j++) {
            oacc[j][0] *= al0; oacc[j][1] *= al0;
            oacc[j][2] *= al1; oacc[j][3] *= al1;
        }

        uint32_t pah[4][4], pal[4][4];
        #pragma unroll
        for (int kc = 0; kc < 4; kc++) {
            int j0 = 2 * kc, j1 = 2 * kc + 1;
            float p00 = sacc[j0][0], p01 = sacc[j0][1];
            float p02 = sacc[j0][2], p03 = sacc[j0][3];
            float p10 = sacc[j1][0], p11 = sacc[j1][1];
            float p12 = sacc[j1][2], p13 = sacc[j1][3];
            float h00 = __bfloat162float(__float2bfloat16(p00));
            float h01 = __bfloat162float(__float2bfloat16(p01));
            float h02 = __bfloat162float(__float2bfloat16(p02));
            float h03 = __bfloat162float(__float2bfloat16(p03));
            float h10 = __bfloat162float(__float2bfloat16(p10));
            float h11 = __bfloat162float(__float2bfloat16(p11));
            float h12 = __bfloat162float(__float2bfloat16(p12));
            float h13 = __bfloat162float(__float2bfloat16(p13));
            pah[kc][0] = packbf2(h00, h01);
            pah[kc][1] = packbf2(h02, h03);
            pah[kc][2] = packbf2(h10, h11);
            pah[kc][3] = packbf2(h12, h13);
            pal[kc][0] = packbf2(p00 - h00, p01 - h01);
            pal[kc][1] = packbf2(p02 - h02, p03 - h03);
            pal[kc][2] = packbf2(p10 - h10, p11 - h11);
            pal[kc][3] = packbf2(p12 - h12, p13 - h13);
        }

        #pragma unroll
        for (int kc = 0; kc < 4; kc++) {
            #pragma unroll
            for (int jj = 0; jj < 4; jj++) {
                uint32_t off = (uint32_t)((kc * 16 + (g8 & 1) * 8 + l8) * 144 +
                                          (jj * 16 + (g8 >> 1) * 8) * 2);
                uint32_t vbh[4], vbl[4];
                ldsm_x4_t(vbh, buf + 18432 + off);
                ldsm_x4_t(vbl, buf + 27648 + off);
                uint32_t b0h[2] = {vbh[0], vbh[1]}, b1h[2] = {vbh[2], vbh[3]};
                uint32_t b0l[2] = {vbl[0], vbl[1]}, b1l[2] = {vbl[2], vbl[3]};
                mma16816(oacc[2 * jj],     pah[kc], b0h);
                mma16816(oacc[2 * jj],     pah[kc], b0l);
                mma16816(oacc[2 * jj],     pal[kc], b0h);
                mma16816(oacc[2 * jj + 1], pah[kc], b1h);
                mma16816(oacc[2 * jj + 1], pah[kc], b1l);
                mma16816(oacc[2 * jj + 1], pal[kc], b1h);
            }
        }
        __syncthreads();
    }

    float i0 = 1.0f / l0, i1 = 1.0f / l1;
    #pragma unroll
    for (int j = 0; j < 8; j++) {
        int col = h * HD + j * 8 + tig * 2;
        float o0 = oacc[j][0] * i0, o1 = oacc[j][1] * i0;
        float o2 = oacc[j][2] * i1, o3 = oacc[j][3] * i1;
        float h0 = __bfloat162float(__float2bfloat16(o0));
        float h1 = __bfloat162float(__float2bfloat16(o1));
        float h2 = __bfloat162float(__float2bfloat16(o2));
        float h3 = __bfloat162float(__float2bfloat16(o3));
        *(uint32_t*)&Oh[(size_t)row0 * HID + col] = packbf2(h0, h1);
        *(uint32_t*)&Oh[(size_t)row1 * HID + col] = packbf2(h2, h3);
        *(uint32_t*)&Ol[(size_t)row0 * HID + col] = packbf2(o0 - h0, o1 - h1);
        *(uint32_t*)&Ol[(size_t)row1 * HID + col] = packbf2(o2 - h2, o3 - h3);
    }
}

// ---------------- launch ----------------
extern "C" void kernel_launch(void* const* d_in, const int* in_sizes, int n_in,
                              void* d_out, int out_size)
{
    const float* X   = (const float*)d_in[0];
    const int*   pid = (const int*)d_in[2];
    const float* Wq  = (const float*)d_in[3];
    const float* Wk  = (const float*)d_in[4];
    const float* Wv  = (const float*)d_in[5];
    const float* Wo  = (const float*)d_in[6];
    float* out = (float*)d_out;

    float *q, *kv, *sx, *ts, *pmax;
    int8_t *Xh8, *Xl8, *Wh8, *Wl8;
    cudaGetSymbolAddress((void**)&q,   g_q);
    cudaGetSymbolAddress((void**)&kv,  g_kv);
    cudaGetSymbolAddress((void**)&sx,  g_sx);
    cudaGetSymbolAddress((void**)&ts,  g_ts);
    cudaGetSymbolAddress((void**)&pmax,g_pmax);
    cudaGetSymbolAddress((void**)&Xh8, g_Xh8);
    cudaGetSymbolAddress((void**)&Xl8, g_Xl8);
    cudaGetSymbolAddress((void**)&Wh8, g_Wh8);
    cudaGetSymbolAddress((void**)&Wl8, g_Wl8);
    __nv_bfloat16 *Woh, *Wol, *Ah, *Al, *qh, *ql, *kh, *kl, *vh, *vl;
    cudaGetSymbolAddress((void**)&Woh, g_Wohi); cudaGetSymbolAddress((void**)&Wol, g_Wolo);
    cudaGetSymbolAddress((void**)&Ah,  g_Ahi);  cudaGetSymbolAddress((void**)&Al,  g_Alo);
    cudaGetSymbolAddress((void**)&qh,  g_qh);   cudaGetSymbolAddress((void**)&ql,  g_ql);
    cudaGetSymbolAddress((void**)&kh,  g_kh);   cudaGetSymbolAddress((void**)&kl,  g_kl);
    cudaGetSymbolAddress((void**)&vh,  g_vh);   cudaGetSymbolAddress((void**)&vl,  g_vl);

    cudaFuncSetAttribute(imma_gemm, cudaFuncAttributeMaxDynamicSharedMemorySize, IMMA_SMEM);
    cudaFuncSetAttribute(mma_gemm, cudaFuncAttributeMaxDynamicSharedMemorySize, GEMM_SMEM_BYTES);
    cudaFuncSetAttribute(attn_tc, cudaFuncAttributeMaxDynamicSharedMemorySize, ATTN_SMEM);

    // quantization
    xquant_k<<<S_LEN, 256>>>(X, Xh8, Xl8, sx);
    colmax_k<<<dim3(8, 16), 256>>>(Wq, pmax, 2048, 0);
    colmax_k<<<dim3(2, 16), 256>>>(Wk, pmax, 512, 2048);
    colmax_k<<<dim3(2, 16), 256>>>(Wv, pmax, 512, 2560);
    wquant_t<<<dim3(64, 64), 256>>>(Wq, pmax, Wh8, Wl8, ts, 2048, 0);
    wquant_t<<<dim3(16, 64), 256>>>(Wk, pmax, Wh8, Wl8, ts, 512, 2048);
    wquant_t<<<dim3(16, 64), 256>>>(Wv, pmax, Wh8, Wl8, ts, 512, 2560);
    split_k<<<(HID * HID) / 256, 256>>>(Wo, Woh, Wol, HID * HID);

    // fused QKV projection (int8 IMMA)
    imma_gemm<<<dim3(NQKV / 64, S_LEN / 64), 128, IMMA_SMEM>>>(
        Xh8, Xl8, Wh8, Wl8, sx, ts, q, kv);

    // RoPE + bf16 split
    {
        int total = S_LEN * 48 * 32;
        rope_split_k<<<(total + 255) / 256, 256>>>(q, kv, pid, qh, ql, kh, kl, vh, vl);
    }

    // attention
    attn_tc<<<dim3(16, NH), 256, ATTN_SMEM>>>(qh, ql, kh, kl, vh, vl, Ah, Al);

    // O projection (bf16x3)
    mma_gemm<<<dim3(HID / BN, S_LEN / BM), 128, GEMM_SMEM_BYTES>>>(
        Ah, Al, Woh, Wol, out, HID, HID);
}

// round 8
// speedup vs baseline: 1.5931x; 1.5931x over previous
#include <cuda_runtime.h>
#include <cuda_bf16.h>
#include <math.h>
#include <stdint.h>

#define S_LEN 2048
#define HID   2048
#define NH    32
#define NKV   8
#define HD    64
#define KVW   1024
#define NQKV  3072

// ---------------- scratch ----------------
__device__ __nv_bfloat16 g_Xhi [S_LEN * HID],  g_Xlo [S_LEN * HID];
__device__ __nv_bfloat16 g_Wqkvh[HID * NQKV],  g_Wqkvl[HID * NQKV];
__device__ __nv_bfloat16 g_Wohi[HID * HID],    g_Wolo[HID * HID];
__device__ __nv_bfloat16 g_Ahi [S_LEN * HID],  g_Alo [S_LEN * HID];

__device__ __nv_bfloat16 g_qh[S_LEN * HID], g_ql[S_LEN * HID];
__device__ __nv_bfloat16 g_kh[S_LEN * 512], g_kl[S_LEN * 512];
__device__ __nv_bfloat16 g_vh[S_LEN * 512], g_vl[S_LEN * 512];

// ---------------- helpers ----------------
__device__ __forceinline__ uint32_t sptr(const void* p) {
    return (uint32_t)__cvta_generic_to_shared(p);
}
__device__ __forceinline__ void cp16(uint32_t dst, const void* src) {
    asm volatile("cp.async.cg.shared.global [%0], [%1], 16;\n" :: "r"(dst), "l"(src));
}
__device__ __forceinline__ void ldsm_x4(uint32_t* r, uint32_t addr) {
    asm volatile("ldmatrix.sync.aligned.m8n8.x4.shared.b16 {%0,%1,%2,%3}, [%4];\n"
        : "=r"(r[0]), "=r"(r[1]), "=r"(r[2]), "=r"(r[3]) : "r"(addr));
}
__device__ __forceinline__ void ldsm_x4_t(uint32_t* r, uint32_t addr) {
    asm volatile("ldmatrix.sync.aligned.m8n8.x4.trans.shared.b16 {%0,%1,%2,%3}, [%4];\n"
        : "=r"(r[0]), "=r"(r[1]), "=r"(r[2]), "=r"(r[3]) : "r"(addr));
}
__device__ __forceinline__ void mma16816(float* c, const uint32_t* a, const uint32_t* b) {
    asm volatile(
        "mma.sync.aligned.m16n8k16.row.col.f32.bf16.bf16.f32 "
        "{%0,%1,%2,%3}, {%4,%5,%6,%7}, {%8,%9}, {%0,%1,%2,%3};\n"
        : "+f"(c[0]), "+f"(c[1]), "+f"(c[2]), "+f"(c[3])
        : "r"(a[0]), "r"(a[1]), "r"(a[2]), "r"(a[3]), "r"(b[0]), "r"(b[1]));
}
__device__ __forceinline__ uint32_t packbf2(float x, float y) {
    __nv_bfloat162 h = __floats2bfloat162_rn(x, y);
    return *(uint32_t*)&h;
}
__device__ __forceinline__ void store_pair(__nv_bfloat16* oh, __nv_bfloat16* ol,
                                           size_t idx, float a, float b) {
    float ha = __bfloat162float(__float2bfloat16(a));
    float hb = __bfloat162float(__float2bfloat16(b));
    *(uint32_t*)&oh[idx] = packbf2(ha, hb);
    *(uint32_t*)&ol[idx] = packbf2(a - ha, b - hb);
}

// ---------------- vectorized splits (8 elems/thread) ----------------
__global__ __launch_bounds__(256) void split_v4(
    const float* __restrict__ in,
    __nv_bfloat16* __restrict__ hi, __nv_bfloat16* __restrict__ lo, int n8)
{
    int i = blockIdx.x * 256 + threadIdx.x;
    if (i >= n8) return;
    const float4* p = (const float4*)in + 2 * (size_t)i;
    float4 f0 = p[0], f1 = p[1];
    float v[8] = {f0.x, f0.y, f0.z, f0.w, f1.x, f1.y, f1.z, f1.w};
    uint32_t h[4], l[4];
    #pragma unroll
    for (int k = 0; k < 4; k++) {
        float a = v[2 * k], b = v[2 * k + 1];
        float ha = __bfloat162float(__float2bfloat16(a));
        float hb = __bfloat162float(__float2bfloat16(b));
        h[k] = packbf2(ha, hb);
        l[k] = packbf2(a - ha, b - hb);
    }
    ((uint4*)hi)[i] = make_uint4(h[0], h[1], h[2], h[3]);
    ((uint4*)lo)[i] = make_uint4(l[0], l[1], l[2], l[3]);
}

__global__ __launch_bounds__(256) void split_pack_v4(
    const float* __restrict__ in,
    __nv_bfloat16* __restrict__ hi, __nv_bfloat16* __restrict__ lo,
    int cols8, int ostride8, int ooff8, int n8)
{
    int i = blockIdx.x * 256 + threadIdx.x;
    if (i >= n8) return;
    int r = i / cols8, c8 = i % cols8;
    const float4* p = (const float4*)in + 2 * (size_t)i;
    float4 f0 = p[0], f1 = p[1];
    float v[8] = {f0.x, f0.y, f0.z, f0.w, f1.x, f1.y, f1.z, f1.w};
    uint32_t h[4], l[4];
    #pragma unroll
    for (int k = 0; k < 4; k++) {
        float a = v[2 * k], b = v[2 * k + 1];
        float ha = __bfloat162float(__float2bfloat16(a));
        float hb = __bfloat162float(__float2bfloat16(b));
        h[k] = packbf2(ha, hb);
        l[k] = packbf2(a - ha, b - hb);
    }
    size_t o = (size_t)r * ostride8 + ooff8 + c8;
    ((uint4*)hi)[o] = make_uint4(h[0], h[1], h[2], h[3]);
    ((uint4*)lo)[o] = make_uint4(l[0], l[1], l[2], l[3]);
}

// ---------------- GEMM tiles: 128x128 CTA, 4 warps, 64x64 warp tile ----------------
#define BM 128
#define BN 128
#define BK 32
#define ASTRIDE 40
#define BSTRIDE 136
#define A_T (BM * ASTRIDE)
#define B_T (BK * BSTRIDE)
#define STAGE_ELEMS (2 * A_T + 2 * B_T)
#define GEMM_SMEM_BYTES (2 * STAGE_ELEMS * 2)

__device__ __forceinline__ void load_tile(
    __nv_bfloat16* sm,
    const __nv_bfloat16* __restrict__ Ah, const __nv_bfloat16* __restrict__ Al,
    const __nv_bfloat16* __restrict__ Bh, const __nv_bfloat16* __restrict__ Bl,
    int K, int NB, int m0, int n0, int k0, int t)
{
    #pragma unroll
    for (int c = t; c < 512; c += 128) {
        int row = c >> 2, col = (c & 3) * 8;
        size_t g = (size_t)(m0 + row) * K + k0 + col;
        uint32_t s = (uint32_t)(row * ASTRIDE + col);
        cp16(sptr(sm + s),       Ah + g);
        cp16(sptr(sm + A_T + s), Al + g);
    }
    #pragma unroll
    for (int c = t; c < 512; c += 128) {
        int row = c >> 4, col = (c & 15) * 8;
        size_t g = (size_t)(k0 + row) * NB + n0 + col;
        uint32_t s = (uint32_t)(row * BSTRIDE + col);
        cp16(sptr(sm + 2 * A_T + s),       Bh + g);
        cp16(sptr(sm + 2 * A_T + B_T + s), Bl + g);
    }
}

// shared mainloop producing acc[4][8][4]
#define GEMM_MAINLOOP(Ah, Al, Bh, Bl, K, NB)                                        \
    float acc[4][8][4];                                                             \
    _Pragma("unroll")                                                               \
    for (int i = 0; i < 4; i++)                                                     \
        _Pragma("unroll")                                                           \
        for (int j = 0; j < 8; j++)                                                 \
            _Pragma("unroll")                                                       \
            for (int r = 0; r < 4; r++) acc[i][j][r] = 0.f;                         \
    const int g8 = lane >> 3;                                                       \
    const int l8 = lane & 7;                                                        \
    load_tile(sm, Ah, Al, Bh, Bl, K, NB, m0, n0, 0, t);                             \
    asm volatile("cp.async.commit_group;\n");                                       \
    const int nk = K / BK;                                                          \
    for (int kt = 0; kt < nk; kt++) {                                               \
        __nv_bfloat16* buf = sm + (kt & 1) * STAGE_ELEMS;                           \
        if (kt + 1 < nk) {                                                          \
            load_tile(sm + ((kt + 1) & 1) * STAGE_ELEMS, Ah, Al, Bh, Bl,            \
                      K, NB, m0, n0, (kt + 1) * BK, t);                             \
            asm volatile("cp.async.commit_group;\n");                               \
            asm volatile("cp.async.wait_group 1;\n");                               \
        } else {                                                                    \
            asm volatile("cp.async.wait_group 0;\n");                               \
        }                                                                           \
        __syncthreads();                                                            \
        _Pragma("unroll")                                                           \
        for (int ks = 0; ks < 2; ks++) {                                            \
            uint32_t ah[4][4], al[4][4], bh[8][2], bl[8][2];                        \
            _Pragma("unroll")                                                       \
            for (int i = 0; i < 4; i++) {                                           \
                int row = wm * 64 + i * 16 + (g8 & 1) * 8 + l8;                     \
                int col = ks * 16 + (g8 >> 1) * 8;                                  \
                ldsm_x4(ah[i], sptr(buf + row * ASTRIDE + col));                    \
                ldsm_x4(al[i], sptr(buf + A_T + row * ASTRIDE + col));              \
            }                                                                       \
            _Pragma("unroll")                                                       \
            for (int jj = 0; jj < 4; jj++) {                                        \
                int krow = ks * 16 + (g8 & 1) * 8 + l8;                             \
                int ncol = wn * 64 + jj * 16 + (g8 >> 1) * 8;                       \
                uint32_t r4[4];                                                     \
                ldsm_x4_t(r4, sptr(buf + 2 * A_T + krow * BSTRIDE + ncol));         \
                bh[2 * jj][0] = r4[0]; bh[2 * jj][1] = r4[1];                       \
                bh[2 * jj + 1][0] = r4[2]; bh[2 * jj + 1][1] = r4[3];               \
                ldsm_x4_t(r4, sptr(buf + 2 * A_T + B_T + krow * BSTRIDE + ncol));   \
                bl[2 * jj][0] = r4[0]; bl[2 * jj][1] = r4[1];                       \
                bl[2 * jj + 1][0] = r4[2]; bl[2 * jj + 1][1] = r4[3];               \
            }                                                                       \
            _Pragma("unroll")                                                       \
            for (int i = 0; i < 4; i++)                                             \
                _Pragma("unroll")                                                   \
                for (int j = 0; j < 8; j++) {                                       \
                    mma16816(acc[i][j], ah[i], bh[j]);                              \
                    mma16816(acc[i][j], ah[i], bl[j]);                              \
                    mma16816(acc[i][j], al[i], bh[j]);                              \
                }                                                                   \
        }                                                                           \
        __syncthreads();                                                            \
    }

// QKV GEMM with fused RoPE + bf16 hi/lo split epilogue
__global__ __launch_bounds__(128, 2) void qkv_gemm(
    const __nv_bfloat16* __restrict__ Ah, const __nv_bfloat16* __restrict__ Al,
    const __nv_bfloat16* __restrict__ Bh, const __nv_bfloat16* __restrict__ Bl,
    const int* __restrict__ pid,
    __nv_bfloat16* __restrict__ qh, __nv_bfloat16* __restrict__ ql,
    __nv_bfloat16* __restrict__ kh, __nv_bfloat16* __restrict__ kl,
    __nv_bfloat16* __restrict__ vh, __nv_bfloat16* __restrict__ vl)
{
    extern __shared__ __nv_bfloat16 sm[];
    const int t = threadIdx.x, lane = t & 31, w = t >> 5;
    const int wm = w >> 1, wn = w & 1;
    const int m0 = blockIdx.y * BM, n0 = blockIdx.x * BN;

    GEMM_MAINLOOP(Ah, Al, Bh, Bl, HID, NQKV)

    // epilogue: warp tile = one 64-wide head
    const int gc = n0 + wn * 64;
    __nv_bfloat16 *oh, *ol; int ldo, base; float scale;
    bool dorope;
    if (gc < 2048)      { oh = qh; ol = ql; ldo = HID; base = gc;        scale = 0.125f; dorope = true; }
    else if (gc < 2560) { oh = kh; ol = kl; ldo = 512; base = gc - 2048; scale = 1.f;    dorope = true; }
    else                { oh = vh; ol = vl; ldo = 512; base = gc - 2560; scale = 1.f;    dorope = false; }

    #pragma unroll
    for (int i = 0; i < 4; i++) {
        int r0 = m0 + wm * 64 + i * 16 + (lane >> 2);
        int r1 = r0 + 8;
        float p0 = (float)pid[r0], p1 = (float)pid[r1];
        #pragma unroll
        for (int j = 0; j < 4; j++) {
            int ch = j * 8 + (lane & 3) * 2;
            float x10 = acc[i][j][0],     x11 = acc[i][j][1];
            float x12 = acc[i][j][2],     x13 = acc[i][j][3];
            float x20 = acc[i][j + 4][0], x21 = acc[i][j + 4][1];
            float x22 = acc[i][j + 4][2], x23 = acc[i][j + 4][3];
            float y10, y11, y12, y13, y20, y21, y22, y23;
            if (dorope) {
                float inv0 = __powf(10000.f, -(float)ch * (1.f / 32.f));
                float inv1 = __powf(10000.f, -(float)(ch + 1) * (1.f / 32.f));
                float s00, c00, s01, c01, s10, c10, s11, c11;
                __sincosf(p0 * inv0, &s00, &c00);
                __sincosf(p0 * inv1, &s01, &c01);
                __sincosf(p1 * inv0, &s10, &c10);
                __sincosf(p1 * inv1, &s11, &c11);
                y10 = (x10 * c00 - x20 * s00) * scale; y20 = (x20 * c00 + x10 * s00) * scale;
                y11 = (x11 * c01 - x21 * s01) * scale; y21 = (x21 * c01 + x11 * s01) * scale;
                y12 = (x12 * c10 - x22 * s10) * scale; y22 = (x22 * c10 + x12 * s10) * scale;
                y13 = (x13 * c11 - x23 * s11) * scale; y23 = (x23 * c11 + x13 * s11) * scale;
            } else {
                y10 = x10; y11 = x11; y12 = x12; y13 = x13;
                y20 = x20; y21 = x21; y22 = x22; y23 = x23;
            }
            size_t b0 = (size_t)r0 * ldo + base + ch;
            size_t b1 = (size_t)r1 * ldo + base + ch;
            store_pair(oh, ol, b0,      y10, y11);
            store_pair(oh, ol, b0 + 32, y20, y21);
            store_pair(oh, ol, b1,      y12, y13);
            store_pair(oh, ol, b1 + 32, y22, y23);
        }
    }
}

// plain fp32-output GEMM (O projection)
__global__ __launch_bounds__(128, 2) void mma_gemm(
    const __nv_bfloat16* __restrict__ Ah, const __nv_bfloat16* __restrict__ Al,
    const __nv_bfloat16* __restrict__ Bh, const __nv_bfloat16* __restrict__ Bl,
    float* __restrict__ C, int NB, int K)
{
    extern __shared__ __nv_bfloat16 sm[];
    const int t = threadIdx.x, lane = t & 31, w = t >> 5;
    const int wm = w >> 1, wn = w & 1;
    const int m0 = blockIdx.y * BM, n0 = blockIdx.x * BN;

    GEMM_MAINLOOP(Ah, Al, Bh, Bl, K, NB)

    #pragma unroll
    for (int i = 0; i < 4; i++)
        #pragma unroll
        for (int j = 0; j < 8; j++) {
            int row = m0 + wm * 64 + i * 16 + (lane >> 2);
            int col = n0 + wn * 64 + j * 8 + (lane & 3) * 2;
            *(float2*)&C[(size_t)row * NB + col] =
                make_float2(acc[i][j][0], acc[i][j][1]);
            *(float2*)&C[(size_t)(row + 8) * NB + col] =
                make_float2(acc[i][j][2], acc[i][j][3]);
        }
}

// ---------------- tensor-core flash attention (causal) ----------------
#define QHI_OFF 0
#define QLO_OFF (128 * 144)
#define BUF_OFF (2 * 128 * 144)
#define KVBUF   (4 * 64 * 144)
#define ATTN_SMEM (BUF_OFF + 2 * KVBUF)

__device__ __forceinline__ void attn_load_kv(
    uint32_t bufb,
    const __nv_bfloat16* __restrict__ kh, const __nv_bfloat16* __restrict__ kl,
    const __nv_bfloat16* __restrict__ vh, const __nv_bfloat16* __restrict__ vl,
    int k0, int kvh, int t)
{
    #pragma unroll
    for (int i = 0; i < 2; i++) {
        int idx = i * 256 + t;
        int row = idx >> 3, cc = idx & 7;
        uint32_t off = (uint32_t)(row * 144 + cc * 16);
        size_t g = (size_t)(k0 + row) * 512 + kvh * HD + cc * 8;
        cp16(bufb + off,         kh + g);
        cp16(bufb + 9216 + off,  kl + g);
        cp16(bufb + 18432 + off, vh + g);
        cp16(bufb + 27648 + off, vl + g);
    }
}

__global__ __launch_bounds__(256) void attn_tc(
    const __nv_bfloat16* __restrict__ qh, const __nv_bfloat16* __restrict__ ql,
    const __nv_bfloat16* __restrict__ kh, const __nv_bfloat16* __restrict__ kl,
    const __nv_bfloat16* __restrict__ vh, const __nv_bfloat16* __restrict__ vl,
    __nv_bfloat16* __restrict__ Oh, __nv_bfloat16* __restrict__ Ol)
{
    extern __shared__ __align__(1024) char asmem[];
    const uint32_t sb = sptr(asmem);
    const int qt  = 15 - blockIdx.x;
    const int h   = blockIdx.y;
    const int kvh = h >> 2;
    const int t = threadIdx.x, w = t >> 5, lane = t & 31;
    const int g8 = lane >> 3, l8 = lane & 7, tig = lane & 3, g = lane >> 2;
    const int q0 = qt * 128;

    #pragma unroll
    for (int i = 0; i < 4; i++) {
        int idx = i * 256 + t;
        int row = idx >> 3, cc = idx & 7;
        uint32_t off = (uint32_t)(row * 144 + cc * 16);
        size_t gg = (size_t)(q0 + row) * HID + h * HD + cc * 8;
        cp16(sb + QHI_OFF + off, qh + gg);
        cp16(sb + QLO_OFF + off, ql + gg);
    }
    attn_load_kv(sb + BUF_OFF, kh, kl, vh, vl, 0, kvh, t);
    asm volatile("cp.async.commit_group;\n");
    asm volatile("cp.async.wait_group 0;\n");
    __syncthreads();

    uint32_t qah[4][4], qal[4][4];
    #pragma unroll
    for (int kc = 0; kc < 4; kc++) {
        uint32_t off = (uint32_t)((w * 16 + (g8 & 1) * 8 + l8) * 144 +
                                  (kc * 16 + (g8 >> 1) * 8) * 2);
        ldsm_x4(qah[kc], sb + QHI_OFF + off);
        ldsm_x4(qal[kc], sb + QLO_OFF + off);
    }

    float oacc[8][4];
    #pragma unroll
    for (int j = 0; j < 8; j++)
        #pragma unroll
        for (int r = 0; r < 4; r++) oacc[j][r] = 0.f;
    float m0 = -1e30f, m1 = -1e30f, l0 = 0.f, l1 = 0.f;

    const int row0 = q0 + w * 16 + g;
    const int row1 = row0 + 8;
    const int nkt = 2 * qt + 2;

    for (int kt = 0; kt < nkt; kt++) {
        const uint32_t buf = sb + BUF_OFF + (uint32_t)(kt & 1) * KVBUF;
        if (kt + 1 < nkt) {
            attn_load_kv(sb + BUF_OFF + (uint32_t)((kt + 1) & 1) * KVBUF,
                         kh, kl, vh, vl, (kt + 1) * 64, kvh, t);
            asm volatile("cp.async.commit_group;\n");
            asm volatile("cp.async.wait_group 1;\n");
        } else {
            asm volatile("cp.async.wait_group 0;\n");
        }
        __syncthreads();

        float sacc[8][4];
        #pragma unroll
        for (int j = 0; j < 8; j++)
            #pragma unroll
            for (int r = 0; r < 4; r++) sacc[j][r] = 0.f;

        #pragma unroll
        for (int kg = 0; kg < 4; kg++) {
            #pragma unroll
            for (int kc = 0; kc < 4; kc++) {
                uint32_t off = (uint32_t)((kg * 16 + (g8 & 1) * 8 + l8) * 144 +
                                          (kc * 16 + (g8 >> 1) * 8) * 2);
                uint32_t kbh[4], kbl[4];
                ldsm_x4(kbh, buf + off);
                ldsm_x4(kbl, buf + 9216 + off);
                uint32_t b0h[2] = {kbh[0], kbh[2]}, b1h[2] = {kbh[1], kbh[3]};
                uint32_t b0l[2] = {kbl[0], kbl[2]}, b1l[2] = {kbl[1], kbl[3]};
                mma16816(sacc[2 * kg],     qah[kc], b0h);
                mma16816(sacc[2 * kg],     qah[kc], b0l);
                mma16816(sacc[2 * kg],     qal[kc], b0h);
                mma16816(sacc[2 * kg + 1], qah[kc], b1h);
                mma16816(sacc[2 * kg + 1], qah[kc], b1l);
                mma16816(sacc[2 * kg + 1], qal[kc], b1h);
            }
        }

        if (kt >= 2 * qt) {
            #pragma unroll
            for (int j = 0; j < 8; j++) {
                int col = kt * 64 + j * 8 + tig * 2;
                if (col > row0)     sacc[j][0] = -1e30f;
                if (col + 1 > row0) sacc[j][1] = -1e30f;
                if (col > row1)     sacc[j][2] = -1e30f;
                if (col + 1 > row1) sacc[j][3] = -1e30f;
            }
        }

        float mx0 = -1e30f, mx1 = -1e30f;
        #pragma unroll
        for (int j = 0; j < 8; j++) {
            mx0 = fmaxf(mx0, fmaxf(sacc[j][0], sacc[j][1]));
            mx1 = fmaxf(mx1, fmaxf(sacc[j][2], sacc[j][3]));
        }
        mx0 = fmaxf(mx0, __shfl_xor_sync(0xffffffffu, mx0, 1));
        mx0 = fmaxf(mx0, __shfl_xor_sync(0xffffffffu, mx0, 2));
        mx1 = fmaxf(mx1, __shfl_xor_sync(0xffffffffu, mx1, 1));
        mx1 = fmaxf(mx1, __shfl_xor_sync(0xffffffffu, mx1, 2));

        float nm0 = fmaxf(m0, mx0), nm1 = fmaxf(m1, mx1);
        float al0 = __expf(m0 - nm0), al1 = __expf(m1 - nm1);
        m0 = nm0; m1 = nm1;

        float rs0 = 0.f, rs1 = 0.f;
        #pragma unroll
        for (int j = 0; j < 8; j++) {
            sacc[j][0] = __expf(sacc[j][0] - nm0);
            sacc[j][1] = __expf(sacc[j][1] - nm0);
            sacc[j][2] = __expf(sacc[j][2] - nm1);
            sacc[j][3] = __expf(sacc[j][3] - nm1);
            rs0 += sacc[j][0] + sacc[j][1];
            rs1 += sacc[j][2] + sacc[j][3];
        }
        rs0 += __shfl_xor_sync(0xffffffffu, rs0, 1);
        rs0 += __shfl_xor_sync(0xffffffffu, rs0, 2);
        rs1 += __shfl_xor_sync(0xffffffffu, rs1, 1);
        rs1 += __shfl_xor_sync(0xffffffffu, rs1, 2);
        l0 = l0 * al0 + rs0;
        l1 = l1 * al1 + rs1;
        #pragma unroll
        for (int j = 0; j < 8; j++) {
            oacc[j][0] *= al0; oacc[j][1] *= al0;
            oacc[j][2] *= al1; oacc[j][3] *= al1;
        }

        uint32_t pah[4][4], pal[4][4];
        #pragma unroll
        for (int kc = 0; kc < 4; kc++) {
            int j0 = 2 * kc, j1 = 2 * kc + 1;
            float p00 = sacc[j0][0], p01 = sacc[j0][1];
            float p02 = sacc[j0][2], p03 = sacc[j0][3];
            float p10 = sacc[j1][0], p11 = sacc[j1][1];
            float p12 = sacc[j1][2], p13 = sacc[j1][3];
            float h00 = __bfloat162float(__float2bfloat16(p00));
            float h01 = __bfloat162float(__float2bfloat16(p01));
            float h02 = __bfloat162float(__float2bfloat16(p02));
            float h03 = __bfloat162float(__float2bfloat16(p03));
            float h10 = __bfloat162float(__float2bfloat16(p10));
            float h11 = __bfloat162float(__float2bfloat16(p11));
            float h12 = __bfloat162float(__float2bfloat16(p12));
            float h13 = __bfloat162float(__float2bfloat16(p13));
            pah[kc][0] = packbf2(h00, h01);
            pah[kc][1] = packbf2(h02, h03);
            pah[kc][2] = packbf2(h10, h11);
            pah[kc][3] = packbf2(h12, h13);
            pal[kc][0] = packbf2(p00 - h00, p01 - h01);
            pal[kc][1] = packbf2(p02 - h02, p03 - h03);
            pal[kc][2] = packbf2(p10 - h10, p11 - h11);
            pal[kc][3] = packbf2(p12 - h12, p13 - h13);
        }

        #pragma unroll
        for (int kc = 0; kc < 4; kc++) {
            #pragma unroll
            for (int jj = 0; jj < 4; jj++) {
                uint32_t off = (uint32_t)((kc * 16 + (g8 & 1) * 8 + l8) * 144 +
                                          (jj * 16 + (g8 >> 1) * 8) * 2);
                uint32_t vbh[4], vbl[4];
                ldsm_x4_t(vbh, buf + 18432 + off);
                ldsm_x4_t(vbl, buf + 27648 + off);
                uint32_t b0h[2] = {vbh[0], vbh[1]}, b1h[2] = {vbh[2], vbh[3]};
                uint32_t b0l[2] = {vbl[0], vbl[1]}, b1l[2] = {vbl[2], vbl[3]};
                mma16816(oacc[2 * jj],     pah[kc], b0h);
                mma16816(oacc[2 * jj],     pah[kc], b0l);
                mma16816(oacc[2 * jj],     pal[kc], b0h);
                mma16816(oacc[2 * jj + 1], pah[kc], b1h);
                mma16816(oacc[2 * jj + 1], pah[kc], b1l);
                mma16816(oacc[2 * jj + 1], pal[kc], b1h);
            }
        }
        __syncthreads();
    }

    float i0 = 1.0f / l0, i1 = 1.0f / l1;
    #pragma unroll
    for (int j = 0; j < 8; j++) {
        int col = h * HD + j * 8 + tig * 2;
        float o0 = oacc[j][0] * i0, o1 = oacc[j][1] * i0;
        float o2 = oacc[j][2] * i1, o3 = oacc[j][3] * i1;
        float h0 = __bfloat162float(__float2bfloat16(o0));
        float h1 = __bfloat162float(__float2bfloat16(o1));
        float h2 = __bfloat162float(__float2bfloat16(o2));
        float h3 = __bfloat162float(__float2bfloat16(o3));
        *(uint32_t*)&Oh[(size_t)row0 * HID + col] = packbf2(h0, h1);
        *(uint32_t*)&Oh[(size_t)row1 * HID + col] = packbf2(h2, h3);
        *(uint32_t*)&Ol[(size_t)row0 * HID + col] = packbf2(o0 - h0, o1 - h1);
        *(uint32_t*)&Ol[(size_t)row1 * HID + col] = packbf2(o2 - h2, o3 - h3);
    }
}

// ---------------- launch ----------------
extern "C" void kernel_launch(void* const* d_in, const int* in_sizes, int n_in,
                              void* d_out, int out_size)
{
    const float* X   = (const float*)d_in[0];
    const int*   pid = (const int*)d_in[2];
    const float* Wq  = (const float*)d_in[3];
    const float* Wk  = (const float*)d_in[4];
    const float* Wv  = (const float*)d_in[5];
    const float* Wo  = (const float*)d_in[6];
    float* out = (float*)d_out;

    __nv_bfloat16 *Xh, *Xl, *Wqkvh, *Wqkvl, *Woh, *Wol, *Ah, *Al;
    __nv_bfloat16 *qh, *ql, *kh, *kl, *vh, *vl;
    cudaGetSymbolAddress((void**)&Xh,   g_Xhi);    cudaGetSymbolAddress((void**)&Xl,   g_Xlo);
    cudaGetSymbolAddress((void**)&Wqkvh,g_Wqkvh);  cudaGetSymbolAddress((void**)&Wqkvl,g_Wqkvl);
    cudaGetSymbolAddress((void**)&Woh,  g_Wohi);   cudaGetSymbolAddress((void**)&Wol,  g_Wolo);
    cudaGetSymbolAddress((void**)&Ah,   g_Ahi);    cudaGetSymbolAddress((void**)&Al,   g_Alo);
    cudaGetSymbolAddress((void**)&qh,   g_qh);     cudaGetSymbolAddress((void**)&ql,   g_ql);
    cudaGetSymbolAddress((void**)&kh,   g_kh);     cudaGetSymbolAddress((void**)&kl,   g_kl);
    cudaGetSymbolAddress((void**)&vh,   g_vh);     cudaGetSymbolAddress((void**)&vl,   g_vl);

    cudaFuncSetAttribute(qkv_gemm, cudaFuncAttributeMaxDynamicSharedMemorySize, GEMM_SMEM_BYTES);
    cudaFuncSetAttribute(mma_gemm, cudaFuncAttributeMaxDynamicSharedMemorySize, GEMM_SMEM_BYTES);
    cudaFuncSetAttribute(attn_tc, cudaFuncAttributeMaxDynamicSharedMemorySize, ATTN_SMEM);

    // vectorized splits
    split_v4<<<(S_LEN * HID / 8 + 255) / 256, 256>>>(X, Xh, Xl, S_LEN * HID / 8);
    split_pack_v4<<<(HID * 2048 / 8 + 255) / 256, 256>>>(
        Wq, Wqkvh, Wqkvl, 2048 / 8, NQKV / 8, 0, HID * 2048 / 8);
    split_pack_v4<<<(HID * 512 / 8 + 255) / 256, 256>>>(
        Wk, Wqkvh, Wqkvl, 512 / 8, NQKV / 8, 2048 / 8, HID * 512 / 8);
    split_pack_v4<<<(HID * 512 / 8 + 255) / 256, 256>>>(
        Wv, Wqkvh, Wqkvl, 512 / 8, NQKV / 8, 2560 / 8, HID * 512 / 8);
    split_v4<<<(HID * HID / 8 + 255) / 256, 256>>>(Wo, Woh, Wol, HID * HID / 8);

    // fused QKV projection + RoPE + bf16 split
    qkv_gemm<<<dim3(NQKV / BN, S_LEN / BM), 128, GEMM_SMEM_BYTES>>>(
        Xh, Xl, Wqkvh, Wqkvl, pid, qh, ql, kh, kl, vh, vl);

    // attention
    attn_tc<<<dim3(16, NH), 256, ATTN_SMEM>>>(qh, ql, kh, kl, vh, vl, Ah, Al);

    // O projection
    mma_gemm<<<dim3(HID / BN, S_LEN / BM), 128, GEMM_SMEM_BYTES>>>(
        Ah, Al, Woh, Wol, out, HID, HID);
}

// round 9
// speedup vs baseline: 1.6694x; 1.0479x over previous
#include <cuda_runtime.h>
#include <cuda_bf16.h>
#include <math.h>
#include <stdint.h>

#define S_LEN 2048
#define HID   2048
#define NH    32
#define NKV   8
#define HD    64
#define KVW   1024
#define NQKV  3072

// ---------------- scratch ----------------
__device__ __nv_bfloat16 g_Xhi [S_LEN * HID],  g_Xlo [S_LEN * HID];
__device__ __nv_bfloat16 g_Wqkvh[HID * NQKV],  g_Wqkvl[HID * NQKV];
__device__ __nv_bfloat16 g_Wohi[HID * HID],    g_Wolo[HID * HID];
__device__ __nv_bfloat16 g_Ahi [S_LEN * HID],  g_Alo [S_LEN * HID];

__device__ __nv_bfloat16 g_qh[S_LEN * HID], g_ql[S_LEN * HID];
__device__ __nv_bfloat16 g_kh[S_LEN * 512], g_kl[S_LEN * 512];
__device__ __nv_bfloat16 g_vh[S_LEN * 512], g_vl[S_LEN * 512];

// ---------------- helpers ----------------
__device__ __forceinline__ uint32_t sptr(const void* p) {
    return (uint32_t)__cvta_generic_to_shared(p);
}
__device__ __forceinline__ void cp16(uint32_t dst, const void* src) {
    asm volatile("cp.async.cg.shared.global [%0], [%1], 16;\n" :: "r"(dst), "l"(src));
}
__device__ __forceinline__ void ldsm_x4(uint32_t* r, uint32_t addr) {
    asm volatile("ldmatrix.sync.aligned.m8n8.x4.shared.b16 {%0,%1,%2,%3}, [%4];\n"
        : "=r"(r[0]), "=r"(r[1]), "=r"(r[2]), "=r"(r[3]) : "r"(addr));
}
__device__ __forceinline__ void ldsm_x4_t(uint32_t* r, uint32_t addr) {
    asm volatile("ldmatrix.sync.aligned.m8n8.x4.trans.shared.b16 {%0,%1,%2,%3}, [%4];\n"
        : "=r"(r[0]), "=r"(r[1]), "=r"(r[2]), "=r"(r[3]) : "r"(addr));
}
__device__ __forceinline__ void mma16816(float* c, const uint32_t* a, const uint32_t* b) {
    asm volatile(
        "mma.sync.aligned.m16n8k16.row.col.f32.bf16.bf16.f32 "
        "{%0,%1,%2,%3}, {%4,%5,%6,%7}, {%8,%9}, {%0,%1,%2,%3};\n"
        : "+f"(c[0]), "+f"(c[1]), "+f"(c[2]), "+f"(c[3])
        : "r"(a[0]), "r"(a[1]), "r"(a[2]), "r"(a[3]), "r"(b[0]), "r"(b[1]));
}
__device__ __forceinline__ uint32_t packbf2(float x, float y) {
    __nv_bfloat162 h = __floats2bfloat162_rn(x, y);
    return *(uint32_t*)&h;
}
__device__ __forceinline__ void store_pair(__nv_bfloat16* oh, __nv_bfloat16* ol,
                                           size_t idx, float a, float b) {
    float ha = __bfloat162float(__float2bfloat16(a));
    float hb = __bfloat162float(__float2bfloat16(b));
    *(uint32_t*)&oh[idx] = packbf2(ha, hb);
    *(uint32_t*)&ol[idx] = packbf2(a - ha, b - hb);
}

// ---------------- vectorized splits (8 elems/thread) ----------------
__global__ __launch_bounds__(256) void split_v4(
    const float* __restrict__ in,
    __nv_bfloat16* __restrict__ hi, __nv_bfloat16* __restrict__ lo, int n8)
{
    int i = blockIdx.x * 256 + threadIdx.x;
    if (i >= n8) return;
    const float4* p = (const float4*)in + 2 * (size_t)i;
    float4 f0 = p[0], f1 = p[1];
    float v[8] = {f0.x, f0.y, f0.z, f0.w, f1.x, f1.y, f1.z, f1.w};
    uint32_t h[4], l[4];
    #pragma unroll
    for (int k = 0; k < 4; k++) {
        float a = v[2 * k], b = v[2 * k + 1];
        float ha = __bfloat162float(__float2bfloat16(a));
        float hb = __bfloat162float(__float2bfloat16(b));
        h[k] = packbf2(ha, hb);
        l[k] = packbf2(a - ha, b - hb);
    }
    ((uint4*)hi)[i] = make_uint4(h[0], h[1], h[2], h[3]);
    ((uint4*)lo)[i] = make_uint4(l[0], l[1], l[2], l[3]);
}

__global__ __launch_bounds__(256) void split_pack_v4(
    const float* __restrict__ in,
    __nv_bfloat16* __restrict__ hi, __nv_bfloat16* __restrict__ lo,
    int cols8, int ostride8, int ooff8, int n8)
{
    int i = blockIdx.x * 256 + threadIdx.x;
    if (i >= n8) return;
    int r = i / cols8, c8 = i % cols8;
    const float4* p = (const float4*)in + 2 * (size_t)i;
    float4 f0 = p[0], f1 = p[1];
    float v[8] = {f0.x, f0.y, f0.z, f0.w, f1.x, f1.y, f1.z, f1.w};
    uint32_t h[4], l[4];
    #pragma unroll
    for (int k = 0; k < 4; k++) {
        float a = v[2 * k], b = v[2 * k + 1];
        float ha = __bfloat162float(__float2bfloat16(a));
        float hb = __bfloat162float(__float2bfloat16(b));
        h[k] = packbf2(ha, hb);
        l[k] = packbf2(a - ha, b - hb);
    }
    size_t o = (size_t)r * ostride8 + ooff8 + c8;
    ((uint4*)hi)[o] = make_uint4(h[0], h[1], h[2], h[3]);
    ((uint4*)lo)[o] = make_uint4(l[0], l[1], l[2], l[3]);
}

// ---------------- GEMM tiles: 128x128 CTA, 4 warps, 64x64 warp tile ----------------
#define BM 128
#define BN 128
#define BK 32
#define ASTRIDE 40
#define BSTRIDE 136
#define A_T (BM * ASTRIDE)
#define B_T (BK * BSTRIDE)
#define STAGE_ELEMS (2 * A_T + 2 * B_T)
#define GEMM_SMEM_BYTES (2 * STAGE_ELEMS * 2)

__device__ __forceinline__ void load_tile(
    __nv_bfloat16* sm,
    const __nv_bfloat16* __restrict__ Ah, const __nv_bfloat16* __restrict__ Al,
    const __nv_bfloat16* __restrict__ Bh, const __nv_bfloat16* __restrict__ Bl,
    int K, int NB, int m0, int n0, int k0, int t)
{
    #pragma unroll
    for (int c = t; c < 512; c += 128) {
        int row = c >> 2, col = (c & 3) * 8;
        size_t g = (size_t)(m0 + row) * K + k0 + col;
        uint32_t s = (uint32_t)(row * ASTRIDE + col);
        cp16(sptr(sm + s),       Ah + g);
        cp16(sptr(sm + A_T + s), Al + g);
    }
    #pragma unroll
    for (int c = t; c < 512; c += 128) {
        int row = c >> 4, col = (c & 15) * 8;
        size_t g = (size_t)(k0 + row) * NB + n0 + col;
        uint32_t s = (uint32_t)(row * BSTRIDE + col);
        cp16(sptr(sm + 2 * A_T + s),       Bh + g);
        cp16(sptr(sm + 2 * A_T + B_T + s), Bl + g);
    }
}

#define GEMM_MAINLOOP(Ah, Al, Bh, Bl, K, NB)                                        \
    float acc[4][8][4];                                                             \
    _Pragma("unroll")                                                               \
    for (int i = 0; i < 4; i++)                                                     \
        _Pragma("unroll")                                                           \
        for (int j = 0; j < 8; j++)                                                 \
            _Pragma("unroll")                                                       \
            for (int r = 0; r < 4; r++) acc[i][j][r] = 0.f;                         \
    const int g8 = lane >> 3;                                                       \
    const int l8 = lane & 7;                                                        \
    load_tile(sm, Ah, Al, Bh, Bl, K, NB, m0, n0, 0, t);                             \
    asm volatile("cp.async.commit_group;\n");                                       \
    const int nk = K / BK;                                                          \
    for (int kt = 0; kt < nk; kt++) {                                               \
        __nv_bfloat16* buf = sm + (kt & 1) * STAGE_ELEMS;                           \
        if (kt + 1 < nk) {                                                          \
            load_tile(sm + ((kt + 1) & 1) * STAGE_ELEMS, Ah, Al, Bh, Bl,            \
                      K, NB, m0, n0, (kt + 1) * BK, t);                             \
            asm volatile("cp.async.commit_group;\n");                               \
            asm volatile("cp.async.wait_group 1;\n");                               \
        } else {                                                                    \
            asm volatile("cp.async.wait_group 0;\n");                               \
        }                                                                           \
        __syncthreads();                                                            \
        _Pragma("unroll")                                                           \
        for (int ks = 0; ks < 2; ks++) {                                            \
            uint32_t ah[4][4], al[4][4], bh[8][2], bl[8][2];                        \
            _Pragma("unroll")                                                       \
            for (int i = 0; i < 4; i++) {                                           \
                int row = wm * 64 + i * 16 + (g8 & 1) * 8 + l8;                     \
                int col = ks * 16 + (g8 >> 1) * 8;                                  \
                ldsm_x4(ah[i], sptr(buf + row * ASTRIDE + col));                    \
                ldsm_x4(al[i], sptr(buf + A_T + row * ASTRIDE + col));              \
            }                                                                       \
            _Pragma("unroll")                                                       \
            for (int jj = 0; jj < 4; jj++) {                                        \
                int krow = ks * 16 + (g8 & 1) * 8 + l8;                             \
                int ncol = wn * 64 + jj * 16 + (g8 >> 1) * 8;                       \
                uint32_t r4[4];                                                     \
                ldsm_x4_t(r4, sptr(buf + 2 * A_T + krow * BSTRIDE + ncol));         \
                bh[2 * jj][0] = r4[0]; bh[2 * jj][1] = r4[1];                       \
                bh[2 * jj + 1][0] = r4[2]; bh[2 * jj + 1][1] = r4[3];               \
                ldsm_x4_t(r4, sptr(buf + 2 * A_T + B_T + krow * BSTRIDE + ncol));   \
                bl[2 * jj][0] = r4[0]; bl[2 * jj][1] = r4[1];                       \
                bl[2 * jj + 1][0] = r4[2]; bl[2 * jj + 1][1] = r4[3];               \
            }                                                                       \
            _Pragma("unroll")                                                       \
            for (int i = 0; i < 4; i++)                                             \
                _Pragma("unroll")                                                   \
                for (int j = 0; j < 8; j++) {                                       \
                    mma16816(acc[i][j], ah[i], bh[j]);                              \
                    mma16816(acc[i][j], ah[i], bl[j]);                              \
                    mma16816(acc[i][j], al[i], bh[j]);                              \
                }                                                                   \
        }                                                                           \
        __syncthreads();                                                            \
    }

// QKV GEMM with fused RoPE + bf16 hi/lo split epilogue
__global__ __launch_bounds__(128, 2) void qkv_gemm(
    const __nv_bfloat16* __restrict__ Ah, const __nv_bfloat16* __restrict__ Al,
    const __nv_bfloat16* __restrict__ Bh, const __nv_bfloat16* __restrict__ Bl,
    const int* __restrict__ pid,
    __nv_bfloat16* __restrict__ qh, __nv_bfloat16* __restrict__ ql,
    __nv_bfloat16* __restrict__ kh, __nv_bfloat16* __restrict__ kl,
    __nv_bfloat16* __restrict__ vh, __nv_bfloat16* __restrict__ vl)
{
    extern __shared__ __nv_bfloat16 sm[];
    const int t = threadIdx.x, lane = t & 31, w = t >> 5;
    const int wm = w >> 1, wn = w & 1;
    const int m0 = blockIdx.y * BM, n0 = blockIdx.x * BN;

    GEMM_MAINLOOP(Ah, Al, Bh, Bl, HID, NQKV)

    const int gc = n0 + wn * 64;
    __nv_bfloat16 *oh, *ol; int ldo, base; float scale;
    bool dorope;
    if (gc < 2048)      { oh = qh; ol = ql; ldo = HID; base = gc;        scale = 0.125f; dorope = true; }
    else if (gc < 2560) { oh = kh; ol = kl; ldo = 512; base = gc - 2048; scale = 1.f;    dorope = true; }
    else                { oh = vh; ol = vl; ldo = 512; base = gc - 2560; scale = 1.f;    dorope = false; }

    #pragma unroll
    for (int i = 0; i < 4; i++) {
        int r0 = m0 + wm * 64 + i * 16 + (lane >> 2);
        int r1 = r0 + 8;
        float p0 = (float)pid[r0], p1 = (float)pid[r1];
        #pragma unroll
        for (int j = 0; j < 4; j++) {
            int ch = j * 8 + (lane & 3) * 2;
            float x10 = acc[i][j][0],     x11 = acc[i][j][1];
            float x12 = acc[i][j][2],     x13 = acc[i][j][3];
            float x20 = acc[i][j + 4][0], x21 = acc[i][j + 4][1];
            float x22 = acc[i][j + 4][2], x23 = acc[i][j + 4][3];
            float y10, y11, y12, y13, y20, y21, y22, y23;
            if (dorope) {
                float inv0 = __powf(10000.f, -(float)ch * (1.f / 32.f));
                float inv1 = __powf(10000.f, -(float)(ch + 1) * (1.f / 32.f));
                float s00, c00, s01, c01, s10, c10, s11, c11;
                __sincosf(p0 * inv0, &s00, &c00);
                __sincosf(p0 * inv1, &s01, &c01);
                __sincosf(p1 * inv0, &s10, &c10);
                __sincosf(p1 * inv1, &s11, &c11);
                y10 = (x10 * c00 - x20 * s00) * scale; y20 = (x20 * c00 + x10 * s00) * scale;
                y11 = (x11 * c01 - x21 * s01) * scale; y21 = (x21 * c01 + x11 * s01) * scale;
                y12 = (x12 * c10 - x22 * s10) * scale; y22 = (x22 * c10 + x12 * s10) * scale;
                y13 = (x13 * c11 - x23 * s11) * scale; y23 = (x23 * c11 + x13 * s11) * scale;
            } else {
                y10 = x10; y11 = x11; y12 = x12; y13 = x13;
                y20 = x20; y21 = x21; y22 = x22; y23 = x23;
            }
            size_t b0 = (size_t)r0 * ldo + base + ch;
            size_t b1 = (size_t)r1 * ldo + base + ch;
            store_pair(oh, ol, b0,      y10, y11);
            store_pair(oh, ol, b0 + 32, y20, y21);
            store_pair(oh, ol, b1,      y12, y13);
            store_pair(oh, ol, b1 + 32, y22, y23);
        }
    }
}

// plain fp32-output GEMM (O projection)
__global__ __launch_bounds__(128, 2) void mma_gemm(
    const __nv_bfloat16* __restrict__ Ah, const __nv_bfloat16* __restrict__ Al,
    const __nv_bfloat16* __restrict__ Bh, const __nv_bfloat16* __restrict__ Bl,
    float* __restrict__ C, int NB, int K)
{
    extern __shared__ __nv_bfloat16 sm[];
    const int t = threadIdx.x, lane = t & 31, w = t >> 5;
    const int wm = w >> 1, wn = w & 1;
    const int m0 = blockIdx.y * BM, n0 = blockIdx.x * BN;

    GEMM_MAINLOOP(Ah, Al, Bh, Bl, K, NB)

    #pragma unroll
    for (int i = 0; i < 4; i++)
        #pragma unroll
        for (int j = 0; j < 8; j++) {
            int row = m0 + wm * 64 + i * 16 + (lane >> 2);
            int col = n0 + wn * 64 + j * 8 + (lane & 3) * 2;
            *(float2*)&C[(size_t)row * NB + col] =
                make_float2(acc[i][j][0], acc[i][j][1]);
            *(float2*)&C[(size_t)(row + 8) * NB + col] =
                make_float2(acc[i][j][2], acc[i][j][3]);
        }
}

// ---------------- tensor-core flash attention (causal) ----------------
// 64 q-rows x 4 warps per CTA; 2 CTAs/SM. K-tiles of 64 keys.
#define QHI_OFF 0
#define QLO_OFF (64 * 144)                 // 9216
#define BUF_OFF (2 * 64 * 144)             // 18432
#define KVBUF   (4 * 64 * 144)             // 36864
#define ATTN_SMEM (BUF_OFF + 2 * KVBUF)    // 92160

__device__ __forceinline__ void attn_load_kv(
    uint32_t bufb,
    const __nv_bfloat16* __restrict__ kh, const __nv_bfloat16* __restrict__ kl,
    const __nv_bfloat16* __restrict__ vh, const __nv_bfloat16* __restrict__ vl,
    int k0, int kvh, int t)
{
    #pragma unroll
    for (int i = 0; i < 4; i++) {
        int idx = i * 128 + t;
        int row = idx >> 3, cc = idx & 7;
        uint32_t off = (uint32_t)(row * 144 + cc * 16);
        size_t g = (size_t)(k0 + row) * 512 + kvh * HD + cc * 8;
        cp16(bufb + off,         kh + g);
        cp16(bufb + 9216 + off,  kl + g);
        cp16(bufb + 18432 + off, vh + g);
        cp16(bufb + 27648 + off, vl + g);
    }
}

__global__ __launch_bounds__(128, 2) void attn_tc(
    const __nv_bfloat16* __restrict__ qh, const __nv_bfloat16* __restrict__ ql,
    const __nv_bfloat16* __restrict__ kh, const __nv_bfloat16* __restrict__ kl,
    const __nv_bfloat16* __restrict__ vh, const __nv_bfloat16* __restrict__ vl,
    __nv_bfloat16* __restrict__ Oh, __nv_bfloat16* __restrict__ Ol)
{
    extern __shared__ __align__(1024) char asmem[];
    const uint32_t sb = sptr(asmem);
    const int qt  = 31 - blockIdx.x;       // big tiles first
    const int h   = blockIdx.y;
    const int kvh = h >> 2;
    const int t = threadIdx.x, w = t >> 5, lane = t & 31;
    const int g8 = lane >> 3, l8 = lane & 7, tig = lane & 3, g = lane >> 2;
    const int q0 = qt * 64;

    // load Q tile (64 rows, hi/lo) + K/V tile 0
    #pragma unroll
    for (int i = 0; i < 4; i++) {
        int idx = i * 128 + t;
        int row = idx >> 3, cc = idx & 7;
        uint32_t off = (uint32_t)(row * 144 + cc * 16);
        size_t gg = (size_t)(q0 + row) * HID + h * HD + cc * 8;
        cp16(sb + QHI_OFF + off, qh + gg);
        cp16(sb + QLO_OFF + off, ql + gg);
    }
    attn_load_kv(sb + BUF_OFF, kh, kl, vh, vl, 0, kvh, t);
    asm volatile("cp.async.commit_group;\n");
    asm volatile("cp.async.wait_group 0;\n");
    __syncthreads();

    uint32_t qah[4][4], qal[4][4];
    #pragma unroll
    for (int kc = 0; kc < 4; kc++) {
        uint32_t off = (uint32_t)((w * 16 + (g8 & 1) * 8 + l8) * 144 +
                                  (kc * 16 + (g8 >> 1) * 8) * 2);
        ldsm_x4(qah[kc], sb + QHI_OFF + off);
        ldsm_x4(qal[kc], sb + QLO_OFF + off);
    }

    float oacc[8][4];
    #pragma unroll
    for (int j = 0; j < 8; j++)
        #pragma unroll
        for (int r = 0; r < 4; r++) oacc[j][r] = 0.f;
    float m0 = -1e30f, m1 = -1e30f, l0 = 0.f, l1 = 0.f;

    const int row0 = q0 + w * 16 + g;
    const int row1 = row0 + 8;
    const int nkt = qt + 1;

    for (int kt = 0; kt < nkt; kt++) {
        const uint32_t buf = sb + BUF_OFF + (uint32_t)(kt & 1) * KVBUF;
        if (kt + 1 < nkt) {
            attn_load_kv(sb + BUF_OFF + (uint32_t)((kt + 1) & 1) * KVBUF,
                         kh, kl, vh, vl, (kt + 1) * 64, kvh, t);
            asm volatile("cp.async.commit_group;\n");
            asm volatile("cp.async.wait_group 1;\n");
        } else {
            asm volatile("cp.async.wait_group 0;\n");
        }
        __syncthreads();

        float sacc[8][4];
        #pragma unroll
        for (int j = 0; j < 8; j++)
            #pragma unroll
            for (int r = 0; r < 4; r++) sacc[j][r] = 0.f;

        #pragma unroll
        for (int kg = 0; kg < 4; kg++) {
            #pragma unroll
            for (int kc = 0; kc < 4; kc++) {
                uint32_t off = (uint32_t)((kg * 16 + (g8 & 1) * 8 + l8) * 144 +
                                          (kc * 16 + (g8 >> 1) * 8) * 2);
                uint32_t kbh[4], kbl[4];
                ldsm_x4(kbh, buf + off);
                ldsm_x4(kbl, buf + 9216 + off);
                uint32_t b0h[2] = {kbh[0], kbh[2]}, b1h[2] = {kbh[1], kbh[3]};
                uint32_t b0l[2] = {kbl[0], kbl[2]}, b1l[2] = {kbl[1], kbl[3]};
                mma16816(sacc[2 * kg],     qah[kc], b0h);
                mma16816(sacc[2 * kg],     qah[kc], b0l);
                mma16816(sacc[2 * kg],     qal[kc], b0h);
                mma16816(sacc[2 * kg + 1], qah[kc], b1h);
                mma16816(sacc[2 * kg + 1], qah[kc], b1l);
                mma16816(sacc[2 * kg + 1], qal[kc], b1h);
            }
        }

        if (kt >= qt) {   // diagonal tile
            #pragma unroll
            for (int j = 0; j < 8; j++) {
                int col = kt * 64 + j * 8 + tig * 2;
                if (col > row0)     sacc[j][0] = -1e30f;
                if (col + 1 > row0) sacc[j][1] = -1e30f;
                if (col > row1)     sacc[j][2] = -1e30f;
                if (col + 1 > row1) sacc[j][3] = -1e30f;
            }
        }

        float mx0 = -1e30f, mx1 = -1e30f;
        #pragma unroll
        for (int j = 0; j < 8; j++) {
            mx0 = fmaxf(mx0, fmaxf(sacc[j][0], sacc[j][1]));
            mx1 = fmaxf(mx1, fmaxf(sacc[j][2], sacc[j][3]));
        }
        mx0 = fmaxf(mx0, __shfl_xor_sync(0xffffffffu, mx0, 1));
        mx0 = fmaxf(mx0, __shfl_xor_sync(0xffffffffu, mx0, 2));
        mx1 = fmaxf(mx1, __shfl_xor_sync(0xffffffffu, mx1, 1));
        mx1 = fmaxf(mx1, __shfl_xor_sync(0xffffffffu, mx1, 2));

        float nm0 = fmaxf(m0, mx0), nm1 = fmaxf(m1, mx1);
        float al0 = __expf(m0 - nm0), al1 = __expf(m1 - nm1);
        m0 = nm0; m1 = nm1;

        float rs0 = 0.f, rs1 = 0.f;
        #pragma unroll
        for (int j = 0; j < 8; j++) {
            sacc[j][0] = __expf(sacc[j][0] - nm0);
            sacc[j][1] = __expf(sacc[j][1] - nm0);
            sacc[j][2] = __expf(sacc[j][2] - nm1);
            sacc[j][3] = __expf(sacc[j][3] - nm1);
            rs0 += sacc[j][0] + sacc[j][1];
            rs1 += sacc[j][2] + sacc[j][3];
        }
        rs0 += __shfl_xor_sync(0xffffffffu, rs0, 1);
        rs0 += __shfl_xor_sync(0xffffffffu, rs0, 2);
        rs1 += __shfl_xor_sync(0xffffffffu, rs1, 1);
        rs1 += __shfl_xor_sync(0xffffffffu, rs1, 2);
        l0 = l0 * al0 + rs0;
        l1 = l1 * al1 + rs1;
        #pragma unroll
        for (int j = 0; j < 8; j++) {
            oacc[j][0] *= al0; oacc[j][1] *= al0;
            oacc[j][2] *= al1; oacc[j][3] *= al1;
        }

        uint32_t pah[4][4], pal[4][4];
        #pragma unroll
        for (int kc = 0; kc < 4; kc++) {
            int j0 = 2 * kc, j1 = 2 * kc + 1;
            float p00 = sacc[j0][0], p01 = sacc[j0][1];
            float p02 = sacc[j0][2], p03 = sacc[j0][3];
            float p10 = sacc[j1][0], p11 = sacc[j1][1];
            float p12 = sacc[j1][2], p13 = sacc[j1][3];
            float h00 = __bfloat162float(__float2bfloat16(p00));
            float h01 = __bfloat162float(__float2bfloat16(p01));
            float h02 = __bfloat162float(__float2bfloat16(p02));
            float h03 = __bfloat162float(__float2bfloat16(p03));
            float h10 = __bfloat162float(__float2bfloat16(p10));
            float h11 = __bfloat162float(__float2bfloat16(p11));
            float h12 = __bfloat162float(__float2bfloat16(p12));
            float h13 = __bfloat162float(__float2bfloat16(p13));
            pah[kc][0] = packbf2(h00, h01);
            pah[kc][1] = packbf2(h02, h03);
            pah[kc][2] = packbf2(h10, h11);
            pah[kc][3] = packbf2(h12, h13);
            pal[kc][0] = packbf2(p00 - h00, p01 - h01);
            pal[kc][1] = packbf2(p02 - h02, p03 - h03);
            pal[kc][2] = packbf2(p10 - h10, p11 - h11);
            pal[kc][3] = packbf2(p12 - h12, p13 - h13);
        }

        #pragma unroll
        for (int kc = 0; kc < 4; kc++) {
            #pragma unroll
            for (int jj = 0; jj < 4; jj++) {
                uint32_t off = (uint32_t)((kc * 16 + (g8 & 1) * 8 + l8) * 144 +
                                          (jj * 16 + (g8 >> 1) * 8) * 2);
                uint32_t vbh[4], vbl[4];
                ldsm_x4_t(vbh, buf + 18432 + off);
                ldsm_x4_t(vbl, buf + 27648 + off);
                uint32_t b0h[2] = {vbh[0], vbh[1]}, b1h[2] = {vbh[2], vbh[3]};
                uint32_t b0l[2] = {vbl[0], vbl[1]}, b1l[2] = {vbl[2], vbl[3]};
                mma16816(oacc[2 * jj],     pah[kc], b0h);
                mma16816(oacc[2 * jj],     pah[kc], b0l);
                mma16816(oacc[2 * jj],     pal[kc], b0h);
                mma16816(oacc[2 * jj + 1], pah[kc], b1h);
                mma16816(oacc[2 * jj + 1], pah[kc], b1l);
                mma16816(oacc[2 * jj + 1], pal[kc], b1h);
            }
        }
        __syncthreads();
    }

    float i0 = 1.0f / l0, i1 = 1.0f / l1;
    #pragma unroll
    for (int j = 0; j < 8; j++) {
        int col = h * HD + j * 8 + tig * 2;
        float o0 = oacc[j][0] * i0, o1 = oacc[j][1] * i0;
        float o2 = oacc[j][2] * i1, o3 = oacc[j][3] * i1;
        float h0 = __bfloat162float(__float2bfloat16(o0));
        float h1 = __bfloat162float(__float2bfloat16(o1));
        float h2 = __bfloat162float(__float2bfloat16(o2));
        float h3 = __bfloat162float(__float2bfloat16(o3));
        *(uint32_t*)&Oh[(size_t)row0 * HID + col] = packbf2(h0, h1);
        *(uint32_t*)&Oh[(size_t)row1 * HID + col] = packbf2(h2, h3);
        *(uint32_t*)&Ol[(size_t)row0 * HID + col] = packbf2(o0 - h0, o1 - h1);
        *(uint32_t*)&Ol[(size_t)row1 * HID + col] = packbf2(o2 - h2, o3 - h3);
    }
}

// ---------------- launch ----------------
extern "C" void kernel_launch(void* const* d_in, const int* in_sizes, int n_in,
                              void* d_out, int out_size)
{
    const float* X   = (const float*)d_in[0];
    const int*   pid = (const int*)d_in[2];
    const float* Wq  = (const float*)d_in[3];
    const float* Wk  = (const float*)d_in[4];
    const float* Wv  = (const float*)d_in[5];
    const float* Wo  = (const float*)d_in[6];
    float* out = (float*)d_out;

    __nv_bfloat16 *Xh, *Xl, *Wqkvh, *Wqkvl, *Woh, *Wol, *Ah, *Al;
    __nv_bfloat16 *qh, *ql, *kh, *kl, *vh, *vl;
    cudaGetSymbolAddress((void**)&Xh,   g_Xhi);    cudaGetSymbolAddress((void**)&Xl,   g_Xlo);
    cudaGetSymbolAddress((void**)&Wqkvh,g_Wqkvh);  cudaGetSymbolAddress((void**)&Wqkvl,g_Wqkvl);
    cudaGetSymbolAddress((void**)&Woh,  g_Wohi);   cudaGetSymbolAddress((void**)&Wol,  g_Wolo);
    cudaGetSymbolAddress((void**)&Ah,   g_Ahi);    cudaGetSymbolAddress((void**)&Al,   g_Alo);
    cudaGetSymbolAddress((void**)&qh,   g_qh);     cudaGetSymbolAddress((void**)&ql,   g_ql);
    cudaGetSymbolAddress((void**)&kh,   g_kh);     cudaGetSymbolAddress((void**)&kl,   g_kl);
    cudaGetSymbolAddress((void**)&vh,   g_vh);     cudaGetSymbolAddress((void**)&vl,   g_vl);

    cudaFuncSetAttribute(qkv_gemm, cudaFuncAttributeMaxDynamicSharedMemorySize, GEMM_SMEM_BYTES);
    cudaFuncSetAttribute(mma_gemm, cudaFuncAttributeMaxDynamicSharedMemorySize, GEMM_SMEM_BYTES);
    cudaFuncSetAttribute(attn_tc, cudaFuncAttributeMaxDynamicSharedMemorySize, ATTN_SMEM);

    // vectorized splits
    split_v4<<<(S_LEN * HID / 8 + 255) / 256, 256>>>(X, Xh, Xl, S_LEN * HID / 8);
    split_pack_v4<<<(HID * 2048 / 8 + 255) / 256, 256>>>(
        Wq, Wqkvh, Wqkvl, 2048 / 8, NQKV / 8, 0, HID * 2048 / 8);
    split_pack_v4<<<(HID * 512 / 8 + 255) / 256, 256>>>(
        Wk, Wqkvh, Wqkvl, 512 / 8, NQKV / 8, 2048 / 8, HID * 512 / 8);
    split_pack_v4<<<(HID * 512 / 8 + 255) / 256, 256>>>(
        Wv, Wqkvh, Wqkvl, 512 / 8, NQKV / 8, 2560 / 8, HID * 512 / 8);
    split_v4<<<(HID * HID / 8 + 255) / 256, 256>>>(Wo, Woh, Wol, HID * HID / 8);

    // fused QKV projection + RoPE + bf16 split
    qkv_gemm<<<dim3(NQKV / BN, S_LEN / BM), 128, GEMM_SMEM_BYTES>>>(
        Xh, Xl, Wqkvh, Wqkvl, pid, qh, ql, kh, kl, vh, vl);

    // attention: 64-row CTAs, 2 CTAs/SM
    attn_tc<<<dim3(32, NH), 128, ATTN_SMEM>>>(qh, ql, kh, kl, vh, vl, Ah, Al);

    // O projection
    mma_gemm<<<dim3(HID / BN, S_LEN / BM), 128, GEMM_SMEM_BYTES>>>(
        Ah, Al, Woh, Wol, out, HID, HID);
}

// round 10
// speedup vs baseline: 2.0567x; 1.2320x over previous
#include <cuda_runtime.h>
#include <cuda_bf16.h>
#include <cuda_fp16.h>
#include <math.h>
#include <stdint.h>

#define S_LEN 2048
#define HID   2048
#define NH    32
#define NKV   8
#define HD    64
#define KVW   1024
#define NQKV  3072

// ---------------- scratch ----------------
__device__ __half g_Xh16 [S_LEN * HID];                 // A for QKV (single fp16)
__device__ __half g_Wqkvh16[HID * NQKV], g_Wqkvl16[HID * NQKV];
__device__ __half g_Woh16[HID * HID],    g_Wol16[HID * HID];
__device__ __half g_A16 [S_LEN * HID];                  // attention out (single fp16)

// attention operands (bf16 hi/lo after RoPE) — attention kernel unchanged
__device__ __nv_bfloat16 g_qh[S_LEN * HID], g_ql[S_LEN * HID];
__device__ __nv_bfloat16 g_kh[S_LEN * 512], g_kl[S_LEN * 512];
__device__ __nv_bfloat16 g_vh[S_LEN * 512], g_vl[S_LEN * 512];

// ---------------- helpers ----------------
__device__ __forceinline__ uint32_t sptr(const void* p) {
    return (uint32_t)__cvta_generic_to_shared(p);
}
__device__ __forceinline__ void cp16(uint32_t dst, const void* src) {
    asm volatile("cp.async.cg.shared.global [%0], [%1], 16;\n" :: "r"(dst), "l"(src));
}
__device__ __forceinline__ void ldsm_x4(uint32_t* r, uint32_t addr) {
    asm volatile("ldmatrix.sync.aligned.m8n8.x4.shared.b16 {%0,%1,%2,%3}, [%4];\n"
        : "=r"(r[0]), "=r"(r[1]), "=r"(r[2]), "=r"(r[3]) : "r"(addr));
}
__device__ __forceinline__ void ldsm_x4_t(uint32_t* r, uint32_t addr) {
    asm volatile("ldmatrix.sync.aligned.m8n8.x4.trans.shared.b16 {%0,%1,%2,%3}, [%4];\n"
        : "=r"(r[0]), "=r"(r[1]), "=r"(r[2]), "=r"(r[3]) : "r"(addr));
}
__device__ __forceinline__ void mma16816(float* c, const uint32_t* a, const uint32_t* b) {
    asm volatile(
        "mma.sync.aligned.m16n8k16.row.col.f32.bf16.bf16.f32 "
        "{%0,%1,%2,%3}, {%4,%5,%6,%7}, {%8,%9}, {%0,%1,%2,%3};\n"
        : "+f"(c[0]), "+f"(c[1]), "+f"(c[2]), "+f"(c[3])
        : "r"(a[0]), "r"(a[1]), "r"(a[2]), "r"(a[3]), "r"(b[0]), "r"(b[1]));
}
__device__ __forceinline__ void mma16816h(float* c, const uint32_t* a, const uint32_t* b) {
    asm volatile(
        "mma.sync.aligned.m16n8k16.row.col.f32.f16.f16.f32 "
        "{%0,%1,%2,%3}, {%4,%5,%6,%7}, {%8,%9}, {%0,%1,%2,%3};\n"
        : "+f"(c[0]), "+f"(c[1]), "+f"(c[2]), "+f"(c[3])
        : "r"(a[0]), "r"(a[1]), "r"(a[2]), "r"(a[3]), "r"(b[0]), "r"(b[1]));
}
__device__ __forceinline__ uint32_t packbf2(float x, float y) {
    __nv_bfloat162 h = __floats2bfloat162_rn(x, y);
    return *(uint32_t*)&h;
}
__device__ __forceinline__ uint32_t packh2(float x, float y) {
    __half2 h = __floats2half2_rn(x, y);
    return *(uint32_t*)&h;
}
__device__ __forceinline__ void store_pair(__nv_bfloat16* oh, __nv_bfloat16* ol,
                                           size_t idx, float a, float b) {
    float ha = __bfloat162float(__float2bfloat16(a));
    float hb = __bfloat162float(__float2bfloat16(b));
    *(uint32_t*)&oh[idx] = packbf2(ha, hb);
    *(uint32_t*)&ol[idx] = packbf2(a - ha, b - hb);
}

// ---------------- conversion kernels ----------------
// fp32 -> single fp16, 8 elems/thread
__global__ __launch_bounds__(256) void cvt_h16_v4(
    const float* __restrict__ in, __half* __restrict__ out, int n8)
{
    int i = blockIdx.x * 256 + threadIdx.x;
    if (i >= n8) return;
    const float4* p = (const float4*)in + 2 * (size_t)i;
    float4 f0 = p[0], f1 = p[1];
    uint32_t h[4];
    h[0] = packh2(f0.x, f0.y); h[1] = packh2(f0.z, f0.w);
    h[2] = packh2(f1.x, f1.y); h[3] = packh2(f1.z, f1.w);
    ((uint4*)out)[i] = make_uint4(h[0], h[1], h[2], h[3]);
}

// fp32 -> fp16 hi/lo split with optional column packing, 8 elems/thread
__global__ __launch_bounds__(256) void split_h16_pack_v4(
    const float* __restrict__ in,
    __half* __restrict__ hi, __half* __restrict__ lo,
    int cols8, int ostride8, int ooff8, int n8)
{
    int i = blockIdx.x * 256 + threadIdx.x;
    if (i >= n8) return;
    int r = i / cols8, c8 = i % cols8;
    const float4* p = (const float4*)in + 2 * (size_t)i;
    float4 f0 = p[0], f1 = p[1];
    float v[8] = {f0.x, f0.y, f0.z, f0.w, f1.x, f1.y, f1.z, f1.w};
    uint32_t h[4], l[4];
    #pragma unroll
    for (int k = 0; k < 4; k++) {
        float a = v[2 * k], b = v[2 * k + 1];
        float ha = __half2float(__float2half_rn(a));
        float hb = __half2float(__float2half_rn(b));
        h[k] = packh2(a, b);            // hi = rn(x)
        l[k] = packh2(a - ha, b - hb);  // lo = x - rn(x)
    }
    size_t o = (size_t)r * ostride8 + ooff8 + c8;
    ((uint4*)hi)[o] = make_uint4(h[0], h[1], h[2], h[3]);
    ((uint4*)lo)[o] = make_uint4(l[0], l[1], l[2], l[3]);
}

// ---------------- fp16 2-pass GEMM: 128x128 CTA, 4 warps, 64x64 warp tile ----------------
#define BM 128
#define BN 128
#define BK 32
#define ASTRIDE 40
#define BSTRIDE 136
#define A_T (BM * ASTRIDE)                 // 5120 elems
#define B_T (BK * BSTRIDE)                 // 4352 elems
#define STAGE_F16 (A_T + 2 * B_T)          // 13824 elems
#define GEMM_SMEM_F16 (2 * STAGE_F16 * 2)  // 55296 bytes

__device__ __forceinline__ void load_tile_f16(
    __half* sm, const __half* __restrict__ A,
    const __half* __restrict__ Bh, const __half* __restrict__ Bl,
    int K, int NB, int m0, int n0, int k0, int t)
{
    #pragma unroll
    for (int c = t; c < 512; c += 128) {       // A: 128x32
        int row = c >> 2, col = (c & 3) * 8;
        size_t g = (size_t)(m0 + row) * K + k0 + col;
        cp16(sptr(sm + row * ASTRIDE + col), A + g);
    }
    #pragma unroll
    for (int c = t; c < 512; c += 128) {       // B: 32x128, hi+lo
        int row = c >> 4, col = (c & 15) * 8;
        size_t g = (size_t)(k0 + row) * NB + n0 + col;
        uint32_t s = (uint32_t)(row * BSTRIDE + col);
        cp16(sptr(sm + A_T + s),       Bh + g);
        cp16(sptr(sm + A_T + B_T + s), Bl + g);
    }
}

#define GEMM_MAINLOOP_F16(A, Bh, Bl, K, NB)                                         \
    float acc[4][8][4];                                                             \
    _Pragma("unroll")                                                               \
    for (int i = 0; i < 4; i++)                                                     \
        _Pragma("unroll")                                                           \
        for (int j = 0; j < 8; j++)                                                 \
            _Pragma("unroll")                                                       \
            for (int r = 0; r < 4; r++) acc[i][j][r] = 0.f;                         \
    const int g8 = lane >> 3;                                                       \
    const int l8 = lane & 7;                                                        \
    load_tile_f16(sm, A, Bh, Bl, K, NB, m0, n0, 0, t);                              \
    asm volatile("cp.async.commit_group;\n");                                       \
    const int nk = K / BK;                                                          \
    for (int kt = 0; kt < nk; kt++) {                                               \
        __half* buf = sm + (kt & 1) * STAGE_F16;                                    \
        if (kt + 1 < nk) {                                                          \
            load_tile_f16(sm + ((kt + 1) & 1) * STAGE_F16, A, Bh, Bl,               \
                          K, NB, m0, n0, (kt + 1) * BK, t);                         \
            asm volatile("cp.async.commit_group;\n");                               \
            asm volatile("cp.async.wait_group 1;\n");                               \
        } else {                                                                    \
            asm volatile("cp.async.wait_group 0;\n");                               \
        }                                                                           \
        __syncthreads();                                                            \
        _Pragma("unroll")                                                           \
        for (int ks = 0; ks < 2; ks++) {                                            \
            uint32_t ah[4][4], bh[8][2], bl[8][2];                                  \
            _Pragma("unroll")                                                       \
            for (int i = 0; i < 4; i++) {                                           \
                int row = wm * 64 + i * 16 + (g8 & 1) * 8 + l8;                     \
                int col = ks * 16 + (g8 >> 1) * 8;                                  \
                ldsm_x4(ah[i], sptr(buf + row * ASTRIDE + col));                    \
            }                                                                       \
            _Pragma("unroll")                                                       \
            for (int jj = 0; jj < 4; jj++) {                                        \
                int krow = ks * 16 + (g8 & 1) * 8 + l8;                             \
                int ncol = wn * 64 + jj * 16 + (g8 >> 1) * 8;                       \
                uint32_t r4[4];                                                     \
                ldsm_x4_t(r4, sptr(buf + A_T + krow * BSTRIDE + ncol));             \
                bh[2 * jj][0] = r4[0]; bh[2 * jj][1] = r4[1];                       \
                bh[2 * jj + 1][0] = r4[2]; bh[2 * jj + 1][1] = r4[3];               \
                ldsm_x4_t(r4, sptr(buf + A_T + B_T + krow * BSTRIDE + ncol));       \
                bl[2 * jj][0] = r4[0]; bl[2 * jj][1] = r4[1];                       \
                bl[2 * jj + 1][0] = r4[2]; bl[2 * jj + 1][1] = r4[3];               \
            }                                                                       \
            _Pragma("unroll")                                                       \
            for (int i = 0; i < 4; i++)                                             \
                _Pragma("unroll")                                                   \
                for (int j = 0; j < 8; j++) {                                       \
                    mma16816h(acc[i][j], ah[i], bh[j]);                             \
                    mma16816h(acc[i][j], ah[i], bl[j]);                             \
                }                                                                   \
        }                                                                           \
        __syncthreads();                                                            \
    }

// QKV GEMM with fused RoPE + bf16 hi/lo split epilogue
__global__ __launch_bounds__(128, 2) void qkv_gemm(
    const __half* __restrict__ A,
    const __half* __restrict__ Bh, const __half* __restrict__ Bl,
    const int* __restrict__ pid,
    __nv_bfloat16* __restrict__ qh, __nv_bfloat16* __restrict__ ql,
    __nv_bfloat16* __restrict__ kh, __nv_bfloat16* __restrict__ kl,
    __nv_bfloat16* __restrict__ vh, __nv_bfloat16* __restrict__ vl)
{
    extern __shared__ __half sm[];
    const int t = threadIdx.x, lane = t & 31, w = t >> 5;
    const int wm = w >> 1, wn = w & 1;
    const int m0 = blockIdx.y * BM, n0 = blockIdx.x * BN;

    GEMM_MAINLOOP_F16(A, Bh, Bl, HID, NQKV)

    const int gc = n0 + wn * 64;
    __nv_bfloat16 *oh, *ol; int ldo, base; float scale;
    bool dorope;
    if (gc < 2048)      { oh = qh; ol = ql; ldo = HID; base = gc;        scale = 0.125f; dorope = true; }
    else if (gc < 2560) { oh = kh; ol = kl; ldo = 512; base = gc - 2048; scale = 1.f;    dorope = true; }
    else                { oh = vh; ol = vl; ldo = 512; base = gc - 2560; scale = 1.f;    dorope = false; }

    #pragma unroll
    for (int i = 0; i < 4; i++) {
        int r0 = m0 + wm * 64 + i * 16 + (lane >> 2);
        int r1 = r0 + 8;
        float p0 = (float)pid[r0], p1 = (float)pid[r1];
        #pragma unroll
        for (int j = 0; j < 4; j++) {
            int ch = j * 8 + (lane & 3) * 2;
            float x10 = acc[i][j][0],     x11 = acc[i][j][1];
            float x12 = acc[i][j][2],     x13 = acc[i][j][3];
            float x20 = acc[i][j + 4][0], x21 = acc[i][j + 4][1];
            float x22 = acc[i][j + 4][2], x23 = acc[i][j + 4][3];
            float y10, y11, y12, y13, y20, y21, y22, y23;
            if (dorope) {
                float inv0 = __powf(10000.f, -(float)ch * (1.f / 32.f));
                float inv1 = __powf(10000.f, -(float)(ch + 1) * (1.f / 32.f));
                float s00, c00, s01, c01, s10, c10, s11, c11;
                __sincosf(p0 * inv0, &s00, &c00);
                __sincosf(p0 * inv1, &s01, &c01);
                __sincosf(p1 * inv0, &s10, &c10);
                __sincosf(p1 * inv1, &s11, &c11);
                y10 = (x10 * c00 - x20 * s00) * scale; y20 = (x20 * c00 + x10 * s00) * scale;
                y11 = (x11 * c01 - x21 * s01) * scale; y21 = (x21 * c01 + x11 * s01) * scale;
                y12 = (x12 * c10 - x22 * s10) * scale; y22 = (x22 * c10 + x12 * s10) * scale;
                y13 = (x13 * c11 - x23 * s11) * scale; y23 = (x23 * c11 + x13 * s11) * scale;
            } else {
                y10 = x10; y11 = x11; y12 = x12; y13 = x13;
                y20 = x20; y21 = x21; y22 = x22; y23 = x23;
            }
            size_t b0 = (size_t)r0 * ldo + base + ch;
            size_t b1 = (size_t)r1 * ldo + base + ch;
            store_pair(oh, ol, b0,      y10, y11);
            store_pair(oh, ol, b0 + 32, y20, y21);
            store_pair(oh, ol, b1,      y12, y13);
            store_pair(oh, ol, b1 + 32, y22, y23);
        }
    }
}

// O projection: fp16 2-pass, fp32 output
__global__ __launch_bounds__(128, 2) void oproj_gemm(
    const __half* __restrict__ A,
    const __half* __restrict__ Bh, const __half* __restrict__ Bl,
    float* __restrict__ C)
{
    extern __shared__ __half sm[];
    const int t = threadIdx.x, lane = t & 31, w = t >> 5;
    const int wm = w >> 1, wn = w & 1;
    const int m0 = blockIdx.y * BM, n0 = blockIdx.x * BN;

    GEMM_MAINLOOP_F16(A, Bh, Bl, HID, HID)

    #pragma unroll
    for (int i = 0; i < 4; i++)
        #pragma unroll
        for (int j = 0; j < 8; j++) {
            int row = m0 + wm * 64 + i * 16 + (lane >> 2);
            int col = n0 + wn * 64 + j * 8 + (lane & 3) * 2;
            *(float2*)&C[(size_t)row * HID + col] =
                make_float2(acc[i][j][0], acc[i][j][1]);
            *(float2*)&C[(size_t)(row + 8) * HID + col] =
                make_float2(acc[i][j][2], acc[i][j][3]);
        }
}

// ---------------- tensor-core flash attention (causal, bf16x3, unchanged math) ----------------
#define QHI_OFF 0
#define QLO_OFF (64 * 144)
#define BUF_OFF (2 * 64 * 144)
#define KVBUF   (4 * 64 * 144)
#define ATTN_SMEM (BUF_OFF + 2 * KVBUF)

__device__ __forceinline__ void attn_load_kv(
    uint32_t bufb,
    const __nv_bfloat16* __restrict__ kh, const __nv_bfloat16* __restrict__ kl,
    const __nv_bfloat16* __restrict__ vh, const __nv_bfloat16* __restrict__ vl,
    int k0, int kvh, int t)
{
    #pragma unroll
    for (int i = 0; i < 4; i++) {
        int idx = i * 128 + t;
        int row = idx >> 3, cc = idx & 7;
        uint32_t off = (uint32_t)(row * 144 + cc * 16);
        size_t g = (size_t)(k0 + row) * 512 + kvh * HD + cc * 8;
        cp16(bufb + off,         kh + g);
        cp16(bufb + 9216 + off,  kl + g);
        cp16(bufb + 18432 + off, vh + g);
        cp16(bufb + 27648 + off, vl + g);
    }
}

__global__ __launch_bounds__(128, 2) void attn_tc(
    const __nv_bfloat16* __restrict__ qh, const __nv_bfloat16* __restrict__ ql,
    const __nv_bfloat16* __restrict__ kh, const __nv_bfloat16* __restrict__ kl,
    const __nv_bfloat16* __restrict__ vh, const __nv_bfloat16* __restrict__ vl,
    __half* __restrict__ Aout)
{
    extern __shared__ __align__(1024) char asmem[];
    const uint32_t sb = sptr(asmem);
    const int qt  = 31 - blockIdx.x;
    const int h   = blockIdx.y;
    const int kvh = h >> 2;
    const int t = threadIdx.x, w = t >> 5, lane = t & 31;
    const int g8 = lane >> 3, l8 = lane & 7, tig = lane & 3, g = lane >> 2;
    const int q0 = qt * 64;

    #pragma unroll
    for (int i = 0; i < 4; i++) {
        int idx = i * 128 + t;
        int row = idx >> 3, cc = idx & 7;
        uint32_t off = (uint32_t)(row * 144 + cc * 16);
        size_t gg = (size_t)(q0 + row) * HID + h * HD + cc * 8;
        cp16(sb + QHI_OFF + off, qh + gg);
        cp16(sb + QLO_OFF + off, ql + gg);
    }
    attn_load_kv(sb + BUF_OFF, kh, kl, vh, vl, 0, kvh, t);
    asm volatile("cp.async.commit_group;\n");
    asm volatile("cp.async.wait_group 0;\n");
    __syncthreads();

    uint32_t qah[4][4], qal[4][4];
    #pragma unroll
    for (int kc = 0; kc < 4; kc++) {
        uint32_t off = (uint32_t)((w * 16 + (g8 & 1) * 8 + l8) * 144 +
                                  (kc * 16 + (g8 >> 1) * 8) * 2);
        ldsm_x4(qah[kc], sb + QHI_OFF + off);
        ldsm_x4(qal[kc], sb + QLO_OFF + off);
    }

    float oacc[8][4];
    #pragma unroll
    for (int j = 0; j < 8; j++)
        #pragma unroll
        for (int r = 0; r < 4; r++) oacc[j][r] = 0.f;
    float m0 = -1e30f, m1 = -1e30f, l0 = 0.f, l1 = 0.f;

    const int row0 = q0 + w * 16 + g;
    const int row1 = row0 + 8;
    const int nkt = qt + 1;

    for (int kt = 0; kt < nkt; kt++) {
        const uint32_t buf = sb + BUF_OFF + (uint32_t)(kt & 1) * KVBUF;
        if (kt + 1 < nkt) {
            attn_load_kv(sb + BUF_OFF + (uint32_t)((kt + 1) & 1) * KVBUF,
                         kh, kl, vh, vl, (kt + 1) * 64, kvh, t);
            asm volatile("cp.async.commit_group;\n");
            asm volatile("cp.async.wait_group 1;\n");
        } else {
            asm volatile("cp.async.wait_group 0;\n");
        }
        __syncthreads();

        float sacc[8][4];
        #pragma unroll
        for (int j = 0; j < 8; j++)
            #pragma unroll
            for (int r = 0; r < 4; r++) sacc[j][r] = 0.f;

        #pragma unroll
        for (int kg = 0; kg < 4; kg++) {
            #pragma unroll
            for (int kc = 0; kc < 4; kc++) {
                uint32_t off = (uint32_t)((kg * 16 + (g8 & 1) * 8 + l8) * 144 +
                                          (kc * 16 + (g8 >> 1) * 8) * 2);
                uint32_t kbh[4], kbl[4];
                ldsm_x4(kbh, buf + off);
                ldsm_x4(kbl, buf + 9216 + off);
                uint32_t b0h[2] = {kbh[0], kbh[2]}, b1h[2] = {kbh[1], kbh[3]};
                uint32_t b0l[2] = {kbl[0], kbl[2]}, b1l[2] = {kbl[1], kbl[3]};
                mma16816(sacc[2 * kg],     qah[kc], b0h);
                mma16816(sacc[2 * kg],     qah[kc], b0l);
                mma16816(sacc[2 * kg],     qal[kc], b0h);
                mma16816(sacc[2 * kg + 1], qah[kc], b1h);
                mma16816(sacc[2 * kg + 1], qah[kc], b1l);
                mma16816(sacc[2 * kg + 1], qal[kc], b1h);
            }
        }

        if (kt >= qt) {
            #pragma unroll
            for (int j = 0; j < 8; j++) {
                int col = kt * 64 + j * 8 + tig * 2;
                if (col > row0)     sacc[j][0] = -1e30f;
                if (col + 1 > row0) sacc[j][1] = -1e30f;
                if (col > row1)     sacc[j][2] = -1e30f;
                if (col + 1 > row1) sacc[j][3] = -1e30f;
            }
        }

        float mx0 = -1e30f, mx1 = -1e30f;
        #pragma unroll
        for (int j = 0; j < 8; j++) {
            mx0 = fmaxf(mx0, fmaxf(sacc[j][0], sacc[j][1]));
            mx1 = fmaxf(mx1, fmaxf(sacc[j][2], sacc[j][3]));
        }
        mx0 = fmaxf(mx0, __shfl_xor_sync(0xffffffffu, mx0, 1));
        mx0 = fmaxf(mx0, __shfl_xor_sync(0xffffffffu, mx0, 2));
        mx1 = fmaxf(mx1, __shfl_xor_sync(0xffffffffu, mx1, 1));
        mx1 = fmaxf(mx1, __shfl_xor_sync(0xffffffffu, mx1, 2));

        float nm0 = fmaxf(m0, mx0), nm1 = fmaxf(m1, mx1);
        float al0 = __expf(m0 - nm0), al1 = __expf(m1 - nm1);
        m0 = nm0; m1 = nm1;

        float rs0 = 0.f, rs1 = 0.f;
        #pragma unroll
        for (int j = 0; j < 8; j++) {
            sacc[j][0] = __expf(sacc[j][0] - nm0);
            sacc[j][1] = __expf(sacc[j][1] - nm0);
            sacc[j][2] = __expf(sacc[j][2] - nm1);
            sacc[j][3] = __expf(sacc[j][3] - nm1);
            rs0 += sacc[j][0] + sacc[j][1];
            rs1 += sacc[j][2] + sacc[j][3];
        }
        rs0 += __shfl_xor_sync(0xffffffffu, rs0, 1);
        rs0 += __shfl_xor_sync(0xffffffffu, rs0, 2);
        rs1 += __shfl_xor_sync(0xffffffffu, rs1, 1);
        rs1 += __shfl_xor_sync(0xffffffffu, rs1, 2);
        l0 = l0 * al0 + rs0;
        l1 = l1 * al1 + rs1;
        #pragma unroll
        for (int j = 0; j < 8; j++) {
            oacc[j][0] *= al0; oacc[j][1] *= al0;
            oacc[j][2] *= al1; oacc[j][3] *= al1;
        }

        uint32_t pah[4][4], pal[4][4];
        #pragma unroll
        for (int kc = 0; kc < 4; kc++) {
            int j0 = 2 * kc, j1 = 2 * kc + 1;
            float p00 = sacc[j0][0], p01 = sacc[j0][1];
            float p02 = sacc[j0][2], p03 = sacc[j0][3];
            float p10 = sacc[j1][0], p11 = sacc[j1][1];
            float p12 = sacc[j1][2], p13 = sacc[j1][3];
            float h00 = __bfloat162float(__float2bfloat16(p00));
            float h01 = __bfloat162float(__float2bfloat16(p01));
            float h02 = __bfloat162float(__float2bfloat16(p02));
            float h03 = __bfloat162float(__float2bfloat16(p03));
            float h10 = __bfloat162float(__float2bfloat16(p10));
            float h11 = __bfloat162float(__float2bfloat16(p11));
            float h12 = __bfloat162float(__float2bfloat16(p12));
            float h13 = __bfloat162float(__float2bfloat16(p13));
            pah[kc][0] = packbf2(h00, h01);
            pah[kc][1] = packbf2(h02, h03);
            pah[kc][2] = packbf2(h10, h11);
            pah[kc][3] = packbf2(h12, h13);
            pal[kc][0] = packbf2(p00 - h00, p01 - h01);
            pal[kc][1] = packbf2(p02 - h02, p03 - h03);
            pal[kc][2] = packbf2(p10 - h10, p11 - h11);
            pal[kc][3] = packbf2(p12 - h12, p13 - h13);
        }

        #pragma unroll
        for (int kc = 0; kc < 4; kc++) {
            #pragma unroll
            for (int jj = 0; jj < 4; jj++) {
                uint32_t off = (uint32_t)((kc * 16 + (g8 & 1) * 8 + l8) * 144 +
                                          (jj * 16 + (g8 >> 1) * 8) * 2);
                uint32_t vbh[4], vbl[4];
                ldsm_x4_t(vbh, buf + 18432 + off);
                ldsm_x4_t(vbl, buf + 27648 + off);
                uint32_t b0h[2] = {vbh[0], vbh[1]}, b1h[2] = {vbh[2], vbh[3]};
                uint32_t b0l[2] = {vbl[0], vbl[1]}, b1l[2] = {vbl[2], vbl[3]};
                mma16816(oacc[2 * jj],     pah[kc], b0h);
                mma16816(oacc[2 * jj],     pah[kc], b0l);
                mma16816(oacc[2 * jj],     pal[kc], b0h);
                mma16816(oacc[2 * jj + 1], pah[kc], b1h);
                mma16816(oacc[2 * jj + 1], pah[kc], b1l);
                mma16816(oacc[2 * jj + 1], pal[kc], b1h);
            }
        }
        __syncthreads();
    }

    // epilogue: single fp16 A for the 2-pass O-proj
    float i0 = 1.0f / l0, i1 = 1.0f / l1;
    #pragma unroll
    for (int j = 0; j < 8; j++) {
        int col = h * HD + j * 8 + tig * 2;
        float o0 = oacc[j][0] * i0, o1 = oacc[j][1] * i0;
        float o2 = oacc[j][2] * i1, o3 = oacc[j][3] * i1;
        *(uint32_t*)&Aout[(size_t)row0 * HID + col] = packh2(o0, o1);
        *(uint32_t*)&Aout[(size_t)row1 * HID + col] = packh2(o2, o3);
    }
}

// ---------------- launch ----------------
extern "C" void kernel_launch(void* const* d_in, const int* in_sizes, int n_in,
                              void* d_out, int out_size)
{
    const float* X   = (const float*)d_in[0];
    const int*   pid = (const int*)d_in[2];
    const float* Wq  = (const float*)d_in[3];
    const float* Wk  = (const float*)d_in[4];
    const float* Wv  = (const float*)d_in[5];
    const float* Wo  = (const float*)d_in[6];
    float* out = (float*)d_out;

    __half *Xh, *Wqkvh, *Wqkvl, *Woh, *Wol, *A16;
    __nv_bfloat16 *qh, *ql, *kh, *kl, *vh, *vl;
    cudaGetSymbolAddress((void**)&Xh,    g_Xh16);
    cudaGetSymbolAddress((void**)&Wqkvh, g_Wqkvh16);
    cudaGetSymbolAddress((void**)&Wqkvl, g_Wqkvl16);
    cudaGetSymbolAddress((void**)&Woh,   g_Woh16);
    cudaGetSymbolAddress((void**)&Wol,   g_Wol16);
    cudaGetSymbolAddress((void**)&A16,   g_A16);
    cudaGetSymbolAddress((void**)&qh,    g_qh);  cudaGetSymbolAddress((void**)&ql, g_ql);
    cudaGetSymbolAddress((void**)&kh,    g_kh);  cudaGetSymbolAddress((void**)&kl, g_kl);
    cudaGetSymbolAddress((void**)&vh,    g_vh);  cudaGetSymbolAddress((void**)&vl, g_vl);

    cudaFuncSetAttribute(qkv_gemm,  cudaFuncAttributeMaxDynamicSharedMemorySize, GEMM_SMEM_F16);
    cudaFuncSetAttribute(oproj_gemm,cudaFuncAttributeMaxDynamicSharedMemorySize, GEMM_SMEM_F16);
    cudaFuncSetAttribute(attn_tc,   cudaFuncAttributeMaxDynamicSharedMemorySize, ATTN_SMEM);

    // conversions
    cvt_h16_v4<<<(S_LEN * HID / 8 + 255) / 256, 256>>>(X, Xh, S_LEN * HID / 8);
    split_h16_pack_v4<<<(HID * 2048 / 8 + 255) / 256, 256>>>(
        Wq, Wqkvh, Wqkvl, 2048 / 8, NQKV / 8, 0, HID * 2048 / 8);
    split_h16_pack_v4<<<(HID * 512 / 8 + 255) / 256, 256>>>(
        Wk, Wqkvh, Wqkvl, 512 / 8, NQKV / 8, 2048 / 8, HID * 512 / 8);
    split_h16_pack_v4<<<(HID * 512 / 8 + 255) / 256, 256>>>(
        Wv, Wqkvh, Wqkvl, 512 / 8, NQKV / 8, 2560 / 8, HID * 512 / 8);
    split_h16_pack_v4<<<(HID * HID / 8 + 255) / 256, 256>>>(
        Wo, Woh, Wol, HID / 8, HID / 8, 0, HID * HID / 8);

    // fused QKV projection + RoPE + bf16 split (fp16 2-pass)
    qkv_gemm<<<dim3(NQKV / BN, S_LEN / BM), 128, GEMM_SMEM_F16>>>(
        Xh, Wqkvh, Wqkvl, pid, qh, ql, kh, kl, vh, vl);

    // attention (bf16x3) -> single fp16 A
    attn_tc<<<dim3(32, NH), 128, ATTN_SMEM>>>(qh, ql, kh, kl, vh, vl, A16);

    // O projection (fp16 2-pass)
    oproj_gemm<<<dim3(HID / BN, S_LEN / BM), 128, GEMM_SMEM_F16>>>(
        A16, Woh, Wol, out);
}

// round 12
// speedup vs baseline: 2.2571x; 1.0975x over previous
#include <cuda_runtime.h>
#include <cuda_bf16.h>
#include <cuda_fp16.h>
#include <math.h>
#include <stdint.h>

#define S_LEN 2048
#define HID   2048
#define NH    32
#define NKV   8
#define HD    64
#define KVW   1024
#define NQKV  3072

// ---------------- scratch ----------------
__device__ __half g_Xh16 [S_LEN * HID];
__device__ __half g_Wqkvh16[HID * NQKV], g_Wqkvl16[HID * NQKV];
__device__ __half g_Woh16[HID * HID],    g_Wol16[HID * HID];
__device__ __half g_A16 [S_LEN * HID];

// attention operands (fp16 after RoPE): Q single, K/V hi+lo
__device__ __half g_q16[S_LEN * HID];
__device__ __half g_kh16[S_LEN * 512], g_kl16[S_LEN * 512];
__device__ __half g_vh16[S_LEN * 512], g_vl16[S_LEN * 512];

// ---------------- helpers ----------------
__device__ __forceinline__ uint32_t sptr(const void* p) {
    return (uint32_t)__cvta_generic_to_shared(p);
}
__device__ __forceinline__ void cp16(uint32_t dst, const void* src) {
    asm volatile("cp.async.cg.shared.global [%0], [%1], 16;\n" :: "r"(dst), "l"(src));
}
__device__ __forceinline__ void ldsm_x4(uint32_t* r, uint32_t addr) {
    asm volatile("ldmatrix.sync.aligned.m8n8.x4.shared.b16 {%0,%1,%2,%3}, [%4];\n"
        : "=r"(r[0]), "=r"(r[1]), "=r"(r[2]), "=r"(r[3]) : "r"(addr));
}
__device__ __forceinline__ void ldsm_x4_t(uint32_t* r, uint32_t addr) {
    asm volatile("ldmatrix.sync.aligned.m8n8.x4.trans.shared.b16 {%0,%1,%2,%3}, [%4];\n"
        : "=r"(r[0]), "=r"(r[1]), "=r"(r[2]), "=r"(r[3]) : "r"(addr));
}
__device__ __forceinline__ void mma16816h(float* c, const uint32_t* a, const uint32_t* b) {
    asm volatile(
        "mma.sync.aligned.m16n8k16.row.col.f32.f16.f16.f32 "
        "{%0,%1,%2,%3}, {%4,%5,%6,%7}, {%8,%9}, {%0,%1,%2,%3};\n"
        : "+f"(c[0]), "+f"(c[1]), "+f"(c[2]), "+f"(c[3])
        : "r"(a[0]), "r"(a[1]), "r"(a[2]), "r"(a[3]), "r"(b[0]), "r"(b[1]));
}
__device__ __forceinline__ uint32_t packh2(float x, float y) {
    __half2 h = __floats2half2_rn(x, y);
    return *(uint32_t*)&h;
}
__device__ __forceinline__ void store_pair_h(__half* oh, __half* ol,
                                             size_t idx, float a, float b) {
    float ha = __half2float(__float2half_rn(a));
    float hb = __half2float(__float2half_rn(b));
    *(uint32_t*)&oh[idx] = packh2(a, b);
    *(uint32_t*)&ol[idx] = packh2(a - ha, b - hb);
}

// ---------------- conversion kernels ----------------
__global__ __launch_bounds__(256) void cvt_h16_v4(
    const float* __restrict__ in, __half* __restrict__ out, int n8)
{
    int i = blockIdx.x * 256 + threadIdx.x;
    if (i >= n8) return;
    const float4* p = (const float4*)in + 2 * (size_t)i;
    float4 f0 = p[0], f1 = p[1];
    uint32_t h[4];
    h[0] = packh2(f0.x, f0.y); h[1] = packh2(f0.z, f0.w);
    h[2] = packh2(f1.x, f1.y); h[3] = packh2(f1.z, f1.w);
    ((uint4*)out)[i] = make_uint4(h[0], h[1], h[2], h[3]);
}

__global__ __launch_bounds__(256) void split_h16_pack_v4(
    const float* __restrict__ in,
    __half* __restrict__ hi, __half* __restrict__ lo,
    int cols8, int ostride8, int ooff8, int n8)
{
    int i = blockIdx.x * 256 + threadIdx.x;
    if (i >= n8) return;
    int r = i / cols8, c8 = i % cols8;
    const float4* p = (const float4*)in + 2 * (size_t)i;
    float4 f0 = p[0], f1 = p[1];
    float v[8] = {f0.x, f0.y, f0.z, f0.w, f1.x, f1.y, f1.z, f1.w};
    uint32_t h[4], l[4];
    #pragma unroll
    for (int k = 0; k < 4; k++) {
        float a = v[2 * k], b = v[2 * k + 1];
        float ha = __half2float(__float2half_rn(a));
        float hb = __half2float(__float2half_rn(b));
        h[k] = packh2(a, b);
        l[k] = packh2(a - ha, b - hb);
    }
    size_t o = (size_t)r * ostride8 + ooff8 + c8;
    ((uint4*)hi)[o] = make_uint4(h[0], h[1], h[2], h[3]);
    ((uint4*)lo)[o] = make_uint4(l[0], l[1], l[2], l[3]);
}

// ---------------- fp16 2-pass GEMM: 128x128 CTA, 4 warps, 64x64 warp tile ----------------
#define BM 128
#define BN 128
#define BK 32
#define ASTRIDE 40
#define BSTRIDE 136
#define A_T (BM * ASTRIDE)
#define B_T (BK * BSTRIDE)
#define STAGE_F16 (A_T + 2 * B_T)
#define GEMM_SMEM_F16 (2 * STAGE_F16 * 2)

__device__ __forceinline__ void load_tile_f16(
    __half* sm, const __half* __restrict__ A,
    const __half* __restrict__ Bh, const __half* __restrict__ Bl,
    int K, int NB, int m0, int n0, int k0, int t)
{
    #pragma unroll
    for (int c = t; c < 512; c += 128) {
        int row = c >> 2, col = (c & 3) * 8;
        size_t g = (size_t)(m0 + row) * K + k0 + col;
        cp16(sptr(sm + row * ASTRIDE + col), A + g);
    }
    #pragma unroll
    for (int c = t; c < 512; c += 128) {
        int row = c >> 4, col = (c & 15) * 8;
        size_t g = (size_t)(k0 + row) * NB + n0 + col;
        uint32_t s = (uint32_t)(row * BSTRIDE + col);
        cp16(sptr(sm + A_T + s),       Bh + g);
        cp16(sptr(sm + A_T + B_T + s), Bl + g);
    }
}

#define GEMM_MAINLOOP_F16(A, Bh, Bl, K, NB)                                         \
    float acc[4][8][4];                                                             \
    _Pragma("unroll")                                                               \
    for (int i = 0; i < 4; i++)                                                     \
        _Pragma("unroll")                                                           \
        for (int j = 0; j < 8; j++)                                                 \
            _Pragma("unroll")                                                       \
            for (int r = 0; r < 4; r++) acc[i][j][r] = 0.f;                         \
    const int g8 = lane >> 3;                                                       \
    const int l8 = lane & 7;                                                        \
    load_tile_f16(sm, A, Bh, Bl, K, NB, m0, n0, 0, t);                              \
    asm volatile("cp.async.commit_group;\n");                                       \
    const int nk = K / BK;                                                          \
    for (int kt = 0; kt < nk; kt++) {                                               \
        __half* buf = sm + (kt & 1) * STAGE_F16;                                    \
        if (kt + 1 < nk) {                                                          \
            load_tile_f16(sm + ((kt + 1) & 1) * STAGE_F16, A, Bh, Bl,               \
                          K, NB, m0, n0, (kt + 1) * BK, t);                         \
            asm volatile("cp.async.commit_group;\n");                               \
            asm volatile("cp.async.wait_group 1;\n");                               \
        } else {                                                                    \
            asm volatile("cp.async.wait_group 0;\n");                               \
        }                                                                           \
        __syncthreads();                                                            \
        _Pragma("unroll")                                                           \
        for (int ks = 0; ks < 2; ks++) {                                            \
            uint32_t ah[4][4], bh[8][2], bl[8][2];                                  \
            _Pragma("unroll")                                                       \
            for (int i = 0; i < 4; i++) {                                           \
                int row = wm * 64 + i * 16 + (g8 & 1) * 8 + l8;                     \
                int col = ks * 16 + (g8 >> 1) * 8;                                  \
                ldsm_x4(ah[i], sptr(buf + row * ASTRIDE + col));                    \
            }                                                                       \
            _Pragma("unroll")                                                       \
            for (int jj = 0; jj < 4; jj++) {                                        \
                int krow = ks * 16 + (g8 & 1) * 8 + l8;                             \
                int ncol = wn * 64 + jj * 16 + (g8 >> 1) * 8;                       \
                uint32_t r4[4];                                                     \
                ldsm_x4_t(r4, sptr(buf + A_T + krow * BSTRIDE + ncol));             \
                bh[2 * jj][0] = r4[0]; bh[2 * jj][1] = r4[1];                       \
                bh[2 * jj + 1][0] = r4[2]; bh[2 * jj + 1][1] = r4[3];               \
                ldsm_x4_t(r4, sptr(buf + A_T + B_T + krow * BSTRIDE + ncol));       \
                bl[2 * jj][0] = r4[0]; bl[2 * jj][1] = r4[1];                       \
                bl[2 * jj + 1][0] = r4[2]; bl[2 * jj + 1][1] = r4[3];               \
            }                                                                       \
            _Pragma("unroll")                                                       \
            for (int i = 0; i < 4; i++)                                             \
                _Pragma("unroll")                                                   \
                for (int j = 0; j < 8; j++) {                                       \
                    mma16816h(acc[i][j], ah[i], bh[j]);                             \
                    mma16816h(acc[i][j], ah[i], bl[j]);                             \
                }                                                                   \
        }                                                                           \
        __syncthreads();                                                            \
    }

// QKV GEMM with fused RoPE + fp16 output epilogue
__global__ __launch_bounds__(128, 2) void qkv_gemm(
    const __half* __restrict__ A,
    const __half* __restrict__ Bh, const __half* __restrict__ Bl,
    const int* __restrict__ pid,
    __half* __restrict__ q16,
    __half* __restrict__ kh, __half* __restrict__ kl,
    __half* __restrict__ vh, __half* __restrict__ vl)
{
    extern __shared__ __half sm[];
    const int t = threadIdx.x, lane = t & 31, w = t >> 5;
    const int wm = w >> 1, wn = w & 1;
    const int m0 = blockIdx.y * BM, n0 = blockIdx.x * BN;

    GEMM_MAINLOOP_F16(A, Bh, Bl, HID, NQKV)

    const int gc = n0 + wn * 64;
    const int mode = (gc < 2048) ? 0 : (gc < 2560 ? 1 : 2);   // 0=q,1=k,2=v
    const float scale = (mode == 0) ? 0.125f : 1.f;

    #pragma unroll
    for (int i = 0; i < 4; i++) {
        int r0 = m0 + wm * 64 + i * 16 + (lane >> 2);
        int r1 = r0 + 8;
        float p0 = (float)pid[r0], p1 = (float)pid[r1];
        #pragma unroll
        for (int j = 0; j < 4; j++) {
            int ch = j * 8 + (lane & 3) * 2;
            float x10 = acc[i][j][0],     x11 = acc[i][j][1];
            float x12 = acc[i][j][2],     x13 = acc[i][j][3];
            float x20 = acc[i][j + 4][0], x21 = acc[i][j + 4][1];
            float x22 = acc[i][j + 4][2], x23 = acc[i][j + 4][3];
            float y10, y11, y12, y13, y20, y21, y22, y23;
            if (mode < 2) {
                float inv0 = __powf(10000.f, -(float)ch * (1.f / 32.f));
                float inv1 = __powf(10000.f, -(float)(ch + 1) * (1.f / 32.f));
                float s00, c00, s01, c01, s10, c10, s11, c11;
                __sincosf(p0 * inv0, &s00, &c00);
                __sincosf(p0 * inv1, &s01, &c01);
                __sincosf(p1 * inv0, &s10, &c10);
                __sincosf(p1 * inv1, &s11, &c11);
                y10 = (x10 * c00 - x20 * s00) * scale; y20 = (x20 * c00 + x10 * s00) * scale;
                y11 = (x11 * c01 - x21 * s01) * scale; y21 = (x21 * c01 + x11 * s01) * scale;
                y12 = (x12 * c10 - x22 * s10) * scale; y22 = (x22 * c10 + x12 * s10) * scale;
                y13 = (x13 * c11 - x23 * s11) * scale; y23 = (x23 * c11 + x13 * s11) * scale;
            } else {
                y10 = x10; y11 = x11; y12 = x12; y13 = x13;
                y20 = x20; y21 = x21; y22 = x22; y23 = x23;
            }
            if (mode == 0) {
                size_t b0 = (size_t)r0 * HID + gc + ch;
                size_t b1 = (size_t)r1 * HID + gc + ch;
                *(uint32_t*)&q16[b0]      = packh2(y10, y11);
                *(uint32_t*)&q16[b0 + 32] = packh2(y20, y21);
                *(uint32_t*)&q16[b1]      = packh2(y12, y13);
                *(uint32_t*)&q16[b1 + 32] = packh2(y22, y23);
            } else {
                __half* oh = (mode == 1) ? kh : vh;
                __half* ol = (mode == 1) ? kl : vl;
                int base = gc - ((mode == 1) ? 2048 : 2560);
                size_t b0 = (size_t)r0 * 512 + base + ch;
                size_t b1 = (size_t)r1 * 512 + base + ch;
                store_pair_h(oh, ol, b0,      y10, y11);
                store_pair_h(oh, ol, b0 + 32, y20, y21);
                store_pair_h(oh, ol, b1,      y12, y13);
                store_pair_h(oh, ol, b1 + 32, y22, y23);
            }
        }
    }
}

// O projection: fp16 2-pass, fp32 output
__global__ __launch_bounds__(128, 2) void oproj_gemm(
    const __half* __restrict__ A,
    const __half* __restrict__ Bh, const __half* __restrict__ Bl,
    float* __restrict__ C)
{
    extern __shared__ __half sm[];
    const int t = threadIdx.x, lane = t & 31, w = t >> 5;
    const int wm = w >> 1, wn = w & 1;
    const int m0 = blockIdx.y * BM, n0 = blockIdx.x * BN;

    GEMM_MAINLOOP_F16(A, Bh, Bl, HID, HID)

    #pragma unroll
    for (int i = 0; i < 4; i++)
        #pragma unroll
        for (int j = 0; j < 8; j++) {
            int row = m0 + wm * 64 + i * 16 + (lane >> 2);
            int col = n0 + wn * 64 + j * 8 + (lane & 3) * 2;
            *(float2*)&C[(size_t)row * HID + col] =
                make_float2(acc[i][j][0], acc[i][j][1]);
            *(float2*)&C[(size_t)(row + 8) * HID + col] =
                make_float2(acc[i][j][2], acc[i][j][3]);
        }
}

// ---------------- fp16 2-pass flash attention (causal) ----------------
// 64 q-rows x 4 warps per CTA; 2 CTAs/SM. K-tiles of 64 keys.
#define Q_OFF   0
#define BUF_OFF (64 * 144)                 // 9216
#define KVBUF   (4 * 64 * 144)             // 36864
#define ATTN_SMEM (BUF_OFF + 2 * KVBUF)    // 82944

__device__ __forceinline__ void attn_load_kv(
    uint32_t bufb,
    const __half* __restrict__ kh, const __half* __restrict__ kl,
    const __half* __restrict__ vh, const __half* __restrict__ vl,
    int k0, int kvh, int t)
{
    #pragma unroll
    for (int i = 0; i < 4; i++) {
        int idx = i * 128 + t;
        int row = idx >> 3, cc = idx & 7;
        uint32_t off = (uint32_t)(row * 144 + cc * 16);
        size_t g = (size_t)(k0 + row) * 512 + kvh * HD + cc * 8;
        cp16(bufb + off,         kh + g);
        cp16(bufb + 9216 + off,  kl + g);
        cp16(bufb + 18432 + off, vh + g);
        cp16(bufb + 27648 + off, vl + g);
    }
}

__global__ __launch_bounds__(128, 2) void attn_tc(
    const __half* __restrict__ q16,
    const __half* __restrict__ kh, const __half* __restrict__ kl,
    const __half* __restrict__ vh, const __half* __restrict__ vl,
    __half* __restrict__ Aout)
{
    extern __shared__ __align__(1024) char asmem[];
    const uint32_t sb = sptr(asmem);
    const int qt  = 31 - blockIdx.x;
    const int h   = blockIdx.y;
    const int kvh = h >> 2;
    const int t = threadIdx.x, w = t >> 5, lane = t & 31;
    const int g8 = lane >> 3, l8 = lane & 7, tig = lane & 3, g = lane >> 2;
    const int q0 = qt * 64;

    // load Q tile: 64 rows x 128 B = 512 chunks; 128 threads x 4 chunks (FIXED)
    {
        int row = t >> 1, cc = (t & 1) * 4;          // row 0..63, cc 0 or 4
        uint32_t off = (uint32_t)(row * 144 + cc * 16);
        size_t gg = (size_t)(q0 + row) * HID + h * HD + cc * 8;
        cp16(sb + Q_OFF + off,      q16 + gg);
        cp16(sb + Q_OFF + off + 16, q16 + gg + 8);
        cp16(sb + Q_OFF + off + 32, q16 + gg + 16);
        cp16(sb + Q_OFF + off + 48, q16 + gg + 24);
    }
    attn_load_kv(sb + BUF_OFF, kh, kl, vh, vl, 0, kvh, t);
    asm volatile("cp.async.commit_group;\n");
    asm volatile("cp.async.wait_group 0;\n");
    __syncthreads();

    uint32_t qa[4][4];
    #pragma unroll
    for (int kc = 0; kc < 4; kc++) {
        uint32_t off = (uint32_t)((w * 16 + (g8 & 1) * 8 + l8) * 144 +
                                  (kc * 16 + (g8 >> 1) * 8) * 2);
        ldsm_x4(qa[kc], sb + Q_OFF + off);
    }

    float oacc[8][4];
    #pragma unroll
    for (int j = 0; j < 8; j++)
        #pragma unroll
        for (int r = 0; r < 4; r++) oacc[j][r] = 0.f;
    float m0 = -1e30f, m1 = -1e30f, l0 = 0.f, l1 = 0.f;

    const int row0 = q0 + w * 16 + g;
    const int row1 = row0 + 8;
    const int nkt = qt + 1;

    for (int kt = 0; kt < nkt; kt++) {
        const uint32_t buf = sb + BUF_OFF + (uint32_t)(kt & 1) * KVBUF;
        if (kt + 1 < nkt) {
            attn_load_kv(sb + BUF_OFF + (uint32_t)((kt + 1) & 1) * KVBUF,
                         kh, kl, vh, vl, (kt + 1) * 64, kvh, t);
            asm volatile("cp.async.commit_group;\n");
            asm volatile("cp.async.wait_group 1;\n");
        } else {
            asm volatile("cp.async.wait_group 0;\n");
        }
        __syncthreads();

        float sacc[8][4];
        #pragma unroll
        for (int j = 0; j < 8; j++)
            #pragma unroll
            for (int r = 0; r < 4; r++) sacc[j][r] = 0.f;

        // S = Q K^T : 2-pass (Q single, K hi+lo)
        #pragma unroll
        for (int kg = 0; kg < 4; kg++) {
            #pragma unroll
            for (int kc = 0; kc < 4; kc++) {
                uint32_t off = (uint32_t)((kg * 16 + (g8 & 1) * 8 + l8) * 144 +
                                          (kc * 16 + (g8 >> 1) * 8) * 2);
                uint32_t kbh[4], kbl[4];
                ldsm_x4(kbh, buf + off);
                ldsm_x4(kbl, buf + 9216 + off);
                uint32_t b0h[2] = {kbh[0], kbh[2]}, b1h[2] = {kbh[1], kbh[3]};
                uint32_t b0l[2] = {kbl[0], kbl[2]}, b1l[2] = {kbl[1], kbl[3]};
                mma16816h(sacc[2 * kg],     qa[kc], b0h);
                mma16816h(sacc[2 * kg],     qa[kc], b0l);
                mma16816h(sacc[2 * kg + 1], qa[kc], b1h);
                mma16816h(sacc[2 * kg + 1], qa[kc], b1l);
            }
        }

        if (kt >= qt) {
            #pragma unroll
            for (int j = 0; j < 8; j++) {
                int col = kt * 64 + j * 8 + tig * 2;
                if (col > row0)     sacc[j][0] = -1e30f;
                if (col + 1 > row0) sacc[j][1] = -1e30f;
                if (col > row1)     sacc[j][2] = -1e30f;
                if (col + 1 > row1) sacc[j][3] = -1e30f;
            }
        }

        float mx0 = -1e30f, mx1 = -1e30f;
        #pragma unroll
        for (int j = 0; j < 8; j++) {
            mx0 = fmaxf(mx0, fmaxf(sacc[j][0], sacc[j][1]));
            mx1 = fmaxf(mx1, fmaxf(sacc[j][2], sacc[j][3]));
        }
        mx0 = fmaxf(mx0, __shfl_xor_sync(0xffffffffu, mx0, 1));
        mx0 = fmaxf(mx0, __shfl_xor_sync(0xffffffffu, mx0, 2));
        mx1 = fmaxf(mx1, __shfl_xor_sync(0xffffffffu, mx1, 1));
        mx1 = fmaxf(mx1, __shfl_xor_sync(0xffffffffu, mx1, 2));

        float nm0 = fmaxf(m0, mx0), nm1 = fmaxf(m1, mx1);
        float al0 = __expf(m0 - nm0), al1 = __expf(m1 - nm1);
        m0 = nm0; m1 = nm1;

        float rs0 = 0.f, rs1 = 0.f;
        #pragma unroll
        for (int j = 0; j < 8; j++) {
            sacc[j][0] = __expf(sacc[j][0] - nm0);
            sacc[j][1] = __expf(sacc[j][1] - nm0);
            sacc[j][2] = __expf(sacc[j][2] - nm1);
            sacc[j][3] = __expf(sacc[j][3] - nm1);
            rs0 += sacc[j][0] + sacc[j][1];
            rs1 += sacc[j][2] + sacc[j][3];
        }
        rs0 += __shfl_xor_sync(0xffffffffu, rs0, 1);
        rs0 += __shfl_xor_sync(0xffffffffu, rs0, 2);
        rs1 += __shfl_xor_sync(0xffffffffu, rs1, 1);
        rs1 += __shfl_xor_sync(0xffffffffu, rs1, 2);
        l0 = l0 * al0 + rs0;
        l1 = l1 * al1 + rs1;
        #pragma unroll
        for (int j = 0; j < 8; j++) {
            oacc[j][0] *= al0; oacc[j][1] *= al0;
            oacc[j][2] *= al1; oacc[j][3] *= al1;
        }

        // P -> single fp16 A-frags
        uint32_t pa[4][4];
        #pragma unroll
        for (int kc = 0; kc < 4; kc++) {
            int j0 = 2 * kc, j1 = 2 * kc + 1;
            pa[kc][0] = packh2(sacc[j0][0], sacc[j0][1]);
            pa[kc][1] = packh2(sacc[j0][2], sacc[j0][3]);
            pa[kc][2] = packh2(sacc[j1][0], sacc[j1][1]);
            pa[kc][3] = packh2(sacc[j1][2], sacc[j1][3]);
        }

        // O += P V : 2-pass (P single, V hi+lo)
        #pragma unroll
        for (int kc = 0; kc < 4; kc++) {
            #pragma unroll
            for (int jj = 0; jj < 4; jj++) {
                uint32_t off = (uint32_t)((kc * 16 + (g8 & 1) * 8 + l8) * 144 +
                                          (jj * 16 + (g8 >> 1) * 8) * 2);
                uint32_t vbh[4], vbl[4];
                ldsm_x4_t(vbh, buf + 18432 + off);
                ldsm_x4_t(vbl, buf + 27648 + off);
                uint32_t b0h[2] = {vbh[0], vbh[1]}, b1h[2] = {vbh[2], vbh[3]};
                uint32_t b0l[2] = {vbl[0], vbl[1]}, b1l[2] = {vbl[2], vbl[3]};
                mma16816h(oacc[2 * jj],     pa[kc], b0h);
                mma16816h(oacc[2 * jj],     pa[kc], b0l);
                mma16816h(oacc[2 * jj + 1], pa[kc], b1h);
                mma16816h(oacc[2 * jj + 1], pa[kc], b1l);
            }
        }
        __syncthreads();
    }

    float i0 = 1.0f / l0, i1 = 1.0f / l1;
    #pragma unroll
    for (int j = 0; j < 8; j++) {
        int col = h * HD + j * 8 + tig * 2;
        float o0 = oacc[j][0] * i0, o1 = oacc[j][1] * i0;
        float o2 = oacc[j][2] * i1, o3 = oacc[j][3] * i1;
        *(uint32_t*)&Aout[(size_t)row0 * HID + col] = packh2(o0, o1);
        *(uint32_t*)&Aout[(size_t)row1 * HID + col] = packh2(o2, o3);
    }
}

// ---------------- launch ----------------
extern "C" void kernel_launch(void* const* d_in, const int* in_sizes, int n_in,
                              void* d_out, int out_size)
{
    const float* X   = (const float*)d_in[0];
    const int*   pid = (const int*)d_in[2];
    const float* Wq  = (const float*)d_in[3];
    const float* Wk  = (const float*)d_in[4];
    const float* Wv  = (const float*)d_in[5];
    const float* Wo  = (const float*)d_in[6];
    float* out = (float*)d_out;

    __half *Xh, *Wqkvh, *Wqkvl, *Woh, *Wol, *A16;
    __half *q16, *kh, *kl, *vh, *vl;
    cudaGetSymbolAddress((void**)&Xh,    g_Xh16);
    cudaGetSymbolAddress((void**)&Wqkvh, g_Wqkvh16);
    cudaGetSymbolAddress((void**)&Wqkvl, g_Wqkvl16);
    cudaGetSymbolAddress((void**)&Woh,   g_Woh16);
    cudaGetSymbolAddress((void**)&Wol,   g_Wol16);
    cudaGetSymbolAddress((void**)&A16,   g_A16);
    cudaGetSymbolAddress((void**)&q16,   g_q16);
    cudaGetSymbolAddress((void**)&kh,    g_kh16);  cudaGetSymbolAddress((void**)&kl, g_kl16);
    cudaGetSymbolAddress((void**)&vh,    g_vh16);  cudaGetSymbolAddress((void**)&vl, g_vl16);

    cudaFuncSetAttribute(qkv_gemm,  cudaFuncAttributeMaxDynamicSharedMemorySize, GEMM_SMEM_F16);
    cudaFuncSetAttribute(oproj_gemm,cudaFuncAttributeMaxDynamicSharedMemorySize, GEMM_SMEM_F16);
    cudaFuncSetAttribute(attn_tc,   cudaFuncAttributeMaxDynamicSharedMemorySize, ATTN_SMEM);

    // conversions
    cvt_h16_v4<<<(S_LEN * HID / 8 + 255) / 256, 256>>>(X, Xh, S_LEN * HID / 8);
    split_h16_pack_v4<<<(HID * 2048 / 8 + 255) / 256, 256>>>(
        Wq, Wqkvh, Wqkvl, 2048 / 8, NQKV / 8, 0, HID * 2048 / 8);
    split_h16_pack_v4<<<(HID * 512 / 8 + 255) / 256, 256>>>(
        Wk, Wqkvh, Wqkvl, 512 / 8, NQKV / 8, 2048 / 8, HID * 512 / 8);
    split_h16_pack_v4<<<(HID * 512 / 8 + 255) / 256, 256>>>(
        Wv, Wqkvh, Wqkvl, 512 / 8, NQKV / 8, 2560 / 8, HID * 512 / 8);
    split_h16_pack_v4<<<(HID * HID / 8 + 255) / 256, 256>>>(
        Wo, Woh, Wol, HID / 8, HID / 8, 0, HID * HID / 8);

    // fused QKV projection + RoPE (fp16 2-pass)
    qkv_gemm<<<dim3(NQKV / BN, S_LEN / BM), 128, GEMM_SMEM_F16>>>(
        Xh, Wqkvh, Wqkvl, pid, q16, kh, kl, vh, vl);

    // attention (fp16 2-pass)
    attn_tc<<<dim3(32, NH), 128, ATTN_SMEM>>>(q16, kh, kl, vh, vl, A16);

    // O projection (fp16 2-pass)
    oproj_gemm<<<dim3(HID / BN, S_LEN / BM), 128, GEMM_SMEM_F16>>>(
        A16, Woh, Wol, out);
}

// round 13
// speedup vs baseline: 3.9142x; 1.7341x over previous
#include <cuda_runtime.h>
#include <cuda_fp16.h>
#include <math.h>
#include <stdint.h>

#define S_LEN 2048
#define HID   2048
#define NH    32
#define NKV   8
#define HD    64
#define KVW   1024
#define NQKV  3072

// ---------------- scratch (all single fp16) ----------------
__device__ __half g_Xh16 [S_LEN * HID];
__device__ __half g_Wqkv16[HID * NQKV];
__device__ __half g_Wo16[HID * HID];
__device__ __half g_A16 [S_LEN * HID];

__device__ __half g_q16[S_LEN * HID];
__device__ __half g_k16[S_LEN * 512];
__device__ __half g_v16[S_LEN * 512];

// ---------------- helpers ----------------
__device__ __forceinline__ uint32_t sptr(const void* p) {
    return (uint32_t)__cvta_generic_to_shared(p);
}
__device__ __forceinline__ void cp16(uint32_t dst, const void* src) {
    asm volatile("cp.async.cg.shared.global [%0], [%1], 16;\n" :: "r"(dst), "l"(src));
}
__device__ __forceinline__ void ldsm_x4(uint32_t* r, uint32_t addr) {
    asm volatile("ldmatrix.sync.aligned.m8n8.x4.shared.b16 {%0,%1,%2,%3}, [%4];\n"
        : "=r"(r[0]), "=r"(r[1]), "=r"(r[2]), "=r"(r[3]) : "r"(addr));
}
__device__ __forceinline__ void ldsm_x4_t(uint32_t* r, uint32_t addr) {
    asm volatile("ldmatrix.sync.aligned.m8n8.x4.trans.shared.b16 {%0,%1,%2,%3}, [%4];\n"
        : "=r"(r[0]), "=r"(r[1]), "=r"(r[2]), "=r"(r[3]) : "r"(addr));
}
__device__ __forceinline__ void mma16816h(float* c, const uint32_t* a, const uint32_t* b) {
    asm volatile(
        "mma.sync.aligned.m16n8k16.row.col.f32.f16.f16.f32 "
        "{%0,%1,%2,%3}, {%4,%5,%6,%7}, {%8,%9}, {%0,%1,%2,%3};\n"
        : "+f"(c[0]), "+f"(c[1]), "+f"(c[2]), "+f"(c[3])
        : "r"(a[0]), "r"(a[1]), "r"(a[2]), "r"(a[3]), "r"(b[0]), "r"(b[1]));
}
__device__ __forceinline__ uint32_t packh2(float x, float y) {
    __half2 h = __floats2half2_rn(x, y);
    return *(uint32_t*)&h;
}

// ---------------- conversion kernels ----------------
__global__ __launch_bounds__(256) void cvt_h16_v4(
    const float* __restrict__ in, __half* __restrict__ out, int n8)
{
    int i = blockIdx.x * 256 + threadIdx.x;
    if (i >= n8) return;
    const float4* p = (const float4*)in + 2 * (size_t)i;
    float4 f0 = p[0], f1 = p[1];
    uint32_t h[4];
    h[0] = packh2(f0.x, f0.y); h[1] = packh2(f0.z, f0.w);
    h[2] = packh2(f1.x, f1.y); h[3] = packh2(f1.z, f1.w);
    ((uint4*)out)[i] = make_uint4(h[0], h[1], h[2], h[3]);
}

__global__ __launch_bounds__(256) void cvt_h16_pack_v4(
    const float* __restrict__ in, __half* __restrict__ out,
    int cols8, int ostride8, int ooff8, int n8)
{
    int i = blockIdx.x * 256 + threadIdx.x;
    if (i >= n8) return;
    int r = i / cols8, c8 = i % cols8;
    const float4* p = (const float4*)in + 2 * (size_t)i;
    float4 f0 = p[0], f1 = p[1];
    uint32_t h[4];
    h[0] = packh2(f0.x, f0.y); h[1] = packh2(f0.z, f0.w);
    h[2] = packh2(f1.x, f1.y); h[3] = packh2(f1.z, f1.w);
    ((uint4*)out)[(size_t)r * ostride8 + ooff8 + c8] = make_uint4(h[0], h[1], h[2], h[3]);
}

// ---------------- fp16 single-pass GEMM: 128x128 CTA, 4 warps, 64x64 warp tile ----------------
#define BM 128
#define BN 128
#define BK 32
#define ASTRIDE 40
#define BSTRIDE 136
#define A_T (BM * ASTRIDE)
#define B_T (BK * BSTRIDE)
#define STAGE_F16 (A_T + B_T)              // 9472 elems
#define GEMM_SMEM_F16 (2 * STAGE_F16 * 2)  // 37888 bytes

__device__ __forceinline__ void load_tile_f16(
    __half* sm, const __half* __restrict__ A, const __half* __restrict__ B,
    int K, int NB, int m0, int n0, int k0, int t)
{
    #pragma unroll
    for (int c = t; c < 512; c += 128) {
        int row = c >> 2, col = (c & 3) * 8;
        size_t g = (size_t)(m0 + row) * K + k0 + col;
        cp16(sptr(sm + row * ASTRIDE + col), A + g);
    }
    #pragma unroll
    for (int c = t; c < 512; c += 128) {
        int row = c >> 4, col = (c & 15) * 8;
        size_t g = (size_t)(k0 + row) * NB + n0 + col;
        cp16(sptr(sm + A_T + row * BSTRIDE + col), B + g);
    }
}

#define GEMM_MAINLOOP_F16(A, B, K, NB)                                              \
    float acc[4][8][4];                                                             \
    _Pragma("unroll")                                                               \
    for (int i = 0; i < 4; i++)                                                     \
        _Pragma("unroll")                                                           \
        for (int j = 0; j < 8; j++)                                                 \
            _Pragma("unroll")                                                       \
            for (int r = 0; r < 4; r++) acc[i][j][r] = 0.f;                         \
    const int g8 = lane >> 3;                                                       \
    const int l8 = lane & 7;                                                        \
    load_tile_f16(sm, A, B, K, NB, m0, n0, 0, t);                                   \
    asm volatile("cp.async.commit_group;\n");                                       \
    const int nk = K / BK;                                                          \
    for (int kt = 0; kt < nk; kt++) {                                               \
        __half* buf = sm + (kt & 1) * STAGE_F16;                                    \
        if (kt + 1 < nk) {                                                          \
            load_tile_f16(sm + ((kt + 1) & 1) * STAGE_F16, A, B,                    \
                          K, NB, m0, n0, (kt + 1) * BK, t);                         \
            asm volatile("cp.async.commit_group;\n");                               \
            asm volatile("cp.async.wait_group 1;\n");                               \
        } else {                                                                    \
            asm volatile("cp.async.wait_group 0;\n");                               \
        }                                                                           \
        __syncthreads();                                                            \
        _Pragma("unroll")                                                           \
        for (int ks = 0; ks < 2; ks++) {                                            \
            uint32_t ah[4][4], bh[8][2];                                            \
            _Pragma("unroll")                                                       \
            for (int i = 0; i < 4; i++) {                                           \
                int row = wm * 64 + i * 16 + (g8 & 1) * 8 + l8;                     \
                int col = ks * 16 + (g8 >> 1) * 8;                                  \
                ldsm_x4(ah[i], sptr(buf + row * ASTRIDE + col));                    \
            }                                                                       \
            _Pragma("unroll")                                                       \
            for (int jj = 0; jj < 4; jj++) {                                        \
                int krow = ks * 16 + (g8 & 1) * 8 + l8;                             \
                int ncol = wn * 64 + jj * 16 + (g8 >> 1) * 8;                       \
                uint32_t r4[4];                                                     \
                ldsm_x4_t(r4, sptr(buf + A_T + krow * BSTRIDE + ncol));             \
                bh[2 * jj][0] = r4[0]; bh[2 * jj][1] = r4[1];                       \
                bh[2 * jj + 1][0] = r4[2]; bh[2 * jj + 1][1] = r4[3];               \
            }                                                                       \
            _Pragma("unroll")                                                       \
            for (int i = 0; i < 4; i++)                                             \
                _Pragma("unroll")                                                   \
                for (int j = 0; j < 8; j++)                                         \
                    mma16816h(acc[i][j], ah[i], bh[j]);                             \
        }                                                                           \
        __syncthreads();                                                            \
    }

// QKV GEMM with fused RoPE + fp16 output epilogue
__global__ __launch_bounds__(128, 2) void qkv_gemm(
    const __half* __restrict__ A, const __half* __restrict__ B,
    const int* __restrict__ pid,
    __half* __restrict__ q16, __half* __restrict__ k16, __half* __restrict__ v16)
{
    extern __shared__ __half sm[];
    const int t = threadIdx.x, lane = t & 31, w = t >> 5;
    const int wm = w >> 1, wn = w & 1;
    const int m0 = blockIdx.y * BM, n0 = blockIdx.x * BN;

    GEMM_MAINLOOP_F16(A, B, HID, NQKV)

    const int gc = n0 + wn * 64;
    const int mode = (gc < 2048) ? 0 : (gc < 2560 ? 1 : 2);   // 0=q,1=k,2=v
    const float scale = (mode == 0) ? 0.125f : 1.f;
    __half* outp = (mode == 0) ? q16 : (mode == 1 ? k16 : v16);
    const int ldo  = (mode == 0) ? HID : 512;
    const int base = (mode == 0) ? gc : gc - ((mode == 1) ? 2048 : 2560);

    #pragma unroll
    for (int i = 0; i < 4; i++) {
        int r0 = m0 + wm * 64 + i * 16 + (lane >> 2);
        int r1 = r0 + 8;
        float p0 = (float)pid[r0], p1 = (float)pid[r1];
        #pragma unroll
        for (int j = 0; j < 4; j++) {
            int ch = j * 8 + (lane & 3) * 2;
            float x10 = acc[i][j][0],     x11 = acc[i][j][1];
            float x12 = acc[i][j][2],     x13 = acc[i][j][3];
            float x20 = acc[i][j + 4][0], x21 = acc[i][j + 4][1];
            float x22 = acc[i][j + 4][2], x23 = acc[i][j + 4][3];
            float y10, y11, y12, y13, y20, y21, y22, y23;
            if (mode < 2) {
                float inv0 = __powf(10000.f, -(float)ch * (1.f / 32.f));
                float inv1 = __powf(10000.f, -(float)(ch + 1) * (1.f / 32.f));
                float s00, c00, s01, c01, s10, c10, s11, c11;
                __sincosf(p0 * inv0, &s00, &c00);
                __sincosf(p0 * inv1, &s01, &c01);
                __sincosf(p1 * inv0, &s10, &c10);
                __sincosf(p1 * inv1, &s11, &c11);
                y10 = (x10 * c00 - x20 * s00) * scale; y20 = (x20 * c00 + x10 * s00) * scale;
                y11 = (x11 * c01 - x21 * s01) * scale; y21 = (x21 * c01 + x11 * s01) * scale;
                y12 = (x12 * c10 - x22 * s10) * scale; y22 = (x22 * c10 + x12 * s10) * scale;
                y13 = (x13 * c11 - x23 * s11) * scale; y23 = (x23 * c11 + x13 * s11) * scale;
            } else {
                y10 = x10; y11 = x11; y12 = x12; y13 = x13;
                y20 = x20; y21 = x21; y22 = x22; y23 = x23;
            }
            size_t b0 = (size_t)r0 * ldo + base + ch;
            size_t b1 = (size_t)r1 * ldo + base + ch;
            *(uint32_t*)&outp[b0]      = packh2(y10, y11);
            *(uint32_t*)&outp[b0 + 32] = packh2(y20, y21);
            *(uint32_t*)&outp[b1]      = packh2(y12, y13);
            *(uint32_t*)&outp[b1 + 32] = packh2(y22, y23);
        }
    }
}

// O projection: fp16 single-pass, fp32 output
__global__ __launch_bounds__(128, 2) void oproj_gemm(
    const __half* __restrict__ A, const __half* __restrict__ B,
    float* __restrict__ C)
{
    extern __shared__ __half sm[];
    const int t = threadIdx.x, lane = t & 31, w = t >> 5;
    const int wm = w >> 1, wn = w & 1;
    const int m0 = blockIdx.y * BM, n0 = blockIdx.x * BN;

    GEMM_MAINLOOP_F16(A, B, HID, HID)

    #pragma unroll
    for (int i = 0; i < 4; i++)
        #pragma unroll
        for (int j = 0; j < 8; j++) {
            int row = m0 + wm * 64 + i * 16 + (lane >> 2);
            int col = n0 + wn * 64 + j * 8 + (lane & 3) * 2;
            *(float2*)&C[(size_t)row * HID + col] =
                make_float2(acc[i][j][0], acc[i][j][1]);
            *(float2*)&C[(size_t)(row + 8) * HID + col] =
                make_float2(acc[i][j][2], acc[i][j][3]);
        }
}

// ---------------- fp16 single-pass flash attention (causal) ----------------
// 64 q-rows x 4 warps per CTA. K-tiles of 64 keys, K/V single fp16.
#define Q_OFF   0
#define BUF_OFF (64 * 144)                 // 9216
#define KVBUF   (2 * 64 * 144)             // 18432 (K + V)
#define ATTN_SMEM (BUF_OFF + 2 * KVBUF)    // 46080

__device__ __forceinline__ void attn_load_kv(
    uint32_t bufb,
    const __half* __restrict__ k16, const __half* __restrict__ v16,
    int k0, int kvh, int t)
{
    #pragma unroll
    for (int i = 0; i < 4; i++) {
        int idx = i * 128 + t;
        int row = idx >> 3, cc = idx & 7;
        uint32_t off = (uint32_t)(row * 144 + cc * 16);
        size_t g = (size_t)(k0 + row) * 512 + kvh * HD + cc * 8;
        cp16(bufb + off,        k16 + g);
        cp16(bufb + 9216 + off, v16 + g);
    }
}

__global__ __launch_bounds__(128, 2) void attn_tc(
    const __half* __restrict__ q16,
    const __half* __restrict__ k16, const __half* __restrict__ v16,
    __half* __restrict__ Aout)
{
    extern __shared__ __align__(1024) char asmem[];
    const uint32_t sb = sptr(asmem);
    const int qt  = 31 - blockIdx.x;
    const int h   = blockIdx.y;
    const int kvh = h >> 2;
    const int t = threadIdx.x, w = t >> 5, lane = t & 31;
    const int g8 = lane >> 3, l8 = lane & 7, tig = lane & 3, g = lane >> 2;
    const int q0 = qt * 64;

    // load Q tile: 64 rows x 128 B; 128 threads x 4 chunks
    {
        int row = t >> 1, cc = (t & 1) * 4;
        uint32_t off = (uint32_t)(row * 144 + cc * 16);
        size_t gg = (size_t)(q0 + row) * HID + h * HD + cc * 8;
        cp16(sb + Q_OFF + off,      q16 + gg);
        cp16(sb + Q_OFF + off + 16, q16 + gg + 8);
        cp16(sb + Q_OFF + off + 32, q16 + gg + 16);
        cp16(sb + Q_OFF + off + 48, q16 + gg + 24);
    }
    attn_load_kv(sb + BUF_OFF, k16, v16, 0, kvh, t);
    asm volatile("cp.async.commit_group;\n");
    asm volatile("cp.async.wait_group 0;\n");
    __syncthreads();

    uint32_t qa[4][4];
    #pragma unroll
    for (int kc = 0; kc < 4; kc++) {
        uint32_t off = (uint32_t)((w * 16 + (g8 & 1) * 8 + l8) * 144 +
                                  (kc * 16 + (g8 >> 1) * 8) * 2);
        ldsm_x4(qa[kc], sb + Q_OFF + off);
    }

    float oacc[8][4];
    #pragma unroll
    for (int j = 0; j < 8; j++)
        #pragma unroll
        for (int r = 0; r < 4; r++) oacc[j][r] = 0.f;
    float m0 = -1e30f, m1 = -1e30f, l0 = 0.f, l1 = 0.f;

    const int row0 = q0 + w * 16 + g;
    const int row1 = row0 + 8;
    const int nkt = qt + 1;

    for (int kt = 0; kt < nkt; kt++) {
        const uint32_t buf = sb + BUF_OFF + (uint32_t)(kt & 1) * KVBUF;
        if (kt + 1 < nkt) {
            attn_load_kv(sb + BUF_OFF + (uint32_t)((kt + 1) & 1) * KVBUF,
                         k16, v16, (kt + 1) * 64, kvh, t);
            asm volatile("cp.async.commit_group;\n");
            asm volatile("cp.async.wait_group 1;\n");
        } else {
            asm volatile("cp.async.wait_group 0;\n");
        }
        __syncthreads();

        float sacc[8][4];
        #pragma unroll
        for (int j = 0; j < 8; j++)
            #pragma unroll
            for (int r = 0; r < 4; r++) sacc[j][r] = 0.f;

        // S = Q K^T (single pass)
        #pragma unroll
        for (int kg = 0; kg < 4; kg++) {
            #pragma unroll
            for (int kc = 0; kc < 4; kc++) {
                uint32_t off = (uint32_t)((kg * 16 + (g8 & 1) * 8 + l8) * 144 +
                                          (kc * 16 + (g8 >> 1) * 8) * 2);
                uint32_t kb[4];
                ldsm_x4(kb, buf + off);
                uint32_t b0[2] = {kb[0], kb[2]}, b1[2] = {kb[1], kb[3]};
                mma16816h(sacc[2 * kg],     qa[kc], b0);
                mma16816h(sacc[2 * kg + 1], qa[kc], b1);
            }
        }

        if (kt >= qt) {
            #pragma unroll
            for (int j = 0; j < 8; j++) {
                int col = kt * 64 + j * 8 + tig * 2;
                if (col > row0)     sacc[j][0] = -1e30f;
                if (col + 1 > row0) sacc[j][1] = -1e30f;
                if (col > row1)     sacc[j][2] = -1e30f;
                if (col + 1 > row1) sacc[j][3] = -1e30f;
            }
        }

        float mx0 = -1e30f, mx1 = -1e30f;
        #pragma unroll
        for (int j = 0; j < 8; j++) {
            mx0 = fmaxf(mx0, fmaxf(sacc[j][0], sacc[j][1]));
            mx1 = fmaxf(mx1, fmaxf(sacc[j][2], sacc[j][3]));
        }
        mx0 = fmaxf(mx0, __shfl_xor_sync(0xffffffffu, mx0, 1));
        mx0 = fmaxf(mx0, __shfl_xor_sync(0xffffffffu, mx0, 2));
        mx1 = fmaxf(mx1, __shfl_xor_sync(0xffffffffu, mx1, 1));
        mx1 = fmaxf(mx1, __shfl_xor_sync(0xffffffffu, mx1, 2));

        float nm0 = fmaxf(m0, mx0), nm1 = fmaxf(m1, mx1);
        float al0 = __expf(m0 - nm0), al1 = __expf(m1 - nm1);
        m0 = nm0; m1 = nm1;

        float rs0 = 0.f, rs1 = 0.f;
        #pragma unroll
        for (int j = 0; j < 8; j++) {
            sacc[j][0] = __expf(sacc[j][0] - nm0);
            sacc[j][1] = __expf(sacc[j][1] - nm0);
            sacc[j][2] = __expf(sacc[j][2] - nm1);
            sacc[j][3] = __expf(sacc[j][3] - nm1);
            rs0 += sacc[j][0] + sacc[j][1];
            rs1 += sacc[j][2] + sacc[j][3];
        }
        rs0 += __shfl_xor_sync(0xffffffffu, rs0, 1);
        rs0 += __shfl_xor_sync(0xffffffffu, rs0, 2);
        rs1 += __shfl_xor_sync(0xffffffffu, rs1, 1);
        rs1 += __shfl_xor_sync(0xffffffffu, rs1, 2);
        l0 = l0 * al0 + rs0;
        l1 = l1 * al1 + rs1;
        #pragma unroll
        for (int j = 0; j < 8; j++) {
            oacc[j][0] *= al0; oacc[j][1] *= al0;
            oacc[j][2] *= al1; oacc[j][3] *= al1;
        }

        // P -> fp16 A-frags
        uint32_t pa[4][4];
        #pragma unroll
        for (int kc = 0; kc < 4; kc++) {
            int j0 = 2 * kc, j1 = 2 * kc + 1;
            pa[kc][0] = packh2(sacc[j0][0], sacc[j0][1]);
            pa[kc][1] = packh2(sacc[j0][2], sacc[j0][3]);
            pa[kc][2] = packh2(sacc[j1][0], sacc[j1][1]);
            pa[kc][3] = packh2(sacc[j1][2], sacc[j1][3]);
        }

        // O += P V (single pass)
        #pragma unroll
        for (int kc = 0; kc < 4; kc++) {
            #pragma unroll
            for (int jj = 0; jj < 4; jj++) {
                uint32_t off = (uint32_t)((kc * 16 + (g8 & 1) * 8 + l8) * 144 +
                                          (jj * 16 + (g8 >> 1) * 8) * 2);
                uint32_t vb[4];
                ldsm_x4_t(vb, buf + 9216 + off);
                uint32_t b0[2] = {vb[0], vb[1]}, b1[2] = {vb[2], vb[3]};
                mma16816h(oacc[2 * jj],     pa[kc], b0);
                mma16816h(oacc[2 * jj + 1], pa[kc], b1);
            }
        }
        __syncthreads();
    }

    float i0 = 1.0f / l0, i1 = 1.0f / l1;
    #pragma unroll
    for (int j = 0; j < 8; j++) {
        int col = h * HD + j * 8 + tig * 2;
        float o0 = oacc[j][0] * i0, o1 = oacc[j][1] * i0;
        float o2 = oacc[j][2] * i1, o3 = oacc[j][3] * i1;
        *(uint32_t*)&Aout[(size_t)row0 * HID + col] = packh2(o0, o1);
        *(uint32_t*)&Aout[(size_t)row1 * HID + col] = packh2(o2, o3);
    }
}

// ---------------- launch ----------------
extern "C" void kernel_launch(void* const* d_in, const int* in_sizes, int n_in,
                              void* d_out, int out_size)
{
    const float* X   = (const float*)d_in[0];
    const int*   pid = (const int*)d_in[2];
    const float* Wq  = (const float*)d_in[3];
    const float* Wk  = (const float*)d_in[4];
    const float* Wv  = (const float*)d_in[5];
    const float* Wo  = (const float*)d_in[6];
    float* out = (float*)d_out;

    __half *Xh, *Wqkv, *Wo16, *A16, *q16, *k16, *v16;
    cudaGetSymbolAddress((void**)&Xh,   g_Xh16);
    cudaGetSymbolAddress((void**)&Wqkv, g_Wqkv16);
    cudaGetSymbolAddress((void**)&Wo16, g_Wo16);
    cudaGetSymbolAddress((void**)&A16,  g_A16);
    cudaGetSymbolAddress((void**)&q16,  g_q16);
    cudaGetSymbolAddress((void**)&k16,  g_k16);
    cudaGetSymbolAddress((void**)&v16,  g_v16);

    cudaFuncSetAttribute(qkv_gemm,  cudaFuncAttributeMaxDynamicSharedMemorySize, GEMM_SMEM_F16);
    cudaFuncSetAttribute(oproj_gemm,cudaFuncAttributeMaxDynamicSharedMemorySize, GEMM_SMEM_F16);
    cudaFuncSetAttribute(attn_tc,   cudaFuncAttributeMaxDynamicSharedMemorySize, ATTN_SMEM);

    // conversions
    cvt_h16_v4<<<(S_LEN * HID / 8 + 255) / 256, 256>>>(X, Xh, S_LEN * HID / 8);
    cvt_h16_pack_v4<<<(HID * 2048 / 8 + 255) / 256, 256>>>(
        Wq, Wqkv, 2048 / 8, NQKV / 8, 0, HID * 2048 / 8);
    cvt_h16_pack_v4<<<(HID * 512 / 8 + 255) / 256, 256>>>(
        Wk, Wqkv, 512 / 8, NQKV / 8, 2048 / 8, HID * 512 / 8);
    cvt_h16_pack_v4<<<(HID * 512 / 8 + 255) / 256, 256>>>(
        Wv, Wqkv, 512 / 8, NQKV / 8, 2560 / 8, HID * 512 / 8);
    cvt_h16_v4<<<(HID * HID / 8 + 255) / 256, 256>>>(Wo, Wo16, HID * HID / 8);

    // fused QKV projection + RoPE (fp16 single-pass)
    qkv_gemm<<<dim3(NQKV / BN, S_LEN / BM), 128, GEMM_SMEM_F16>>>(
        Xh, Wqkv, pid, q16, k16, v16);

    // attention (fp16 single-pass)
    attn_tc<<<dim3(32, NH), 128, ATTN_SMEM>>>(q16, k16, v16, A16);

    // O projection (fp16 single-pass)
    oproj_gemm<<<dim3(HID / BN, S_LEN / BM), 128, GEMM_SMEM_F16>>>(
        A16, Wo16, out);
}

// round 14
// speedup vs baseline: 4.0929x; 1.0457x over previous
#include <cuda_runtime.h>
#include <cuda_fp16.h>
#include <math.h>
#include <stdint.h>

#define S_LEN 2048
#define HID   2048
#define NH    32
#define NKV   8
#define HD    64
#define KVW   1024
#define NQKV  3072

// ---------------- scratch (all single fp16) ----------------
__device__ __half g_Xh16 [S_LEN * HID];
__device__ __half g_Wqkv16[HID * NQKV];
__device__ __half g_Wo16[HID * HID];
__device__ __half g_A16 [S_LEN * HID];

__device__ __half g_q16[S_LEN * HID];
__device__ __half g_k16[S_LEN * 512];
__device__ __half g_v16[S_LEN * 512];

// ---------------- helpers ----------------
__device__ __forceinline__ uint32_t sptr(const void* p) {
    return (uint32_t)__cvta_generic_to_shared(p);
}
__device__ __forceinline__ void cp16(uint32_t dst, const void* src) {
    asm volatile("cp.async.cg.shared.global [%0], [%1], 16;\n" :: "r"(dst), "l"(src));
}
__device__ __forceinline__ void ldsm_x4(uint32_t* r, uint32_t addr) {
    asm volatile("ldmatrix.sync.aligned.m8n8.x4.shared.b16 {%0,%1,%2,%3}, [%4];\n"
        : "=r"(r[0]), "=r"(r[1]), "=r"(r[2]), "=r"(r[3]) : "r"(addr));
}
__device__ __forceinline__ void ldsm_x4_t(uint32_t* r, uint32_t addr) {
    asm volatile("ldmatrix.sync.aligned.m8n8.x4.trans.shared.b16 {%0,%1,%2,%3}, [%4];\n"
        : "=r"(r[0]), "=r"(r[1]), "=r"(r[2]), "=r"(r[3]) : "r"(addr));
}
__device__ __forceinline__ void mma16816h(float* c, const uint32_t* a, const uint32_t* b) {
    asm volatile(
        "mma.sync.aligned.m16n8k16.row.col.f32.f16.f16.f32 "
        "{%0,%1,%2,%3}, {%4,%5,%6,%7}, {%8,%9}, {%0,%1,%2,%3};\n"
        : "+f"(c[0]), "+f"(c[1]), "+f"(c[2]), "+f"(c[3])
        : "r"(a[0]), "r"(a[1]), "r"(a[2]), "r"(a[3]), "r"(b[0]), "r"(b[1]));
}
__device__ __forceinline__ uint32_t packh2(float x, float y) {
    __half2 h = __floats2half2_rn(x, y);
    return *(uint32_t*)&h;
}

// ---------------- conversion kernels (merged) ----------------
// X -> g_Xh16 and Wo -> g_Wo16 in one launch (both straight copies)
__global__ __launch_bounds__(256) void cvt_two_v4(
    const float* __restrict__ X, __half* __restrict__ Xo,
    const float* __restrict__ W, __half* __restrict__ Wo, int n8each)
{
    int i = blockIdx.x * 256 + threadIdx.x;
    const float* src; __half* dst; int idx;
    if (i < n8each) { src = X; dst = Xo; idx = i; }
    else            { src = W; dst = Wo; idx = i - n8each; if (idx >= n8each) return; }
    const float4* p = (const float4*)src + 2 * (size_t)idx;
    float4 f0 = p[0], f1 = p[1];
    uint32_t h[4];
    h[0] = packh2(f0.x, f0.y); h[1] = packh2(f0.z, f0.w);
    h[2] = packh2(f1.x, f1.y); h[3] = packh2(f1.z, f1.w);
    ((uint4*)dst)[idx] = make_uint4(h[0], h[1], h[2], h[3]);
}

// Wq|Wk|Wv -> packed g_Wqkv16 [HID][NQKV] in one launch
__global__ __launch_bounds__(256) void cvt_wqkv_v4(
    const float* __restrict__ Wq, const float* __restrict__ Wk,
    const float* __restrict__ Wv, __half* __restrict__ out, int n8)
{
    int i = blockIdx.x * 256 + threadIdx.x;
    if (i >= n8) return;
    int r = i / (NQKV / 8), c8 = i % (NQKV / 8);
    int col = c8 * 8;
    const float* src;
    if (col < 2048)      src = Wq + (size_t)r * 2048 + col;
    else if (col < 2560) src = Wk + (size_t)r * 512 + (col - 2048);
    else                 src = Wv + (size_t)r * 512 + (col - 2560);
    float4 f0 = ((const float4*)src)[0], f1 = ((const float4*)src)[1];
    uint32_t h[4];
    h[0] = packh2(f0.x, f0.y); h[1] = packh2(f0.z, f0.w);
    h[2] = packh2(f1.x, f1.y); h[3] = packh2(f1.z, f1.w);
    ((uint4*)out)[i] = make_uint4(h[0], h[1], h[2], h[3]);
}

// ---------------- QKV GEMM: 128x192 CTA, 6 warps (2x3), 64x64 warp tile ----------------
// Grid 16x16 = 256 CTAs -> single wave at 2 CTAs/SM.
#define QBM 128
#define QBN 192
#define QBK 32
#define QASTR 40
#define QBSTR 200
#define QA_T (QBM * QASTR)                  // 5120 elems
#define QB_T (QBK * QBSTR)                  // 6400 elems
#define QSTAGE (QA_T + QB_T)                // 11520 elems
#define QKV_SMEM (2 * QSTAGE * 2)           // 46080 bytes

__device__ __forceinline__ void qload_tile(
    __half* sm, const __half* __restrict__ A, const __half* __restrict__ B,
    int m0, int n0, int k0, int t)
{
    // A: 128 rows x 32 cols = 512 chunks (192 threads, uneven)
    for (int c = t; c < 512; c += 192) {
        int row = c >> 2, col = (c & 3) * 8;
        cp16(sptr(sm + row * QASTR + col),
             A + (size_t)(m0 + row) * HID + k0 + col);
    }
    // B: 32 rows x 192 cols = 768 chunks (4 per thread)
    for (int c = t; c < 768; c += 192) {
        int row = c / 24, col = (c % 24) * 8;
        cp16(sptr(sm + QA_T + row * QBSTR + col),
             B + (size_t)(k0 + row) * NQKV + n0 + col);
    }
}

__global__ __launch_bounds__(192, 2) void qkv_gemm(
    const __half* __restrict__ A, const __half* __restrict__ B,
    const int* __restrict__ pid,
    __half* __restrict__ q16, __half* __restrict__ k16, __half* __restrict__ v16)
{
    extern __shared__ __half sm[];
    const int t = threadIdx.x, lane = t & 31, w = t >> 5;
    const int wm = w / 3, wn = w % 3;      // 2 x 3 warps, 64x64 tiles
    const int m0 = blockIdx.y * QBM, n0 = blockIdx.x * QBN;
    const int g8 = lane >> 3, l8 = lane & 7;

    float acc[4][8][4];
    #pragma unroll
    for (int i = 0; i < 4; i++)
        #pragma unroll
        for (int j = 0; j < 8; j++)
            #pragma unroll
            for (int r = 0; r < 4; r++) acc[i][j][r] = 0.f;

    qload_tile(sm, A, B, m0, n0, 0, t);
    asm volatile("cp.async.commit_group;\n");

    const int nk = HID / QBK;
    for (int kt = 0; kt < nk; kt++) {
        __half* buf = sm + (kt & 1) * QSTAGE;
        if (kt + 1 < nk) {
            qload_tile(sm + ((kt + 1) & 1) * QSTAGE, A, B, m0, n0, (kt + 1) * QBK, t);
            asm volatile("cp.async.commit_group;\n");
            asm volatile("cp.async.wait_group 1;\n");
        } else {
            asm volatile("cp.async.wait_group 0;\n");
        }
        __syncthreads();

        #pragma unroll
        for (int ks = 0; ks < 2; ks++) {
            uint32_t ah[4][4];
            #pragma unroll
            for (int i = 0; i < 4; i++) {
                int row = wm * 64 + i * 16 + (g8 & 1) * 8 + l8;
                int col = ks * 16 + (g8 >> 1) * 8;
                ldsm_x4(ah[i], sptr(buf + row * QASTR + col));
            }
            #pragma unroll
            for (int jj = 0; jj < 4; jj++) {         // load-and-consume B frags
                int krow = ks * 16 + (g8 & 1) * 8 + l8;
                int ncol = wn * 64 + jj * 16 + (g8 >> 1) * 8;
                uint32_t r4[4];
                ldsm_x4_t(r4, sptr(buf + QA_T + krow * QBSTR + ncol));
                uint32_t b0[2] = {r4[0], r4[1]}, b1[2] = {r4[2], r4[3]};
                #pragma unroll
                for (int i = 0; i < 4; i++) {
                    mma16816h(acc[i][2 * jj],     ah[i], b0);
                    mma16816h(acc[i][2 * jj + 1], ah[i], b1);
                }
            }
        }
        __syncthreads();
    }

    // fused RoPE + fp16 epilogue; warp tile = one 64-wide head
    const int gc = n0 + wn * 64;
    const int mode = (gc < 2048) ? 0 : (gc < 2560 ? 1 : 2);   // 0=q,1=k,2=v
    const float scale = (mode == 0) ? 0.125f : 1.f;
    __half* outp = (mode == 0) ? q16 : (mode == 1 ? k16 : v16);
    const int ldo  = (mode == 0) ? HID : 512;
    const int base = (mode == 0) ? gc : gc - ((mode == 1) ? 2048 : 2560);

    #pragma unroll
    for (int i = 0; i < 4; i++) {
        int r0 = m0 + wm * 64 + i * 16 + (lane >> 2);
        int r1 = r0 + 8;
        float p0 = (float)pid[r0], p1 = (float)pid[r1];
        #pragma unroll
        for (int j = 0; j < 4; j++) {
            int ch = j * 8 + (lane & 3) * 2;
            float x10 = acc[i][j][0],     x11 = acc[i][j][1];
            float x12 = acc[i][j][2],     x13 = acc[i][j][3];
            float x20 = acc[i][j + 4][0], x21 = acc[i][j + 4][1];
            float x22 = acc[i][j + 4][2], x23 = acc[i][j + 4][3];
            float y10, y11, y12, y13, y20, y21, y22, y23;
            if (mode < 2) {
                float inv0 = __powf(10000.f, -(float)ch * (1.f / 32.f));
                float inv1 = __powf(10000.f, -(float)(ch + 1) * (1.f / 32.f));
                float s00, c00, s01, c01, s10, c10, s11, c11;
                __sincosf(p0 * inv0, &s00, &c00);
                __sincosf(p0 * inv1, &s01, &c01);
                __sincosf(p1 * inv0, &s10, &c10);
                __sincosf(p1 * inv1, &s11, &c11);
                y10 = (x10 * c00 - x20 * s00) * scale; y20 = (x20 * c00 + x10 * s00) * scale;
                y11 = (x11 * c01 - x21 * s01) * scale; y21 = (x21 * c01 + x11 * s01) * scale;
                y12 = (x12 * c10 - x22 * s10) * scale; y22 = (x22 * c10 + x12 * s10) * scale;
                y13 = (x13 * c11 - x23 * s11) * scale; y23 = (x23 * c11 + x13 * s11) * scale;
            } else {
                y10 = x10; y11 = x11; y12 = x12; y13 = x13;
                y20 = x20; y21 = x21; y22 = x22; y23 = x23;
            }
            size_t b0 = (size_t)r0 * ldo + base + ch;
            size_t b1 = (size_t)r1 * ldo + base + ch;
            *(uint32_t*)&outp[b0]      = packh2(y10, y11);
            *(uint32_t*)&outp[b0 + 32] = packh2(y20, y21);
            *(uint32_t*)&outp[b1]      = packh2(y12, y13);
            *(uint32_t*)&outp[b1 + 32] = packh2(y22, y23);
        }
    }
}

// ---------------- O projection: 128x128 CTA (proven round-13 config) ----------------
#define BM 128
#define BN 128
#define BK 32
#define ASTRIDE 40
#define BSTRIDE 136
#define A_T (BM * ASTRIDE)
#define B_T (BK * BSTRIDE)
#define STAGE_F16 (A_T + B_T)
#define GEMM_SMEM_F16 (2 * STAGE_F16 * 2)

__device__ __forceinline__ void load_tile_f16(
    __half* sm, const __half* __restrict__ A, const __half* __restrict__ B,
    int K, int NB, int m0, int n0, int k0, int t)
{
    #pragma unroll
    for (int c = t; c < 512; c += 128) {
        int row = c >> 2, col = (c & 3) * 8;
        cp16(sptr(sm + row * ASTRIDE + col),
             A + (size_t)(m0 + row) * K + k0 + col);
    }
    #pragma unroll
    for (int c = t; c < 512; c += 128) {
        int row = c >> 4, col = (c & 15) * 8;
        cp16(sptr(sm + A_T + row * BSTRIDE + col),
             B + (size_t)(k0 + row) * NB + n0 + col);
    }
}

__global__ __launch_bounds__(128, 2) void oproj_gemm(
    const __half* __restrict__ A, const __half* __restrict__ B,
    float* __restrict__ C)
{
    extern __shared__ __half sm[];
    const int t = threadIdx.x, lane = t & 31, w = t >> 5;
    const int wm = w >> 1, wn = w & 1;
    const int m0 = blockIdx.y * BM, n0 = blockIdx.x * BN;
    const int g8 = lane >> 3, l8 = lane & 7;

    float acc[4][8][4];
    #pragma unroll
    for (int i = 0; i < 4; i++)
        #pragma unroll
        for (int j = 0; j < 8; j++)
            #pragma unroll
            for (int r = 0; r < 4; r++) acc[i][j][r] = 0.f;

    load_tile_f16(sm, A, B, HID, HID, m0, n0, 0, t);
    asm volatile("cp.async.commit_group;\n");

    const int nk = HID / BK;
    for (int kt = 0; kt < nk; kt++) {
        __half* buf = sm + (kt & 1) * STAGE_F16;
        if (kt + 1 < nk) {
            load_tile_f16(sm + ((kt + 1) & 1) * STAGE_F16, A, B,
                          HID, HID, m0, n0, (kt + 1) * BK, t);
            asm volatile("cp.async.commit_group;\n");
            asm volatile("cp.async.wait_group 1;\n");
        } else {
            asm volatile("cp.async.wait_group 0;\n");
        }
        __syncthreads();

        #pragma unroll
        for (int ks = 0; ks < 2; ks++) {
            uint32_t ah[4][4];
            #pragma unroll
            for (int i = 0; i < 4; i++) {
                int row = wm * 64 + i * 16 + (g8 & 1) * 8 + l8;
                int col = ks * 16 + (g8 >> 1) * 8;
                ldsm_x4(ah[i], sptr(buf + row * ASTRIDE + col));
            }
            #pragma unroll
            for (int jj = 0; jj < 4; jj++) {
                int krow = ks * 16 + (g8 & 1) * 8 + l8;
                int ncol = wn * 64 + jj * 16 + (g8 >> 1) * 8;
                uint32_t r4[4];
                ldsm_x4_t(r4, sptr(buf + A_T + krow * BSTRIDE + ncol));
                uint32_t b0[2] = {r4[0], r4[1]}, b1[2] = {r4[2], r4[3]};
                #pragma unroll
                for (int i = 0; i < 4; i++) {
                    mma16816h(acc[i][2 * jj],     ah[i], b0);
                    mma16816h(acc[i][2 * jj + 1], ah[i], b1);
                }
            }
        }
        __syncthreads();
    }

    #pragma unroll
    for (int i = 0; i < 4; i++)
        #pragma unroll
        for (int j = 0; j < 8; j++) {
            int row = m0 + wm * 64 + i * 16 + (lane >> 2);
            int col = n0 + wn * 64 + j * 8 + (lane & 3) * 2;
            *(float2*)&C[(size_t)row * HID + col] =
                make_float2(acc[i][j][0], acc[i][j][1]);
            *(float2*)&C[(size_t)(row + 8) * HID + col] =
                make_float2(acc[i][j][2], acc[i][j][3]);
        }
}

// ---------------- fp16 flash attention (causal), 3 CTAs/SM ----------------
#define Q_OFF   0
#define BUF_OFF (64 * 144)
#define KVBUF   (2 * 64 * 144)
#define ATTN_SMEM (BUF_OFF + 2 * KVBUF)    // 46080

__device__ __forceinline__ void attn_load_kv(
    uint32_t bufb,
    const __half* __restrict__ k16, const __half* __restrict__ v16,
    int k0, int kvh, int t)
{
    #pragma unroll
    for (int i = 0; i < 4; i++) {
        int idx = i * 128 + t;
        int row = idx >> 3, cc = idx & 7;
        uint32_t off = (uint32_t)(row * 144 + cc * 16);
        size_t g = (size_t)(k0 + row) * 512 + kvh * HD + cc * 8;
        cp16(bufb + off,        k16 + g);
        cp16(bufb + 9216 + off, v16 + g);
    }
}

__global__ __launch_bounds__(128, 3) void attn_tc(
    const __half* __restrict__ q16,
    const __half* __restrict__ k16, const __half* __restrict__ v16,
    __half* __restrict__ Aout)
{
    extern __shared__ __align__(1024) char asmem[];
    const uint32_t sb = sptr(asmem);
    const int qt  = 31 - blockIdx.x;
    const int h   = blockIdx.y;
    const int kvh = h >> 2;
    const int t = threadIdx.x, w = t >> 5, lane = t & 31;
    const int g8 = lane >> 3, l8 = lane & 7, tig = lane & 3, g = lane >> 2;
    const int q0 = qt * 64;

    {
        int row = t >> 1, cc = (t & 1) * 4;
        uint32_t off = (uint32_t)(row * 144 + cc * 16);
        size_t gg = (size_t)(q0 + row) * HID + h * HD + cc * 8;
        cp16(sb + Q_OFF + off,      q16 + gg);
        cp16(sb + Q_OFF + off + 16, q16 + gg + 8);
        cp16(sb + Q_OFF + off + 32, q16 + gg + 16);
        cp16(sb + Q_OFF + off + 48, q16 + gg + 24);
    }
    attn_load_kv(sb + BUF_OFF, k16, v16, 0, kvh, t);
    asm volatile("cp.async.commit_group;\n");
    asm volatile("cp.async.wait_group 0;\n");
    __syncthreads();

    uint32_t qa[4][4];
    #pragma unroll
    for (int kc = 0; kc < 4; kc++) {
        uint32_t off = (uint32_t)((w * 16 + (g8 & 1) * 8 + l8) * 144 +
                                  (kc * 16 + (g8 >> 1) * 8) * 2);
        ldsm_x4(qa[kc], sb + Q_OFF + off);
    }

    float oacc[8][4];
    #pragma unroll
    for (int j = 0; j < 8; j++)
        #pragma unroll
        for (int r = 0; r < 4; r++) oacc[j][r] = 0.f;
    float m0 = -1e30f, m1 = -1e30f, l0 = 0.f, l1 = 0.f;

    const int row0 = q0 + w * 16 + g;
    const int row1 = row0 + 8;
    const int nkt = qt + 1;

    for (int kt = 0; kt < nkt; kt++) {
        const uint32_t buf = sb + BUF_OFF + (uint32_t)(kt & 1) * KVBUF;
        if (kt + 1 < nkt) {
            attn_load_kv(sb + BUF_OFF + (uint32_t)((kt + 1) & 1) * KVBUF,
                         k16, v16, (kt + 1) * 64, kvh, t);
            asm volatile("cp.async.commit_group;\n");
            asm volatile("cp.async.wait_group 1;\n");
        } else {
            asm volatile("cp.async.wait_group 0;\n");
        }
        __syncthreads();

        float sacc[8][4];
        #pragma unroll
        for (int j = 0; j < 8; j++)
            #pragma unroll
            for (int r = 0; r < 4; r++) sacc[j][r] = 0.f;

        #pragma unroll
        for (int kg = 0; kg < 4; kg++) {
            #pragma unroll
            for (int kc = 0; kc < 4; kc++) {
                uint32_t off = (uint32_t)((kg * 16 + (g8 & 1) * 8 + l8) * 144 +
                                          (kc * 16 + (g8 >> 1) * 8) * 2);
                uint32_t kb[4];
                ldsm_x4(kb, buf + off);
                uint32_t b0[2] = {kb[0], kb[2]}, b1[2] = {kb[1], kb[3]};
                mma16816h(sacc[2 * kg],     qa[kc], b0);
                mma16816h(sacc[2 * kg + 1], qa[kc], b1);
            }
        }

        if (kt >= qt) {
            #pragma unroll
            for (int j = 0; j < 8; j++) {
                int col = kt * 64 + j * 8 + tig * 2;
                if (col > row0)     sacc[j][0] = -1e30f;
                if (col + 1 > row0) sacc[j][1] = -1e30f;
                if (col > row1)     sacc[j][2] = -1e30f;
                if (col + 1 > row1) sacc[j][3] = -1e30f;
            }
        }

        float mx0 = -1e30f, mx1 = -1e30f;
        #pragma unroll
        for (int j = 0; j < 8; j++) {
            mx0 = fmaxf(mx0, fmaxf(sacc[j][0], sacc[j][1]));
            mx1 = fmaxf(mx1, fmaxf(sacc[j][2], sacc[j][3]));
        }
        mx0 = fmaxf(mx0, __shfl_xor_sync(0xffffffffu, mx0, 1));
        mx0 = fmaxf(mx0, __shfl_xor_sync(0xffffffffu, mx0, 2));
        mx1 = fmaxf(mx1, __shfl_xor_sync(0xffffffffu, mx1, 1));
        mx1 = fmaxf(mx1, __shfl_xor_sync(0xffffffffu, mx1, 2));

        float nm0 = fmaxf(m0, mx0), nm1 = fmaxf(m1, mx1);
        float al0 = __expf(m0 - nm0), al1 = __expf(m1 - nm1);
        m0 = nm0; m1 = nm1;

        float rs0 = 0.f, rs1 = 0.f;
        #pragma unroll
        for (int j = 0; j < 8; j++) {
            sacc[j][0] = __expf(sacc[j][0] - nm0);
            sacc[j][1] = __expf(sacc[j][1] - nm0);
            sacc[j][2] = __expf(sacc[j][2] - nm1);
            sacc[j][3] = __expf(sacc[j][3] - nm1);
            rs0 += sacc[j][0] + sacc[j][1];
            rs1 += sacc[j][2] + sacc[j][3];
        }
        rs0 += __shfl_xor_sync(0xffffffffu, rs0, 1);
        rs0 += __shfl_xor_sync(0xffffffffu, rs0, 2);
        rs1 += __shfl_xor_sync(0xffffffffu, rs1, 1);
        rs1 += __shfl_xor_sync(0xffffffffu, rs1, 2);
        l0 = l0 * al0 + rs0;
        l1 = l1 * al1 + rs1;
        #pragma unroll
        for (int j = 0; j < 8; j++) {
            oacc[j][0] *= al0; oacc[j][1] *= al0;
            oacc[j][2] *= al1; oacc[j][3] *= al1;
        }

        uint32_t pa[4][4];
        #pragma unroll
        for (int kc = 0; kc < 4; kc++) {
            int j0 = 2 * kc, j1 = 2 * kc + 1;
            pa[kc][0] = packh2(sacc[j0][0], sacc[j0][1]);
            pa[kc][1] = packh2(sacc[j0][2], sacc[j0][3]);
            pa[kc][2] = packh2(sacc[j1][0], sacc[j1][1]);
            pa[kc][3] = packh2(sacc[j1][2], sacc[j1][3]);
        }

        #pragma unroll
        for (int kc = 0; kc < 4; kc++) {
            #pragma unroll
            for (int jj = 0; jj < 4; jj++) {
                uint32_t off = (uint32_t)((kc * 16 + (g8 & 1) * 8 + l8) * 144 +
                                          (jj * 16 + (g8 >> 1) * 8) * 2);
                uint32_t vb[4];
                ldsm_x4_t(vb, buf + 9216 + off);
                uint32_t b0[2] = {vb[0], vb[1]}, b1[2] = {vb[2], vb[3]};
                mma16816h(oacc[2 * jj],     pa[kc], b0);
                mma16816h(oacc[2 * jj + 1], pa[kc], b1);
            }
        }
        __syncthreads();
    }

    float i0 = 1.0f / l0, i1 = 1.0f / l1;
    #pragma unroll
    for (int j = 0; j < 8; j++) {
        int col = h * HD + j * 8 + tig * 2;
        float o0 = oacc[j][0] * i0, o1 = oacc[j][1] * i0;
        float o2 = oacc[j][2] * i1, o3 = oacc[j][3] * i1;
        *(uint32_t*)&Aout[(size_t)row0 * HID + col] = packh2(o0, o1);
        *(uint32_t*)&Aout[(size_t)row1 * HID + col] = packh2(o2, o3);
    }
}

// ---------------- launch ----------------
extern "C" void kernel_launch(void* const* d_in, const int* in_sizes, int n_in,
                              void* d_out, int out_size)
{
    const float* X   = (const float*)d_in[0];
    const int*   pid = (const int*)d_in[2];
    const float* Wq  = (const float*)d_in[3];
    const float* Wk  = (const float*)d_in[4];
    const float* Wv  = (const float*)d_in[5];
    const float* Wo  = (const float*)d_in[6];
    float* out = (float*)d_out;

    __half *Xh, *Wqkv, *Wo16, *A16, *q16, *k16, *v16;
    cudaGetSymbolAddress((void**)&Xh,   g_Xh16);
    cudaGetSymbolAddress((void**)&Wqkv, g_Wqkv16);
    cudaGetSymbolAddress((void**)&Wo16, g_Wo16);
    cudaGetSymbolAddress((void**)&A16,  g_A16);
    cudaGetSymbolAddress((void**)&q16,  g_q16);
    cudaGetSymbolAddress((void**)&k16,  g_k16);
    cudaGetSymbolAddress((void**)&v16,  g_v16);

    cudaFuncSetAttribute(qkv_gemm,  cudaFuncAttributeMaxDynamicSharedMemorySize, QKV_SMEM);
    cudaFuncSetAttribute(oproj_gemm,cudaFuncAttributeMaxDynamicSharedMemorySize, GEMM_SMEM_F16);
    cudaFuncSetAttribute(attn_tc,   cudaFuncAttributeMaxDynamicSharedMemorySize, ATTN_SMEM);

    // conversions (2 launches)
    {
        int n8each = S_LEN * HID / 8;
        cvt_two_v4<<<(2 * n8each + 255) / 256, 256>>>(X, Xh, Wo, Wo16, n8each);
        int n8 = HID * NQKV / 8;
        cvt_wqkv_v4<<<(n8 + 255) / 256, 256>>>(Wq, Wk, Wv, Wqkv, n8);
    }

    // fused QKV projection + RoPE (single-wave 128x192 tiles)
    qkv_gemm<<<dim3(NQKV / QBN, S_LEN / QBM), 192, QKV_SMEM>>>(
        Xh, Wqkv, pid, q16, k16, v16);

    // attention (3 CTAs/SM)
    attn_tc<<<dim3(32, NH), 128, ATTN_SMEM>>>(q16, k16, v16, A16);

    // O projection
    oproj_gemm<<<dim3(HID / BN, S_LEN / BM), 128, GEMM_SMEM_F16>>>(
        A16, Wo16, out);
}

// round 15
// speedup vs baseline: 4.1635x; 1.0172x over previous
#include <cuda_runtime.h>
#include <cuda_fp16.h>
#include <math.h>
#include <stdint.h>

#define S_LEN 2048
#define HID   2048
#define NH    32
#define NKV   8
#define HD    64
#define KVW   1024
#define NQKV  3072
#define LOG2E 1.4426950408889634f

// ---------------- scratch (all single fp16) ----------------
__device__ __half g_Xh16 [S_LEN * HID];
__device__ __half g_Wqkv16[HID * NQKV];
__device__ __half g_Wo16[HID * HID];
__device__ __half g_A16 [S_LEN * HID];

__device__ __half g_q16[S_LEN * HID];   // holds q * (1/8) * log2(e)
__device__ __half g_k16[S_LEN * 512];
__device__ __half g_v16[S_LEN * 512];

// ---------------- helpers ----------------
__device__ __forceinline__ uint32_t sptr(const void* p) {
    return (uint32_t)__cvta_generic_to_shared(p);
}
__device__ __forceinline__ void cp16(uint32_t dst, const void* src) {
    asm volatile("cp.async.cg.shared.global [%0], [%1], 16;\n" :: "r"(dst), "l"(src));
}
__device__ __forceinline__ void ldsm_x4(uint32_t* r, uint32_t addr) {
    asm volatile("ldmatrix.sync.aligned.m8n8.x4.shared.b16 {%0,%1,%2,%3}, [%4];\n"
        : "=r"(r[0]), "=r"(r[1]), "=r"(r[2]), "=r"(r[3]) : "r"(addr));
}
__device__ __forceinline__ void ldsm_x4_t(uint32_t* r, uint32_t addr) {
    asm volatile("ldmatrix.sync.aligned.m8n8.x4.trans.shared.b16 {%0,%1,%2,%3}, [%4];\n"
        : "=r"(r[0]), "=r"(r[1]), "=r"(r[2]), "=r"(r[3]) : "r"(addr));
}
__device__ __forceinline__ void mma16816h(float* c, const uint32_t* a, const uint32_t* b) {
    asm volatile(
        "mma.sync.aligned.m16n8k16.row.col.f32.f16.f16.f32 "
        "{%0,%1,%2,%3}, {%4,%5,%6,%7}, {%8,%9}, {%0,%1,%2,%3};\n"
        : "+f"(c[0]), "+f"(c[1]), "+f"(c[2]), "+f"(c[3])
        : "r"(a[0]), "r"(a[1]), "r"(a[2]), "r"(a[3]), "r"(b[0]), "r"(b[1]));
}
__device__ __forceinline__ uint32_t packh2(float x, float y) {
    __half2 h = __floats2half2_rn(x, y);
    return *(uint32_t*)&h;
}

// ---------------- conversion kernels (merged) ----------------
__global__ __launch_bounds__(256) void cvt_two_v4(
    const float* __restrict__ X, __half* __restrict__ Xo,
    const float* __restrict__ W, __half* __restrict__ Wo, int n8each)
{
    int i = blockIdx.x * 256 + threadIdx.x;
    const float* src; __half* dst; int idx;
    if (i < n8each) { src = X; dst = Xo; idx = i; }
    else            { src = W; dst = Wo; idx = i - n8each; if (idx >= n8each) return; }
    const float4* p = (const float4*)src + 2 * (size_t)idx;
    float4 f0 = p[0], f1 = p[1];
    uint32_t h[4];
    h[0] = packh2(f0.x, f0.y); h[1] = packh2(f0.z, f0.w);
    h[2] = packh2(f1.x, f1.y); h[3] = packh2(f1.z, f1.w);
    ((uint4*)dst)[idx] = make_uint4(h[0], h[1], h[2], h[3]);
}

__global__ __launch_bounds__(256) void cvt_wqkv_v4(
    const float* __restrict__ Wq, const float* __restrict__ Wk,
    const float* __restrict__ Wv, __half* __restrict__ out, int n8)
{
    int i = blockIdx.x * 256 + threadIdx.x;
    if (i >= n8) return;
    int r = i / (NQKV / 8), c8 = i % (NQKV / 8);
    int col = c8 * 8;
    const float* src;
    if (col < 2048)      src = Wq + (size_t)r * 2048 + col;
    else if (col < 2560) src = Wk + (size_t)r * 512 + (col - 2048);
    else                 src = Wv + (size_t)r * 512 + (col - 2560);
    float4 f0 = ((const float4*)src)[0], f1 = ((const float4*)src)[1];
    uint32_t h[4];
    h[0] = packh2(f0.x, f0.y); h[1] = packh2(f0.z, f0.w);
    h[2] = packh2(f1.x, f1.y); h[3] = packh2(f1.z, f1.w);
    ((uint4*)out)[i] = make_uint4(h[0], h[1], h[2], h[3]);
}

// ---------------- QKV GEMM: 128x192 CTA, 6 warps (2x3), 64x64 warp tile ----------------
#define QBM 128
#define QBN 192
#define QBK 32
#define QASTR 40
#define QBSTR 200
#define QA_T (QBM * QASTR)
#define QB_T (QBK * QBSTR)
#define QSTAGE (QA_T + QB_T)
#define QKV_SMEM (2 * QSTAGE * 2)

__device__ __forceinline__ void qload_tile(
    __half* sm, const __half* __restrict__ A, const __half* __restrict__ B,
    int m0, int n0, int k0, int t)
{
    for (int c = t; c < 512; c += 192) {
        int row = c >> 2, col = (c & 3) * 8;
        cp16(sptr(sm + row * QASTR + col),
             A + (size_t)(m0 + row) * HID + k0 + col);
    }
    for (int c = t; c < 768; c += 192) {
        int row = c / 24, col = (c % 24) * 8;
        cp16(sptr(sm + QA_T + row * QBSTR + col),
             B + (size_t)(k0 + row) * NQKV + n0 + col);
    }
}

__global__ __launch_bounds__(192, 2) void qkv_gemm(
    const __half* __restrict__ A, const __half* __restrict__ B,
    const int* __restrict__ pid,
    __half* __restrict__ q16, __half* __restrict__ k16, __half* __restrict__ v16)
{
    extern __shared__ __half sm[];
    const int t = threadIdx.x, lane = t & 31, w = t >> 5;
    const int wm = w / 3, wn = w % 3;
    const int m0 = blockIdx.y * QBM, n0 = blockIdx.x * QBN;
    const int g8 = lane >> 3, l8 = lane & 7;

    float acc[4][8][4];
    #pragma unroll
    for (int i = 0; i < 4; i++)
        #pragma unroll
        for (int j = 0; j < 8; j++)
            #pragma unroll
            for (int r = 0; r < 4; r++) acc[i][j][r] = 0.f;

    qload_tile(sm, A, B, m0, n0, 0, t);
    asm volatile("cp.async.commit_group;\n");

    const int nk = HID / QBK;
    for (int kt = 0; kt < nk; kt++) {
        __half* buf = sm + (kt & 1) * QSTAGE;
        if (kt + 1 < nk) {
            qload_tile(sm + ((kt + 1) & 1) * QSTAGE, A, B, m0, n0, (kt + 1) * QBK, t);
            asm volatile("cp.async.commit_group;\n");
            asm volatile("cp.async.wait_group 1;\n");
        } else {
            asm volatile("cp.async.wait_group 0;\n");
        }
        __syncthreads();

        #pragma unroll
        for (int ks = 0; ks < 2; ks++) {
            uint32_t ah[4][4];
            #pragma unroll
            for (int i = 0; i < 4; i++) {
                int row = wm * 64 + i * 16 + (g8 & 1) * 8 + l8;
                int col = ks * 16 + (g8 >> 1) * 8;
                ldsm_x4(ah[i], sptr(buf + row * QASTR + col));
            }
            #pragma unroll
            for (int jj = 0; jj < 4; jj++) {
                int krow = ks * 16 + (g8 & 1) * 8 + l8;
                int ncol = wn * 64 + jj * 16 + (g8 >> 1) * 8;
                uint32_t r4[4];
                ldsm_x4_t(r4, sptr(buf + QA_T + krow * QBSTR + ncol));
                uint32_t b0[2] = {r4[0], r4[1]}, b1[2] = {r4[2], r4[3]};
                #pragma unroll
                for (int i = 0; i < 4; i++) {
                    mma16816h(acc[i][2 * jj],     ah[i], b0);
                    mma16816h(acc[i][2 * jj + 1], ah[i], b1);
                }
            }
        }
        __syncthreads();
    }

    const int gc = n0 + wn * 64;
    const int mode = (gc < 2048) ? 0 : (gc < 2560 ? 1 : 2);
    const float scale = (mode == 0) ? 0.125f * LOG2E : 1.f;   // fold log2(e) into q
    __half* outp = (mode == 0) ? q16 : (mode == 1 ? k16 : v16);
    const int ldo  = (mode == 0) ? HID : 512;
    const int base = (mode == 0) ? gc : gc - ((mode == 1) ? 2048 : 2560);

    #pragma unroll
    for (int i = 0; i < 4; i++) {
        int r0 = m0 + wm * 64 + i * 16 + (lane >> 2);
        int r1 = r0 + 8;
        float p0 = (float)pid[r0], p1 = (float)pid[r1];
        #pragma unroll
        for (int j = 0; j < 4; j++) {
            int ch = j * 8 + (lane & 3) * 2;
            float x10 = acc[i][j][0],     x11 = acc[i][j][1];
            float x12 = acc[i][j][2],     x13 = acc[i][j][3];
            float x20 = acc[i][j + 4][0], x21 = acc[i][j + 4][1];
            float x22 = acc[i][j + 4][2], x23 = acc[i][j + 4][3];
            float y10, y11, y12, y13, y20, y21, y22, y23;
            if (mode < 2) {
                float inv0 = __powf(10000.f, -(float)ch * (1.f / 32.f));
                float inv1 = __powf(10000.f, -(float)(ch + 1) * (1.f / 32.f));
                float s00, c00, s01, c01, s10, c10, s11, c11;
                __sincosf(p0 * inv0, &s00, &c00);
                __sincosf(p0 * inv1, &s01, &c01);
                __sincosf(p1 * inv0, &s10, &c10);
                __sincosf(p1 * inv1, &s11, &c11);
                y10 = (x10 * c00 - x20 * s00) * scale; y20 = (x20 * c00 + x10 * s00) * scale;
                y11 = (x11 * c01 - x21 * s01) * scale; y21 = (x21 * c01 + x11 * s01) * scale;
                y12 = (x12 * c10 - x22 * s10) * scale; y22 = (x22 * c10 + x12 * s10) * scale;
                y13 = (x13 * c11 - x23 * s11) * scale; y23 = (x23 * c11 + x13 * s11) * scale;
            } else {
                y10 = x10; y11 = x11; y12 = x12; y13 = x13;
                y20 = x20; y21 = x21; y22 = x22; y23 = x23;
            }
            size_t b0 = (size_t)r0 * ldo + base + ch;
            size_t b1 = (size_t)r1 * ldo + base + ch;
            *(uint32_t*)&outp[b0]      = packh2(y10, y11);
            *(uint32_t*)&outp[b0 + 32] = packh2(y20, y21);
            *(uint32_t*)&outp[b1]      = packh2(y12, y13);
            *(uint32_t*)&outp[b1 + 32] = packh2(y22, y23);
        }
    }
}

// ---------------- O projection: 128x128 CTA ----------------
#define BM 128
#define BN 128
#define BK 32
#define ASTRIDE 40
#define BSTRIDE 136
#define A_T (BM * ASTRIDE)
#define B_T (BK * BSTRIDE)
#define STAGE_F16 (A_T + B_T)
#define GEMM_SMEM_F16 (2 * STAGE_F16 * 2)

__device__ __forceinline__ void load_tile_f16(
    __half* sm, const __half* __restrict__ A, const __half* __restrict__ B,
    int K, int NB, int m0, int n0, int k0, int t)
{
    #pragma unroll
    for (int c = t; c < 512; c += 128) {
        int row = c >> 2, col = (c & 3) * 8;
        cp16(sptr(sm + row * ASTRIDE + col),
             A + (size_t)(m0 + row) * K + k0 + col);
    }
    #pragma unroll
    for (int c = t; c < 512; c += 128) {
        int row = c >> 4, col = (c & 15) * 8;
        cp16(sptr(sm + A_T + row * BSTRIDE + col),
             B + (size_t)(k0 + row) * NB + n0 + col);
    }
}

__global__ __launch_bounds__(128, 2) void oproj_gemm(
    const __half* __restrict__ A, const __half* __restrict__ B,
    float* __restrict__ C)
{
    extern __shared__ __half sm[];
    const int t = threadIdx.x, lane = t & 31, w = t >> 5;
    const int wm = w >> 1, wn = w & 1;
    const int m0 = blockIdx.y * BM, n0 = blockIdx.x * BN;
    const int g8 = lane >> 3, l8 = lane & 7;

    float acc[4][8][4];
    #pragma unroll
    for (int i = 0; i < 4; i++)
        #pragma unroll
        for (int j = 0; j < 8; j++)
            #pragma unroll
            for (int r = 0; r < 4; r++) acc[i][j][r] = 0.f;

    load_tile_f16(sm, A, B, HID, HID, m0, n0, 0, t);
    asm volatile("cp.async.commit_group;\n");

    const int nk = HID / BK;
    for (int kt = 0; kt < nk; kt++) {
        __half* buf = sm + (kt & 1) * STAGE_F16;
        if (kt + 1 < nk) {
            load_tile_f16(sm + ((kt + 1) & 1) * STAGE_F16, A, B,
                          HID, HID, m0, n0, (kt + 1) * BK, t);
            asm volatile("cp.async.commit_group;\n");
            asm volatile("cp.async.wait_group 1;\n");
        } else {
            asm volatile("cp.async.wait_group 0;\n");
        }
        __syncthreads();

        #pragma unroll
        for (int ks = 0; ks < 2; ks++) {
            uint32_t ah[4][4];
            #pragma unroll
            for (int i = 0; i < 4; i++) {
                int row = wm * 64 + i * 16 + (g8 & 1) * 8 + l8;
                int col = ks * 16 + (g8 >> 1) * 8;
                ldsm_x4(ah[i], sptr(buf + row * ASTRIDE + col));
            }
            #pragma unroll
            for (int jj = 0; jj < 4; jj++) {
                int krow = ks * 16 + (g8 & 1) * 8 + l8;
                int ncol = wn * 64 + jj * 16 + (g8 >> 1) * 8;
                uint32_t r4[4];
                ldsm_x4_t(r4, sptr(buf + A_T + krow * BSTRIDE + ncol));
                uint32_t b0[2] = {r4[0], r4[1]}, b1[2] = {r4[2], r4[3]};
                #pragma unroll
                for (int i = 0; i < 4; i++) {
                    mma16816h(acc[i][2 * jj],     ah[i], b0);
                    mma16816h(acc[i][2 * jj + 1], ah[i], b1);
                }
            }
        }
        __syncthreads();
    }

    #pragma unroll
    for (int i = 0; i < 4; i++)
        #pragma unroll
        for (int j = 0; j < 8; j++) {
            int row = m0 + wm * 64 + i * 16 + (lane >> 2);
            int col = n0 + wn * 64 + j * 8 + (lane & 3) * 2;
            *(float2*)&C[(size_t)row * HID + col] =
                make_float2(acc[i][j][0], acc[i][j][1]);
            *(float2*)&C[(size_t)(row + 8) * HID + col] =
                make_float2(acc[i][j][2], acc[i][j][3]);
        }
}

// ---------------- fp16 flash attention (causal), 4 CTAs/SM, exp2 domain ----------------
#define Q_OFF   0
#define BUF_OFF (64 * 144)
#define KVBUF   (2 * 64 * 144)
#define ATTN_SMEM (BUF_OFF + 2 * KVBUF)    // 46080

__device__ __forceinline__ void attn_load_kv(
    uint32_t bufb,
    const __half* __restrict__ k16, const __half* __restrict__ v16,
    int k0, int kvh, int t)
{
    #pragma unroll
    for (int i = 0; i < 4; i++) {
        int idx = i * 128 + t;
        int row = idx >> 3, cc = idx & 7;
        uint32_t off = (uint32_t)(row * 144 + cc * 16);
        size_t g = (size_t)(k0 + row) * 512 + kvh * HD + cc * 8;
        cp16(bufb + off,        k16 + g);
        cp16(bufb + 9216 + off, v16 + g);
    }
}

__global__ __launch_bounds__(128, 4) void attn_tc(
    const __half* __restrict__ q16,
    const __half* __restrict__ k16, const __half* __restrict__ v16,
    __half* __restrict__ Aout)
{
    extern __shared__ __align__(1024) char asmem[];
    const uint32_t sb = sptr(asmem);
    const int qt  = 31 - blockIdx.x;
    const int h   = blockIdx.y;
    const int kvh = h >> 2;
    const int t = threadIdx.x, w = t >> 5, lane = t & 31;
    const int g8 = lane >> 3, l8 = lane & 7, tig = lane & 3, g = lane >> 2;
    const int q0 = qt * 64;

    {
        int row = t >> 1, cc = (t & 1) * 4;
        uint32_t off = (uint32_t)(row * 144 + cc * 16);
        size_t gg = (size_t)(q0 + row) * HID + h * HD + cc * 8;
        cp16(sb + Q_OFF + off,      q16 + gg);
        cp16(sb + Q_OFF + off + 16, q16 + gg + 8);
        cp16(sb + Q_OFF + off + 32, q16 + gg + 16);
        cp16(sb + Q_OFF + off + 48, q16 + gg + 24);
    }
    attn_load_kv(sb + BUF_OFF, k16, v16, 0, kvh, t);
    asm volatile("cp.async.commit_group;\n");
    asm volatile("cp.async.wait_group 0;\n");
    __syncthreads();

    uint32_t qa[4][4];
    #pragma unroll
    for (int kc = 0; kc < 4; kc++) {
        uint32_t off = (uint32_t)((w * 16 + (g8 & 1) * 8 + l8) * 144 +
                                  (kc * 16 + (g8 >> 1) * 8) * 2);
        ldsm_x4(qa[kc], sb + Q_OFF + off);
    }

    float oacc[8][4];
    #pragma unroll
    for (int j = 0; j < 8; j++)
        #pragma unroll
        for (int r = 0; r < 4; r++) oacc[j][r] = 0.f;
    float m0 = -1e30f, m1 = -1e30f, l0 = 0.f, l1 = 0.f;

    const int row0 = q0 + w * 16 + g;
    const int row1 = row0 + 8;
    const int nkt = qt + 1;

    for (int kt = 0; kt < nkt; kt++) {
        const uint32_t buf = sb + BUF_OFF + (uint32_t)(kt & 1) * KVBUF;
        if (kt + 1 < nkt) {
            attn_load_kv(sb + BUF_OFF + (uint32_t)((kt + 1) & 1) * KVBUF,
                         k16, v16, (kt + 1) * 64, kvh, t);
            asm volatile("cp.async.commit_group;\n");
            asm volatile("cp.async.wait_group 1;\n");
        } else {
            asm volatile("cp.async.wait_group 0;\n");
        }
        __syncthreads();

        float sacc[8][4];
        #pragma unroll
        for (int j = 0; j < 8; j++)
            #pragma unroll
            for (int r = 0; r < 4; r++) sacc[j][r] = 0.f;

        #pragma unroll
        for (int kg = 0; kg < 4; kg++) {
            #pragma unroll
            for (int kc = 0; kc < 4; kc++) {
                uint32_t off = (uint32_t)((kg * 16 + (g8 & 1) * 8 + l8) * 144 +
                                          (kc * 16 + (g8 >> 1) * 8) * 2);
                uint32_t kb[4];
                ldsm_x4(kb, buf + off);
                uint32_t b0[2] = {kb[0], kb[2]}, b1[2] = {kb[1], kb[3]};
                mma16816h(sacc[2 * kg],     qa[kc], b0);
                mma16816h(sacc[2 * kg + 1], qa[kc], b1);
            }
        }

        if (kt >= qt) {
            #pragma unroll
            for (int j = 0; j < 8; j++) {
                int col = kt * 64 + j * 8 + tig * 2;
                if (col > row0)     sacc[j][0] = -1e30f;
                if (col + 1 > row0) sacc[j][1] = -1e30f;
                if (col > row1)     sacc[j][2] = -1e30f;
                if (col + 1 > row1) sacc[j][3] = -1e30f;
            }
        }

        float mx0 = -1e30f, mx1 = -1e30f;
        #pragma unroll
        for (int j = 0; j < 8; j++) {
            mx0 = fmaxf(mx0, fmaxf(sacc[j][0], sacc[j][1]));
            mx1 = fmaxf(mx1, fmaxf(sacc[j][2], sacc[j][3]));
        }
        mx0 = fmaxf(mx0, __shfl_xor_sync(0xffffffffu, mx0, 1));
        mx0 = fmaxf(mx0, __shfl_xor_sync(0xffffffffu, mx0, 2));
        mx1 = fmaxf(mx1, __shfl_xor_sync(0xffffffffu, mx1, 1));
        mx1 = fmaxf(mx1, __shfl_xor_sync(0xffffffffu, mx1, 2));

        float nm0 = fmaxf(m0, mx0), nm1 = fmaxf(m1, mx1);
        float al0 = exp2f(m0 - nm0), al1 = exp2f(m1 - nm1);
        m0 = nm0; m1 = nm1;

        float rs0 = 0.f, rs1 = 0.f;
        #pragma unroll
        for (int j = 0; j < 8; j++) {
            sacc[j][0] = exp2f(sacc[j][0] - nm0);
            sacc[j][1] = exp2f(sacc[j][1] - nm0);
            sacc[j][2] = exp2f(sacc[j][2] - nm1);
            sacc[j][3] = exp2f(sacc[j][3] - nm1);
            rs0 += sacc[j][0] + sacc[j][1];
            rs1 += sacc[j][2] + sacc[j][3];
        }
        rs0 += __shfl_xor_sync(0xffffffffu, rs0, 1);
        rs0 += __shfl_xor_sync(0xffffffffu, rs0, 2);
        rs1 += __shfl_xor_sync(0xffffffffu, rs1, 1);
        rs1 += __shfl_xor_sync(0xffffffffu, rs1, 2);
        l0 = l0 * al0 + rs0;
        l1 = l1 * al1 + rs1;
        #pragma unroll
        for (int j = 0; j < 8; j++) {
            oacc[j][0] *= al0; oacc[j][1] *= al0;
            oacc[j][2] *= al1; oacc[j][3] *= al1;
        }

        uint32_t pa[4][4];
        #pragma unroll
        for (int kc = 0; kc < 4; kc++) {
            int j0 = 2 * kc, j1 = 2 * kc + 1;
            pa[kc][0] = packh2(sacc[j0][0], sacc[j0][1]);
            pa[kc][1] = packh2(sacc[j0][2], sacc[j0][3]);
            pa[kc][2] = packh2(sacc[j1][0], sacc[j1][1]);
            pa[kc][3] = packh2(sacc[j1][2], sacc[j1][3]);
        }

        #pragma unroll
        for (int kc = 0; kc < 4; kc++) {
            #pragma unroll
            for (int jj = 0; jj < 4; jj++) {
                uint32_t off = (uint32_t)((kc * 16 + (g8 & 1) * 8 + l8) * 144 +
                                          (jj * 16 + (g8 >> 1) * 8) * 2);
                uint32_t vb[4];
                ldsm_x4_t(vb, buf + 9216 + off);
                uint32_t b0[2] = {vb[0], vb[1]}, b1[2] = {vb[2], vb[3]};
                mma16816h(oacc[2 * jj],     pa[kc], b0);
                mma16816h(oacc[2 * jj + 1], pa[kc], b1);
            }
        }
        __syncthreads();
    }

    float i0 = 1.0f / l0, i1 = 1.0f / l1;
    #pragma unroll
    for (int j = 0; j < 8; j++) {
        int col = h * HD + j * 8 + tig * 2;
        float o0 = oacc[j][0] * i0, o1 = oacc[j][1] * i0;
        float o2 = oacc[j][2] * i1, o3 = oacc[j][3] * i1;
        *(uint32_t*)&Aout[(size_t)row0 * HID + col] = packh2(o0, o1);
        *(uint32_t*)&Aout[(size_t)row1 * HID + col] = packh2(o2, o3);
    }
}

// ---------------- launch ----------------
extern "C" void kernel_launch(void* const* d_in, const int* in_sizes, int n_in,
                              void* d_out, int out_size)
{
    const float* X   = (const float*)d_in[0];
    const int*   pid = (const int*)d_in[2];
    const float* Wq  = (const float*)d_in[3];
    const float* Wk  = (const float*)d_in[4];
    const float* Wv  = (const float*)d_in[5];
    const float* Wo  = (const float*)d_in[6];
    float* out = (float*)d_out;

    __half *Xh, *Wqkv, *Wo16, *A16, *q16, *k16, *v16;
    cudaGetSymbolAddress((void**)&Xh,   g_Xh16);
    cudaGetSymbolAddress((void**)&Wqkv, g_Wqkv16);
    cudaGetSymbolAddress((void**)&Wo16, g_Wo16);
    cudaGetSymbolAddress((void**)&A16,  g_A16);
    cudaGetSymbolAddress((void**)&q16,  g_q16);
    cudaGetSymbolAddress((void**)&k16,  g_k16);
    cudaGetSymbolAddress((void**)&v16,  g_v16);

    cudaFuncSetAttribute(qkv_gemm,  cudaFuncAttributeMaxDynamicSharedMemorySize, QKV_SMEM);
    cudaFuncSetAttribute(oproj_gemm,cudaFuncAttributeMaxDynamicSharedMemorySize, GEMM_SMEM_F16);
    cudaFuncSetAttribute(attn_tc,   cudaFuncAttributeMaxDynamicSharedMemorySize, ATTN_SMEM);

    {
        int n8each = S_LEN * HID / 8;
        cvt_two_v4<<<(2 * n8each + 255) / 256, 256>>>(X, Xh, Wo, Wo16, n8each);
        int n8 = HID * NQKV / 8;
        cvt_wqkv_v4<<<(n8 + 255) / 256, 256>>>(Wq, Wk, Wv, Wqkv, n8);
    }

    qkv_gemm<<<dim3(NQKV / QBN, S_LEN / QBM), 192, QKV_SMEM>>>(
        Xh, Wqkv, pid, q16, k16, v16);

    attn_tc<<<dim3(32, NH), 128, ATTN_SMEM>>>(q16, k16, v16, A16);

    oproj_gemm<<<dim3(HID / BN, S_LEN / BM), 128, GEMM_SMEM_F16>>>(
        A16, Wo16, out);
}

// round 16
// speedup vs baseline: 4.1997x; 1.0087x over previous
#include <cuda_runtime.h>
#include <cuda_fp16.h>
#include <math.h>
#include <stdint.h>

#define S_LEN 2048
#define HID   2048
#define NH    32
#define NKV   8
#define HD    64
#define KVW   1024
#define NQKV  3072
#define LOG2E 1.4426950408889634f

// ---------------- scratch (all single fp16) ----------------
__device__ __half g_Xh16 [S_LEN * HID];
__device__ __half g_Wqkv16[HID * NQKV];
__device__ __half g_Wo16[HID * HID];
__device__ __half g_A16 [S_LEN * HID];

__device__ __half g_q16[S_LEN * HID];   // q * (1/8) * log2(e)
__device__ __half g_k16[S_LEN * 512];
__device__ __half g_v16[S_LEN * 512];

// ---------------- helpers ----------------
__device__ __forceinline__ uint32_t sptr(const void* p) {
    return (uint32_t)__cvta_generic_to_shared(p);
}
__device__ __forceinline__ void cp16(uint32_t dst, const void* src) {
    asm volatile("cp.async.cg.shared.global [%0], [%1], 16;\n" :: "r"(dst), "l"(src));
}
__device__ __forceinline__ void ldsm_x4(uint32_t* r, uint32_t addr) {
    asm volatile("ldmatrix.sync.aligned.m8n8.x4.shared.b16 {%0,%1,%2,%3}, [%4];\n"
        : "=r"(r[0]), "=r"(r[1]), "=r"(r[2]), "=r"(r[3]) : "r"(addr));
}
__device__ __forceinline__ void ldsm_x4_t(uint32_t* r, uint32_t addr) {
    asm volatile("ldmatrix.sync.aligned.m8n8.x4.trans.shared.b16 {%0,%1,%2,%3}, [%4];\n"
        : "=r"(r[0]), "=r"(r[1]), "=r"(r[2]), "=r"(r[3]) : "r"(addr));
}
__device__ __forceinline__ void mma16816h(float* c, const uint32_t* a, const uint32_t* b) {
    asm volatile(
        "mma.sync.aligned.m16n8k16.row.col.f32.f16.f16.f32 "
        "{%0,%1,%2,%3}, {%4,%5,%6,%7}, {%8,%9}, {%0,%1,%2,%3};\n"
        : "+f"(c[0]), "+f"(c[1]), "+f"(c[2]), "+f"(c[3])
        : "r"(a[0]), "r"(a[1]), "r"(a[2]), "r"(a[3]), "r"(b[0]), "r"(b[1]));
}
__device__ __forceinline__ uint32_t packh2(float x, float y) {
    __half2 h = __floats2half2_rn(x, y);
    return *(uint32_t*)&h;
}

// ---------------- merged conversion kernel (1 launch) ----------------
#define N8X  (S_LEN * HID / 8)     // 524288
#define N8QW (HID * NQKV / 8)      // 786432
__global__ __launch_bounds__(256) void cvt_all_v4(
    const float* __restrict__ X,  __half* __restrict__ Xo,
    const float* __restrict__ Wo, __half* __restrict__ Wo16,
    const float* __restrict__ Wq, const float* __restrict__ Wk,
    const float* __restrict__ Wv, __half* __restrict__ Wqkv)
{
    int i = blockIdx.x * 256 + threadIdx.x;
    const float* src; __half* dst; size_t oidx;
    if (i < N8X) {
        src = X + (size_t)i * 8; dst = Xo; oidx = i;
    } else if (i < 2 * N8X) {
        int idx = i - N8X;
        src = Wo + (size_t)idx * 8; dst = Wo16; oidx = idx;
    } else {
        int idx = i - 2 * N8X;
        if (idx >= N8QW) return;
        int r = idx / (NQKV / 8), c8 = idx % (NQKV / 8);
        int col = c8 * 8;
        if (col < 2048)      src = Wq + (size_t)r * 2048 + col;
        else if (col < 2560) src = Wk + (size_t)r * 512 + (col - 2048);
        else                 src = Wv + (size_t)r * 512 + (col - 2560);
        dst = Wqkv; oidx = idx;
    }
    float4 f0 = ((const float4*)src)[0], f1 = ((const float4*)src)[1];
    uint32_t h[4];
    h[0] = packh2(f0.x, f0.y); h[1] = packh2(f0.z, f0.w);
    h[2] = packh2(f1.x, f1.y); h[3] = packh2(f1.z, f1.w);
    ((uint4*)dst)[oidx] = make_uint4(h[0], h[1], h[2], h[3]);
}

// ---------------- QKV GEMM: 128x192 CTA, 6 warps (2x3), 64x64 warp tile ----------------
#define QBM 128
#define QBN 192
#define QBK 32
#define QASTR 40
#define QBSTR 200
#define QA_T (QBM * QASTR)
#define QB_T (QBK * QBSTR)
#define QSTAGE (QA_T + QB_T)
#define QKV_SMEM (2 * QSTAGE * 2)

__device__ __forceinline__ void qload_tile(
    __half* sm, const __half* __restrict__ A, const __half* __restrict__ B,
    int m0, int n0, int k0, int t)
{
    for (int c = t; c < 512; c += 192) {
        int row = c >> 2, col = (c & 3) * 8;
        cp16(sptr(sm + row * QASTR + col),
             A + (size_t)(m0 + row) * HID + k0 + col);
    }
    for (int c = t; c < 768; c += 192) {
        int row = c / 24, col = (c % 24) * 8;
        cp16(sptr(sm + QA_T + row * QBSTR + col),
             B + (size_t)(k0 + row) * NQKV + n0 + col);
    }
}

__global__ __launch_bounds__(192, 2) void qkv_gemm(
    const __half* __restrict__ A, const __half* __restrict__ B,
    const int* __restrict__ pid,
    __half* __restrict__ q16, __half* __restrict__ k16, __half* __restrict__ v16)
{
    extern __shared__ __half sm[];
    const int t = threadIdx.x, lane = t & 31, w = t >> 5;
    const int wm = w / 3, wn = w % 3;
    const int m0 = blockIdx.y * QBM, n0 = blockIdx.x * QBN;
    const int g8 = lane >> 3, l8 = lane & 7;

    float acc[4][8][4];
    #pragma unroll
    for (int i = 0; i < 4; i++)
        #pragma unroll
        for (int j = 0; j < 8; j++)
            #pragma unroll
            for (int r = 0; r < 4; r++) acc[i][j][r] = 0.f;

    qload_tile(sm, A, B, m0, n0, 0, t);
    asm volatile("cp.async.commit_group;\n");

    const int nk = HID / QBK;
    for (int kt = 0; kt < nk; kt++) {
        __half* buf = sm + (kt & 1) * QSTAGE;
        if (kt + 1 < nk) {
            qload_tile(sm + ((kt + 1) & 1) * QSTAGE, A, B, m0, n0, (kt + 1) * QBK, t);
            asm volatile("cp.async.commit_group;\n");
            asm volatile("cp.async.wait_group 1;\n");
        } else {
            asm volatile("cp.async.wait_group 0;\n");
        }
        __syncthreads();

        #pragma unroll
        for (int ks = 0; ks < 2; ks++) {
            uint32_t ah[4][4];
            #pragma unroll
            for (int i = 0; i < 4; i++) {
                int row = wm * 64 + i * 16 + (g8 & 1) * 8 + l8;
                int col = ks * 16 + (g8 >> 1) * 8;
                ldsm_x4(ah[i], sptr(buf + row * QASTR + col));
            }
            #pragma unroll
            for (int jj = 0; jj < 4; jj++) {
                int krow = ks * 16 + (g8 & 1) * 8 + l8;
                int ncol = wn * 64 + jj * 16 + (g8 >> 1) * 8;
                uint32_t r4[4];
                ldsm_x4_t(r4, sptr(buf + QA_T + krow * QBSTR + ncol));
                uint32_t b0[2] = {r4[0], r4[1]}, b1[2] = {r4[2], r4[3]};
                #pragma unroll
                for (int i = 0; i < 4; i++) {
                    mma16816h(acc[i][2 * jj],     ah[i], b0);
                    mma16816h(acc[i][2 * jj + 1], ah[i], b1);
                }
            }
        }
        __syncthreads();
    }

    const int gc = n0 + wn * 64;
    const int mode = (gc < 2048) ? 0 : (gc < 2560 ? 1 : 2);
    const float scale = (mode == 0) ? 0.125f * LOG2E : 1.f;
    __half* outp = (mode == 0) ? q16 : (mode == 1 ? k16 : v16);
    const int ldo  = (mode == 0) ? HID : 512;
    const int base = (mode == 0) ? gc : gc - ((mode == 1) ? 2048 : 2560);

    #pragma unroll
    for (int i = 0; i < 4; i++) {
        int r0 = m0 + wm * 64 + i * 16 + (lane >> 2);
        int r1 = r0 + 8;
        float p0 = (float)pid[r0], p1 = (float)pid[r1];
        #pragma unroll
        for (int j = 0; j < 4; j++) {
            int ch = j * 8 + (lane & 3) * 2;
            float x10 = acc[i][j][0],     x11 = acc[i][j][1];
            float x12 = acc[i][j][2],     x13 = acc[i][j][3];
            float x20 = acc[i][j + 4][0], x21 = acc[i][j + 4][1];
            float x22 = acc[i][j + 4][2], x23 = acc[i][j + 4][3];
            float y10, y11, y12, y13, y20, y21, y22, y23;
            if (mode < 2) {
                float inv0 = __powf(10000.f, -(float)ch * (1.f / 32.f));
                float inv1 = __powf(10000.f, -(float)(ch + 1) * (1.f / 32.f));
                float s00, c00, s01, c01, s10, c10, s11, c11;
                __sincosf(p0 * inv0, &s00, &c00);
                __sincosf(p0 * inv1, &s01, &c01);
                __sincosf(p1 * inv0, &s10, &c10);
                __sincosf(p1 * inv1, &s11, &c11);
                y10 = (x10 * c00 - x20 * s00) * scale; y20 = (x20 * c00 + x10 * s00) * scale;
                y11 = (x11 * c01 - x21 * s01) * scale; y21 = (x21 * c01 + x11 * s01) * scale;
                y12 = (x12 * c10 - x22 * s10) * scale; y22 = (x22 * c10 + x12 * s10) * scale;
                y13 = (x13 * c11 - x23 * s11) * scale; y23 = (x23 * c11 + x13 * s11) * scale;
            } else {
                y10 = x10; y11 = x11; y12 = x12; y13 = x13;
                y20 = x20; y21 = x21; y22 = x22; y23 = x23;
            }
            size_t b0 = (size_t)r0 * ldo + base + ch;
            size_t b1 = (size_t)r1 * ldo + base + ch;
            *(uint32_t*)&outp[b0]      = packh2(y10, y11);
            *(uint32_t*)&outp[b0 + 32] = packh2(y20, y21);
            *(uint32_t*)&outp[b1]      = packh2(y12, y13);
            *(uint32_t*)&outp[b1 + 32] = packh2(y22, y23);
        }
    }
}

// ---------------- O projection: 128x128 CTA ----------------
#define BM 128
#define BN 128
#define BK 32
#define ASTRIDE 40
#define BSTRIDE 136
#define A_T (BM * ASTRIDE)
#define B_T (BK * BSTRIDE)
#define STAGE_F16 (A_T + B_T)
#define GEMM_SMEM_F16 (2 * STAGE_F16 * 2)

__device__ __forceinline__ void load_tile_f16(
    __half* sm, const __half* __restrict__ A, const __half* __restrict__ B,
    int K, int NB, int m0, int n0, int k0, int t)
{
    #pragma unroll
    for (int c = t; c < 512; c += 128) {
        int row = c >> 2, col = (c & 3) * 8;
        cp16(sptr(sm + row * ASTRIDE + col),
             A + (size_t)(m0 + row) * K + k0 + col);
    }
    #pragma unroll
    for (int c = t; c < 512; c += 128) {
        int row = c >> 4, col = (c & 15) * 8;
        cp16(sptr(sm + A_T + row * BSTRIDE + col),
             B + (size_t)(k0 + row) * NB + n0 + col);
    }
}

__global__ __launch_bounds__(128, 2) void oproj_gemm(
    const __half* __restrict__ A, const __half* __restrict__ B,
    float* __restrict__ C)
{
    extern __shared__ __half sm[];
    const int t = threadIdx.x, lane = t & 31, w = t >> 5;
    const int wm = w >> 1, wn = w & 1;
    const int m0 = blockIdx.y * BM, n0 = blockIdx.x * BN;
    const int g8 = lane >> 3, l8 = lane & 7;

    float acc[4][8][4];
    #pragma unroll
    for (int i = 0; i < 4; i++)
        #pragma unroll
        for (int j = 0; j < 8; j++)
            #pragma unroll
            for (int r = 0; r < 4; r++) acc[i][j][r] = 0.f;

    load_tile_f16(sm, A, B, HID, HID, m0, n0, 0, t);
    asm volatile("cp.async.commit_group;\n");

    const int nk = HID / BK;
    for (int kt = 0; kt < nk; kt++) {
        __half* buf = sm + (kt & 1) * STAGE_F16;
        if (kt + 1 < nk) {
            load_tile_f16(sm + ((kt + 1) & 1) * STAGE_F16, A, B,
                          HID, HID, m0, n0, (kt + 1) * BK, t);
            asm volatile("cp.async.commit_group;\n");
            asm volatile("cp.async.wait_group 1;\n");
        } else {
            asm volatile("cp.async.wait_group 0;\n");
        }
        __syncthreads();

        #pragma unroll
        for (int ks = 0; ks < 2; ks++) {
            uint32_t ah[4][4];
            #pragma unroll
            for (int i = 0; i < 4; i++) {
                int row = wm * 64 + i * 16 + (g8 & 1) * 8 + l8;
                int col = ks * 16 + (g8 >> 1) * 8;
                ldsm_x4(ah[i], sptr(buf + row * ASTRIDE + col));
            }
            #pragma unroll
            for (int jj = 0; jj < 4; jj++) {
                int krow = ks * 16 + (g8 & 1) * 8 + l8;
                int ncol = wn * 64 + jj * 16 + (g8 >> 1) * 8;
                uint32_t r4[4];
                ldsm_x4_t(r4, sptr(buf + A_T + krow * BSTRIDE + ncol));
                uint32_t b0[2] = {r4[0], r4[1]}, b1[2] = {r4[2], r4[3]};
                #pragma unroll
                for (int i = 0; i < 4; i++) {
                    mma16816h(acc[i][2 * jj],     ah[i], b0);
                    mma16816h(acc[i][2 * jj + 1], ah[i], b1);
                }
            }
        }
        __syncthreads();
    }

    #pragma unroll
    for (int i = 0; i < 4; i++)
        #pragma unroll
        for (int j = 0; j < 8; j++) {
            int row = m0 + wm * 64 + i * 16 + (lane >> 2);
            int col = n0 + wn * 64 + j * 8 + (lane & 3) * 2;
            *(float2*)&C[(size_t)row * HID + col] =
                make_float2(acc[i][j][0], acc[i][j][1]);
            *(float2*)&C[(size_t)(row + 8) * HID + col] =
                make_float2(acc[i][j][2], acc[i][j][3]);
        }
}

// ---------------- fp16 flash attention: 128-key tiles, exp2 domain ----------------
// 64 q-rows x 4 warps per CTA; 2 CTAs/SM. Softmax spine runs once per 128 keys.
#define Q_OFF   0
#define BUF_OFF (64 * 144)                  // 9216
#define KVBUF   (2 * 128 * 144)             // 36864 per stage (K 128 rows + V 128 rows)
#define V_OFF   (128 * 144)                 // 18432 within stage
#define ATTN_SMEM (BUF_OFF + 2 * KVBUF)     // 82944

__device__ __forceinline__ void attn_load_kv(
    uint32_t bufb,
    const __half* __restrict__ k16, const __half* __restrict__ v16,
    int k0, int kvh, int t)
{
    #pragma unroll
    for (int i = 0; i < 8; i++) {
        int idx = i * 128 + t;
        int row = idx >> 3, cc = idx & 7;
        uint32_t off = (uint32_t)(row * 144 + cc * 16);
        size_t g = (size_t)(k0 + row) * 512 + kvh * HD + cc * 8;
        cp16(bufb + off,         k16 + g);
        cp16(bufb + V_OFF + off, v16 + g);
    }
}

__global__ __launch_bounds__(128, 2) void attn_tc(
    const __half* __restrict__ q16,
    const __half* __restrict__ k16, const __half* __restrict__ v16,
    __half* __restrict__ Aout)
{
    extern __shared__ __align__(1024) char asmem[];
    const uint32_t sb = sptr(asmem);
    const int qt  = 31 - blockIdx.x;
    const int h   = blockIdx.y;
    const int kvh = h >> 2;
    const int t = threadIdx.x, w = t >> 5, lane = t & 31;
    const int g8 = lane >> 3, l8 = lane & 7, tig = lane & 3, g = lane >> 2;
    const int q0 = qt * 64;

    {
        int row = t >> 1, cc = (t & 1) * 4;
        uint32_t off = (uint32_t)(row * 144 + cc * 16);
        size_t gg = (size_t)(q0 + row) * HID + h * HD + cc * 8;
        cp16(sb + Q_OFF + off,      q16 + gg);
        cp16(sb + Q_OFF + off + 16, q16 + gg + 8);
        cp16(sb + Q_OFF + off + 32, q16 + gg + 16);
        cp16(sb + Q_OFF + off + 48, q16 + gg + 24);
    }
    attn_load_kv(sb + BUF_OFF, k16, v16, 0, kvh, t);
    asm volatile("cp.async.commit_group;\n");
    asm volatile("cp.async.wait_group 0;\n");
    __syncthreads();

    uint32_t qa[4][4];
    #pragma unroll
    for (int kc = 0; kc < 4; kc++) {
        uint32_t off = (uint32_t)((w * 16 + (g8 & 1) * 8 + l8) * 144 +
                                  (kc * 16 + (g8 >> 1) * 8) * 2);
        ldsm_x4(qa[kc], sb + Q_OFF + off);
    }

    float oacc[8][4];
    #pragma unroll
    for (int j = 0; j < 8; j++)
        #pragma unroll
        for (int r = 0; r < 4; r++) oacc[j][r] = 0.f;
    float m0 = -1e30f, m1 = -1e30f, l0 = 0.f, l1 = 0.f;

    const int row0 = q0 + w * 16 + g;
    const int row1 = row0 + 8;
    const int nkt = (qt >> 1) + 1;      // 128-key tiles, causal

    for (int kt = 0; kt < nkt; kt++) {
        const uint32_t buf = sb + BUF_OFF + (uint32_t)(kt & 1) * KVBUF;
        if (kt + 1 < nkt) {
            attn_load_kv(sb + BUF_OFF + (uint32_t)((kt + 1) & 1) * KVBUF,
                         k16, v16, (kt + 1) * 128, kvh, t);
            asm volatile("cp.async.commit_group;\n");
            asm volatile("cp.async.wait_group 1;\n");
        } else {
            asm volatile("cp.async.wait_group 0;\n");
        }
        __syncthreads();

        float sacc[16][4];
        #pragma unroll
        for (int j = 0; j < 16; j++)
            #pragma unroll
            for (int r = 0; r < 4; r++) sacc[j][r] = 0.f;

        // S = Q K^T over 128 keys (8 kg groups)
        #pragma unroll
        for (int kg = 0; kg < 8; kg++) {
            #pragma unroll
            for (int kc = 0; kc < 4; kc++) {
                uint32_t off = (uint32_t)((kg * 16 + (g8 & 1) * 8 + l8) * 144 +
                                          (kc * 16 + (g8 >> 1) * 8) * 2);
                uint32_t kb[4];
                ldsm_x4(kb, buf + off);
                uint32_t b0[2] = {kb[0], kb[2]}, b1[2] = {kb[1], kb[3]};
                mma16816h(sacc[2 * kg],     qa[kc], b0);
                mma16816h(sacc[2 * kg + 1], qa[kc], b1);
            }
        }

        if (kt == nkt - 1) {            // only final tile can cross the diagonal
            #pragma unroll
            for (int j = 0; j < 16; j++) {
                int col = kt * 128 + j * 8 + tig * 2;
                if (col > row0)     sacc[j][0] = -1e30f;
                if (col + 1 > row0) sacc[j][1] = -1e30f;
                if (col > row1)     sacc[j][2] = -1e30f;
                if (col + 1 > row1) sacc[j][3] = -1e30f;
            }
        }

        float mx0 = -1e30f, mx1 = -1e30f;
        #pragma unroll
        for (int j = 0; j < 16; j++) {
            mx0 = fmaxf(mx0, fmaxf(sacc[j][0], sacc[j][1]));
            mx1 = fmaxf(mx1, fmaxf(sacc[j][2], sacc[j][3]));
        }
        mx0 = fmaxf(mx0, __shfl_xor_sync(0xffffffffu, mx0, 1));
        mx0 = fmaxf(mx0, __shfl_xor_sync(0xffffffffu, mx0, 2));
        mx1 = fmaxf(mx1, __shfl_xor_sync(0xffffffffu, mx1, 1));
        mx1 = fmaxf(mx1, __shfl_xor_sync(0xffffffffu, mx1, 2));

        float nm0 = fmaxf(m0, mx0), nm1 = fmaxf(m1, mx1);
        float al0 = exp2f(m0 - nm0), al1 = exp2f(m1 - nm1);
        m0 = nm0; m1 = nm1;

        float rs0 = 0.f, rs1 = 0.f;
        #pragma unroll
        for (int j = 0; j < 16; j++) {
            sacc[j][0] = exp2f(sacc[j][0] - nm0);
            sacc[j][1] = exp2f(sacc[j][1] - nm0);
            sacc[j][2] = exp2f(sacc[j][2] - nm1);
            sacc[j][3] = exp2f(sacc[j][3] - nm1);
            rs0 += sacc[j][0] + sacc[j][1];
            rs1 += sacc[j][2] + sacc[j][3];
        }
        rs0 += __shfl_xor_sync(0xffffffffu, rs0, 1);
        rs0 += __shfl_xor_sync(0xffffffffu, rs0, 2);
        rs1 += __shfl_xor_sync(0xffffffffu, rs1, 1);
        rs1 += __shfl_xor_sync(0xffffffffu, rs1, 2);
        l0 = l0 * al0 + rs0;
        l1 = l1 * al1 + rs1;
        #pragma unroll
        for (int j = 0; j < 8; j++) {
            oacc[j][0] *= al0; oacc[j][1] *= al0;
            oacc[j][2] *= al1; oacc[j][3] *= al1;
        }

        // P -> fp16 A-frags (8 kc groups of 16 keys)
        uint32_t pa[8][4];
        #pragma unroll
        for (int kc = 0; kc < 8; kc++) {
            int j0 = 2 * kc, j1 = 2 * kc + 1;
            pa[kc][0] = packh2(sacc[j0][0], sacc[j0][1]);
            pa[kc][1] = packh2(sacc[j0][2], sacc[j0][3]);
            pa[kc][2] = packh2(sacc[j1][0], sacc[j1][1]);
            pa[kc][3] = packh2(sacc[j1][2], sacc[j1][3]);
        }

        // O += P V over 128 keys
        #pragma unroll
        for (int kc = 0; kc < 8; kc++) {
            #pragma unroll
            for (int jj = 0; jj < 4; jj++) {
                uint32_t off = (uint32_t)((kc * 16 + (g8 & 1) * 8 + l8) * 144 +
                                          (jj * 16 + (g8 >> 1) * 8) * 2);
                uint32_t vb[4];
                ldsm_x4_t(vb, buf + V_OFF + off);
                uint32_t b0[2] = {vb[0], vb[1]}, b1[2] = {vb[2], vb[3]};
                mma16816h(oacc[2 * jj],     pa[kc], b0);
                mma16816h(oacc[2 * jj + 1], pa[kc], b1);
            }
        }
        __syncthreads();
    }

    float i0 = 1.0f / l0, i1 = 1.0f / l1;
    #pragma unroll
    for (int j = 0; j < 8; j++) {
        int col = h * HD + j * 8 + tig * 2;
        float o0 = oacc[j][0] * i0, o1 = oacc[j][1] * i0;
        float o2 = oacc[j][2] * i1, o3 = oacc[j][3] * i1;
        *(uint32_t*)&Aout[(size_t)row0 * HID + col] = packh2(o0, o1);
        *(uint32_t*)&Aout[(size_t)row1 * HID + col] = packh2(o2, o3);
    }
}

// ---------------- launch ----------------
extern "C" void kernel_launch(void* const* d_in, const int* in_sizes, int n_in,
                              void* d_out, int out_size)
{
    const float* X   = (const float*)d_in[0];
    const int*   pid = (const int*)d_in[2];
    const float* Wq  = (const float*)d_in[3];
    const float* Wk  = (const float*)d_in[4];
    const float* Wv  = (const float*)d_in[5];
    const float* Wo  = (const float*)d_in[6];
    float* out = (float*)d_out;

    __half *Xh, *Wqkv, *Wo16, *A16, *q16, *k16, *v16;
    cudaGetSymbolAddress((void**)&Xh,   g_Xh16);
    cudaGetSymbolAddress((void**)&Wqkv, g_Wqkv16);
    cudaGetSymbolAddress((void**)&Wo16, g_Wo16);
    cudaGetSymbolAddress((void**)&A16,  g_A16);
    cudaGetSymbolAddress((void**)&q16,  g_q16);
    cudaGetSymbolAddress((void**)&k16,  g_k16);
    cudaGetSymbolAddress((void**)&v16,  g_v16);

    cudaFuncSetAttribute(qkv_gemm,  cudaFuncAttributeMaxDynamicSharedMemorySize, QKV_SMEM);
    cudaFuncSetAttribute(oproj_gemm,cudaFuncAttributeMaxDynamicSharedMemorySize, GEMM_SMEM_F16);
    cudaFuncSetAttribute(attn_tc,   cudaFuncAttributeMaxDynamicSharedMemorySize, ATTN_SMEM);

    // merged conversions (1 launch)
    {
        int total = 2 * N8X + N8QW;
        cvt_all_v4<<<(total + 255) / 256, 256>>>(X, Xh, Wo, Wo16, Wq, Wk, Wv, Wqkv);
    }

    qkv_gemm<<<dim3(NQKV / QBN, S_LEN / QBM), 192, QKV_SMEM>>>(
        Xh, Wqkv, pid, q16, k16, v16);

    attn_tc<<<dim3(32, NH), 128, ATTN_SMEM>>>(q16, k16, v16, A16);

    oproj_gemm<<<dim3(HID / BN, S_LEN / BM), 128, GEMM_SMEM_F16>>>(
        A16, Wo16, out);
}

// round 17
// speedup vs baseline: 4.3626x; 1.0388x over previous
#include <cuda_runtime.h>
#include <cuda_fp16.h>
#include <math.h>
#include <stdint.h>

#define S_LEN 2048
#define HID   2048
#define NH    32
#define NKV   8
#define HD    64
#define KVW   1024
#define NQKV  3072
#define LOG2E 1.4426950408889634f

// ---------------- scratch (all single fp16) ----------------
__device__ __half g_Xh16 [S_LEN * HID];
__device__ __half g_Wqkv16[HID * NQKV];
__device__ __half g_Wo16[HID * HID];
__device__ __half g_A16 [S_LEN * HID];

__device__ __half g_q16[S_LEN * HID];   // q * (1/8) * log2(e)
__device__ __half g_k16[S_LEN * 512];
__device__ __half g_v16[S_LEN * 512];

// ---------------- helpers ----------------
__device__ __forceinline__ uint32_t sptr(const void* p) {
    return (uint32_t)__cvta_generic_to_shared(p);
}
__device__ __forceinline__ void cp16(uint32_t dst, const void* src) {
    asm volatile("cp.async.cg.shared.global [%0], [%1], 16;\n" :: "r"(dst), "l"(src));
}
__device__ __forceinline__ void ldsm_x4(uint32_t* r, uint32_t addr) {
    asm volatile("ldmatrix.sync.aligned.m8n8.x4.shared.b16 {%0,%1,%2,%3}, [%4];\n"
        : "=r"(r[0]), "=r"(r[1]), "=r"(r[2]), "=r"(r[3]) : "r"(addr));
}
__device__ __forceinline__ void ldsm_x4_t(uint32_t* r, uint32_t addr) {
    asm volatile("ldmatrix.sync.aligned.m8n8.x4.trans.shared.b16 {%0,%1,%2,%3}, [%4];\n"
        : "=r"(r[0]), "=r"(r[1]), "=r"(r[2]), "=r"(r[3]) : "r"(addr));
}
__device__ __forceinline__ void mma16816h(float* c, const uint32_t* a, const uint32_t* b) {
    asm volatile(
        "mma.sync.aligned.m16n8k16.row.col.f32.f16.f16.f32 "
        "{%0,%1,%2,%3}, {%4,%5,%6,%7}, {%8,%9}, {%0,%1,%2,%3};\n"
        : "+f"(c[0]), "+f"(c[1]), "+f"(c[2]), "+f"(c[3])
        : "r"(a[0]), "r"(a[1]), "r"(a[2]), "r"(a[3]), "r"(b[0]), "r"(b[1]));
}
__device__ __forceinline__ uint32_t packh2(float x, float y) {
    __half2 h = __floats2half2_rn(x, y);
    return *(uint32_t*)&h;
}

// ---------------- merged conversion kernel (1 launch) ----------------
#define N8X  (S_LEN * HID / 8)
#define N8QW (HID * NQKV / 8)
__global__ __launch_bounds__(256) void cvt_all_v4(
    const float* __restrict__ X,  __half* __restrict__ Xo,
    const float* __restrict__ Wo, __half* __restrict__ Wo16,
    const float* __restrict__ Wq, const float* __restrict__ Wk,
    const float* __restrict__ Wv, __half* __restrict__ Wqkv)
{
    int i = blockIdx.x * 256 + threadIdx.x;
    const float* src; __half* dst; size_t oidx;
    if (i < N8X) {
        src = X + (size_t)i * 8; dst = Xo; oidx = i;
    } else if (i < 2 * N8X) {
        int idx = i - N8X;
        src = Wo + (size_t)idx * 8; dst = Wo16; oidx = idx;
    } else {
        int idx = i - 2 * N8X;
        if (idx >= N8QW) return;
        int r = idx / (NQKV / 8), c8 = idx % (NQKV / 8);
        int col = c8 * 8;
        if (col < 2048)      src = Wq + (size_t)r * 2048 + col;
        else if (col < 2560) src = Wk + (size_t)r * 512 + (col - 2048);
        else                 src = Wv + (size_t)r * 512 + (col - 2560);
        dst = Wqkv; oidx = idx;
    }
    float4 f0 = ((const float4*)src)[0], f1 = ((const float4*)src)[1];
    uint32_t h[4];
    h[0] = packh2(f0.x, f0.y); h[1] = packh2(f0.z, f0.w);
    h[2] = packh2(f1.x, f1.y); h[3] = packh2(f1.z, f1.w);
    ((uint4*)dst)[oidx] = make_uint4(h[0], h[1], h[2], h[3]);
}

// ---------------- QKV GEMM: 128x192 CTA, 6 warps, 3-stage pipeline ----------------
#define QBM 128
#define QBN 192
#define QBK 32
#define QASTR 40
#define QBSTR 200
#define QA_T (QBM * QASTR)
#define QB_T (QBK * QBSTR)
#define QSTAGE (QA_T + QB_T)
#define QKV_SMEM (3 * QSTAGE * 2)          // 69120 bytes

__device__ __forceinline__ void qload_tile(
    __half* sm, const __half* __restrict__ A, const __half* __restrict__ B,
    int m0, int n0, int k0, int t)
{
    for (int c = t; c < 512; c += 192) {
        int row = c >> 2, col = (c & 3) * 8;
        cp16(sptr(sm + row * QASTR + col),
             A + (size_t)(m0 + row) * HID + k0 + col);
    }
    for (int c = t; c < 768; c += 192) {
        int row = c / 24, col = (c % 24) * 8;
        cp16(sptr(sm + QA_T + row * QBSTR + col),
             B + (size_t)(k0 + row) * NQKV + n0 + col);
    }
}

__global__ __launch_bounds__(192, 2) void qkv_gemm(
    const __half* __restrict__ A, const __half* __restrict__ B,
    const int* __restrict__ pid,
    __half* __restrict__ q16, __half* __restrict__ k16, __half* __restrict__ v16)
{
    extern __shared__ __half sm[];
    const int t = threadIdx.x, lane = t & 31, w = t >> 5;
    const int wm = w / 3, wn = w % 3;
    const int m0 = blockIdx.y * QBM, n0 = blockIdx.x * QBN;
    const int g8 = lane >> 3, l8 = lane & 7;

    float acc[4][8][4];
    #pragma unroll
    for (int i = 0; i < 4; i++)
        #pragma unroll
        for (int j = 0; j < 8; j++)
            #pragma unroll
            for (int r = 0; r < 4; r++) acc[i][j][r] = 0.f;

    qload_tile(sm, A, B, m0, n0, 0, t);
    asm volatile("cp.async.commit_group;\n");
    qload_tile(sm + QSTAGE, A, B, m0, n0, QBK, t);
    asm volatile("cp.async.commit_group;\n");

    const int nk = HID / QBK;
    int sidx = 0;
    for (int kt = 0; kt < nk; kt++) {
        if (kt == nk - 1) asm volatile("cp.async.wait_group 0;\n");
        else              asm volatile("cp.async.wait_group 1;\n");
        __syncthreads();
        __half* buf = sm + sidx * QSTAGE;

        if (kt + 2 < nk) {           // stage (kt+2)%3 was fully read at kt-1
            qload_tile(sm + ((sidx + 2) % 3) * QSTAGE, A, B, m0, n0, (kt + 2) * QBK, t);
            asm volatile("cp.async.commit_group;\n");
        }

        #pragma unroll
        for (int ks = 0; ks < 2; ks++) {
            uint32_t ah[4][4];
            #pragma unroll
            for (int i = 0; i < 4; i++) {
                int row = wm * 64 + i * 16 + (g8 & 1) * 8 + l8;
                int col = ks * 16 + (g8 >> 1) * 8;
                ldsm_x4(ah[i], sptr(buf + row * QASTR + col));
            }
            #pragma unroll
            for (int jj = 0; jj < 4; jj++) {
                int krow = ks * 16 + (g8 & 1) * 8 + l8;
                int ncol = wn * 64 + jj * 16 + (g8 >> 1) * 8;
                uint32_t r4[4];
                ldsm_x4_t(r4, sptr(buf + QA_T + krow * QBSTR + ncol));
                uint32_t b0[2] = {r4[0], r4[1]}, b1[2] = {r4[2], r4[3]};
                #pragma unroll
                for (int i = 0; i < 4; i++) {
                    mma16816h(acc[i][2 * jj],     ah[i], b0);
                    mma16816h(acc[i][2 * jj + 1], ah[i], b1);
                }
            }
        }
        sidx = (sidx + 1) % 3;
    }

    const int gc = n0 + wn * 64;
    const int mode = (gc < 2048) ? 0 : (gc < 2560 ? 1 : 2);
    const float scale = (mode == 0) ? 0.125f * LOG2E : 1.f;
    __half* outp = (mode == 0) ? q16 : (mode == 1 ? k16 : v16);
    const int ldo  = (mode == 0) ? HID : 512;
    const int base = (mode == 0) ? gc : gc - ((mode == 1) ? 2048 : 2560);

    #pragma unroll
    for (int i = 0; i < 4; i++) {
        int r0 = m0 + wm * 64 + i * 16 + (lane >> 2);
        int r1 = r0 + 8;
        float p0 = (float)pid[r0], p1 = (float)pid[r1];
        #pragma unroll
        for (int j = 0; j < 4; j++) {
            int ch = j * 8 + (lane & 3) * 2;
            float x10 = acc[i][j][0],     x11 = acc[i][j][1];
            float x12 = acc[i][j][2],     x13 = acc[i][j][3];
            float x20 = acc[i][j + 4][0], x21 = acc[i][j + 4][1];
            float x22 = acc[i][j + 4][2], x23 = acc[i][j + 4][3];
            float y10, y11, y12, y13, y20, y21, y22, y23;
            if (mode < 2) {
                float inv0 = __powf(10000.f, -(float)ch * (1.f / 32.f));
                float inv1 = __powf(10000.f, -(float)(ch + 1) * (1.f / 32.f));
                float s00, c00, s01, c01, s10, c10, s11, c11;
                __sincosf(p0 * inv0, &s00, &c00);
                __sincosf(p0 * inv1, &s01, &c01);
                __sincosf(p1 * inv0, &s10, &c10);
                __sincosf(p1 * inv1, &s11, &c11);
                y10 = (x10 * c00 - x20 * s00) * scale; y20 = (x20 * c00 + x10 * s00) * scale;
                y11 = (x11 * c01 - x21 * s01) * scale; y21 = (x21 * c01 + x11 * s01) * scale;
                y12 = (x12 * c10 - x22 * s10) * scale; y22 = (x22 * c10 + x12 * s10) * scale;
                y13 = (x13 * c11 - x23 * s11) * scale; y23 = (x23 * c11 + x13 * s11) * scale;
            } else {
                y10 = x10; y11 = x11; y12 = x12; y13 = x13;
                y20 = x20; y21 = x21; y22 = x22; y23 = x23;
            }
            size_t b0 = (size_t)r0 * ldo + base + ch;
            size_t b1 = (size_t)r1 * ldo + base + ch;
            *(uint32_t*)&outp[b0]      = packh2(y10, y11);
            *(uint32_t*)&outp[b0 + 32] = packh2(y20, y21);
            *(uint32_t*)&outp[b1]      = packh2(y12, y13);
            *(uint32_t*)&outp[b1 + 32] = packh2(y22, y23);
        }
    }
}

// ---------------- O projection: 128x128 CTA, 3-stage pipeline ----------------
#define BM 128
#define BN 128
#define BK 32
#define ASTRIDE 40
#define BSTRIDE 136
#define A_T (BM * ASTRIDE)
#define B_T (BK * BSTRIDE)
#define STAGE_F16 (A_T + B_T)
#define GEMM_SMEM_F16 (3 * STAGE_F16 * 2)   // 56832 bytes

__device__ __forceinline__ void load_tile_f16(
    __half* sm, const __half* __restrict__ A, const __half* __restrict__ B,
    int K, int NB, int m0, int n0, int k0, int t)
{
    #pragma unroll
    for (int c = t; c < 512; c += 128) {
        int row = c >> 2, col = (c & 3) * 8;
        cp16(sptr(sm + row * ASTRIDE + col),
             A + (size_t)(m0 + row) * K + k0 + col);
    }
    #pragma unroll
    for (int c = t; c < 512; c += 128) {
        int row = c >> 4, col = (c & 15) * 8;
        cp16(sptr(sm + A_T + row * BSTRIDE + col),
             B + (size_t)(k0 + row) * NB + n0 + col);
    }
}

__global__ __launch_bounds__(128, 2) void oproj_gemm(
    const __half* __restrict__ A, const __half* __restrict__ B,
    float* __restrict__ C)
{
    extern __shared__ __half sm[];
    const int t = threadIdx.x, lane = t & 31, w = t >> 5;
    const int wm = w >> 1, wn = w & 1;
    const int m0 = blockIdx.y * BM, n0 = blockIdx.x * BN;
    const int g8 = lane >> 3, l8 = lane & 7;

    float acc[4][8][4];
    #pragma unroll
    for (int i = 0; i < 4; i++)
        #pragma unroll
        for (int j = 0; j < 8; j++)
            #pragma unroll
            for (int r = 0; r < 4; r++) acc[i][j][r] = 0.f;

    load_tile_f16(sm, A, B, HID, HID, m0, n0, 0, t);
    asm volatile("cp.async.commit_group;\n");
    load_tile_f16(sm + STAGE_F16, A, B, HID, HID, m0, n0, BK, t);
    asm volatile("cp.async.commit_group;\n");

    const int nk = HID / BK;
    int sidx = 0;
    for (int kt = 0; kt < nk; kt++) {
        if (kt == nk - 1) asm volatile("cp.async.wait_group 0;\n");
        else              asm volatile("cp.async.wait_group 1;\n");
        __syncthreads();
        __half* buf = sm + sidx * STAGE_F16;

        if (kt + 2 < nk) {
            load_tile_f16(sm + ((sidx + 2) % 3) * STAGE_F16, A, B,
                          HID, HID, m0, n0, (kt + 2) * BK, t);
            asm volatile("cp.async.commit_group;\n");
        }

        #pragma unroll
        for (int ks = 0; ks < 2; ks++) {
            uint32_t ah[4][4];
            #pragma unroll
            for (int i = 0; i < 4; i++) {
                int row = wm * 64 + i * 16 + (g8 & 1) * 8 + l8;
                int col = ks * 16 + (g8 >> 1) * 8;
                ldsm_x4(ah[i], sptr(buf + row * ASTRIDE + col));
            }
            #pragma unroll
            for (int jj = 0; jj < 4; jj++) {
                int krow = ks * 16 + (g8 & 1) * 8 + l8;
                int ncol = wn * 64 + jj * 16 + (g8 >> 1) * 8;
                uint32_t r4[4];
                ldsm_x4_t(r4, sptr(buf + A_T + krow * BSTRIDE + ncol));
                uint32_t b0[2] = {r4[0], r4[1]}, b1[2] = {r4[2], r4[3]};
                #pragma unroll
                for (int i = 0; i < 4; i++) {
                    mma16816h(acc[i][2 * jj],     ah[i], b0);
                    mma16816h(acc[i][2 * jj + 1], ah[i], b1);
                }
            }
        }
        sidx = (sidx + 1) % 3;
    }

    #pragma unroll
    for (int i = 0; i < 4; i++)
        #pragma unroll
        for (int j = 0; j < 8; j++) {
            int row = m0 + wm * 64 + i * 16 + (lane >> 2);
            int col = n0 + wn * 64 + j * 8 + (lane & 3) * 2;
            *(float2*)&C[(size_t)row * HID + col] =
                make_float2(acc[i][j][0], acc[i][j][1]);
            *(float2*)&C[(size_t)(row + 8) * HID + col] =
                make_float2(acc[i][j][2], acc[i][j][3]);
        }
}

// ---------------- fp16 flash attention: 128-key tiles, exp2 domain ----------------
#define Q_OFF   0
#define BUF_OFF (64 * 144)
#define KVBUF   (2 * 128 * 144)
#define V_OFF   (128 * 144)
#define ATTN_SMEM (BUF_OFF + 2 * KVBUF)

__device__ __forceinline__ void attn_load_kv(
    uint32_t bufb,
    const __half* __restrict__ k16, const __half* __restrict__ v16,
    int k0, int kvh, int t)
{
    #pragma unroll
    for (int i = 0; i < 8; i++) {
        int idx = i * 128 + t;
        int row = idx >> 3, cc = idx & 7;
        uint32_t off = (uint32_t)(row * 144 + cc * 16);
        size_t g = (size_t)(k0 + row) * 512 + kvh * HD + cc * 8;
        cp16(bufb + off,         k16 + g);
        cp16(bufb + V_OFF + off, v16 + g);
    }
}

__global__ __launch_bounds__(128, 2) void attn_tc(
    const __half* __restrict__ q16,
    const __half* __restrict__ k16, const __half* __restrict__ v16,
    __half* __restrict__ Aout)
{
    extern __shared__ __align__(1024) char asmem[];
    const uint32_t sb = sptr(asmem);
    const int qt  = 31 - blockIdx.x;
    const int h   = blockIdx.y;
    const int kvh = h >> 2;
    const int t = threadIdx.x, w = t >> 5, lane = t & 31;
    const int g8 = lane >> 3, l8 = lane & 7, tig = lane & 3, g = lane >> 2;
    const int q0 = qt * 64;

    {
        int row = t >> 1, cc = (t & 1) * 4;
        uint32_t off = (uint32_t)(row * 144 + cc * 16);
        size_t gg = (size_t)(q0 + row) * HID + h * HD + cc * 8;
        cp16(sb + Q_OFF + off,      q16 + gg);
        cp16(sb + Q_OFF + off + 16, q16 + gg + 8);
        cp16(sb + Q_OFF + off + 32, q16 + gg + 16);
        cp16(sb + Q_OFF + off + 48, q16 + gg + 24);
    }
    attn_load_kv(sb + BUF_OFF, k16, v16, 0, kvh, t);
    asm volatile("cp.async.commit_group;\n");
    asm volatile("cp.async.wait_group 0;\n");
    __syncthreads();

    uint32_t qa[4][4];
    #pragma unroll
    for (int kc = 0; kc < 4; kc++) {
        uint32_t off = (uint32_t)((w * 16 + (g8 & 1) * 8 + l8) * 144 +
                                  (kc * 16 + (g8 >> 1) * 8) * 2);
        ldsm_x4(qa[kc], sb + Q_OFF + off);
    }

    float oacc[8][4];
    #pragma unroll
    for (int j = 0; j < 8; j++)
        #pragma unroll
        for (int r = 0; r < 4; r++) oacc[j][r] = 0.f;
    float m0 = -1e30f, m1 = -1e30f, l0 = 0.f, l1 = 0.f;

    const int row0 = q0 + w * 16 + g;
    const int row1 = row0 + 8;
    const int nkt = (qt >> 1) + 1;

    for (int kt = 0; kt < nkt; kt++) {
        const uint32_t buf = sb + BUF_OFF + (uint32_t)(kt & 1) * KVBUF;
        if (kt + 1 < nkt) {
            attn_load_kv(sb + BUF_OFF + (uint32_t)((kt + 1) & 1) * KVBUF,
                         k16, v16, (kt + 1) * 128, kvh, t);
            asm volatile("cp.async.commit_group;\n");
            asm volatile("cp.async.wait_group 1;\n");
        } else {
            asm volatile("cp.async.wait_group 0;\n");
        }
        __syncthreads();

        float sacc[16][4];
        #pragma unroll
        for (int j = 0; j < 16; j++)
            #pragma unroll
            for (int r = 0; r < 4; r++) sacc[j][r] = 0.f;

        #pragma unroll
        for (int kg = 0; kg < 8; kg++) {
            #pragma unroll
            for (int kc = 0; kc < 4; kc++) {
                uint32_t off = (uint32_t)((kg * 16 + (g8 & 1) * 8 + l8) * 144 +
                                          (kc * 16 + (g8 >> 1) * 8) * 2);
                uint32_t kb[4];
                ldsm_x4(kb, buf + off);
                uint32_t b0[2] = {kb[0], kb[2]}, b1[2] = {kb[1], kb[3]};
                mma16816h(sacc[2 * kg],     qa[kc], b0);
                mma16816h(sacc[2 * kg + 1], qa[kc], b1);
            }
        }

        if (kt == nkt - 1) {
            #pragma unroll
            for (int j = 0; j < 16; j++) {
                int col = kt * 128 + j * 8 + tig * 2;
                if (col > row0)     sacc[j][0] = -1e30f;
                if (col + 1 > row0) sacc[j][1] = -1e30f;
                if (col > row1)     sacc[j][2] = -1e30f;
                if (col + 1 > row1) sacc[j][3] = -1e30f;
            }
        }

        float mx0 = -1e30f, mx1 = -1e30f;
        #pragma unroll
        for (int j = 0; j < 16; j++) {
            mx0 = fmaxf(mx0, fmaxf(sacc[j][0], sacc[j][1]));
            mx1 = fmaxf(mx1, fmaxf(sacc[j][2], sacc[j][3]));
        }
        mx0 = fmaxf(mx0, __shfl_xor_sync(0xffffffffu, mx0, 1));
        mx0 = fmaxf(mx0, __shfl_xor_sync(0xffffffffu, mx0, 2));
        mx1 = fmaxf(mx1, __shfl_xor_sync(0xffffffffu, mx1, 1));
        mx1 = fmaxf(mx1, __shfl_xor_sync(0xffffffffu, mx1, 2));

        float nm0 = fmaxf(m0, mx0), nm1 = fmaxf(m1, mx1);
        float al0 = exp2f(m0 - nm0), al1 = exp2f(m1 - nm1);
        m0 = nm0; m1 = nm1;

        float rs0 = 0.f, rs1 = 0.f;
        #pragma unroll
        for (int j = 0; j < 16; j++) {
            sacc[j][0] = exp2f(sacc[j][0] - nm0);
            sacc[j][1] = exp2f(sacc[j][1] - nm0);
            sacc[j][2] = exp2f(sacc[j][2] - nm1);
            sacc[j][3] = exp2f(sacc[j][3] - nm1);
            rs0 += sacc[j][0] + sacc[j][1];
            rs1 += sacc[j][2] + sacc[j][3];
        }
        rs0 += __shfl_xor_sync(0xffffffffu, rs0, 1);
        rs0 += __shfl_xor_sync(0xffffffffu, rs0, 2);
        rs1 += __shfl_xor_sync(0xffffffffu, rs1, 1);
        rs1 += __shfl_xor_sync(0xffffffffu, rs1, 2);
        l0 = l0 * al0 + rs0;
        l1 = l1 * al1 + rs1;
        #pragma unroll
        for (int j = 0; j < 8; j++) {
            oacc[j][0] *= al0; oacc[j][1] *= al0;
            oacc[j][2] *= al1; oacc[j][3] *= al1;
        }

        uint32_t pa[8][4];
        #pragma unroll
        for (int kc = 0; kc < 8; kc++) {
            int j0 = 2 * kc, j1 = 2 * kc + 1;
            pa[kc][0] = packh2(sacc[j0][0], sacc[j0][1]);
            pa[kc][1] = packh2(sacc[j0][2], sacc[j0][3]);
            pa[kc][2] = packh2(sacc[j1][0], sacc[j1][1]);
            pa[kc][3] = packh2(sacc[j1][2], sacc[j1][3]);
        }

        #pragma unroll
        for (int kc = 0; kc < 8; kc++) {
            #pragma unroll
            for (int jj = 0; jj < 4; jj++) {
                uint32_t off = (uint32_t)((kc * 16 + (g8 & 1) * 8 + l8) * 144 +
                                          (jj * 16 + (g8 >> 1) * 8) * 2);
                uint32_t vb[4];
                ldsm_x4_t(vb, buf + V_OFF + off);
                uint32_t b0[2] = {vb[0], vb[1]}, b1[2] = {vb[2], vb[3]};
                mma16816h(oacc[2 * jj],     pa[kc], b0);
                mma16816h(oacc[2 * jj + 1], pa[kc], b1);
            }
        }
        __syncthreads();
    }

    float i0 = 1.0f / l0, i1 = 1.0f / l1;
    #pragma unroll
    for (int j = 0; j < 8; j++) {
        int col = h * HD + j * 8 + tig * 2;
        float o0 = oacc[j][0] * i0, o1 = oacc[j][1] * i0;
        float o2 = oacc[j][2] * i1, o3 = oacc[j][3] * i1;
        *(uint32_t*)&Aout[(size_t)row0 * HID + col] = packh2(o0, o1);
        *(uint32_t*)&Aout[(size_t)row1 * HID + col] = packh2(o2, o3);
    }
}

// ---------------- launch ----------------
extern "C" void kernel_launch(void* const* d_in, const int* in_sizes, int n_in,
                              void* d_out, int out_size)
{
    const float* X   = (const float*)d_in[0];
    const int*   pid = (const int*)d_in[2];
    const float* Wq  = (const float*)d_in[3];
    const float* Wk  = (const float*)d_in[4];
    const float* Wv  = (const float*)d_in[5];
    const float* Wo  = (const float*)d_in[6];
    float* out = (float*)d_out;

    __half *Xh, *Wqkv, *Wo16, *A16, *q16, *k16, *v16;
    cudaGetSymbolAddress((void**)&Xh,   g_Xh16);
    cudaGetSymbolAddress((void**)&Wqkv, g_Wqkv16);
    cudaGetSymbolAddress((void**)&Wo16, g_Wo16);
    cudaGetSymbolAddress((void**)&A16,  g_A16);
    cudaGetSymbolAddress((void**)&q16,  g_q16);
    cudaGetSymbolAddress((void**)&k16,  g_k16);
    cudaGetSymbolAddress((void**)&v16,  g_v16);

    cudaFuncSetAttribute(qkv_gemm,  cudaFuncAttributeMaxDynamicSharedMemorySize, QKV_SMEM);
    cudaFuncSetAttribute(oproj_gemm,cudaFuncAttributeMaxDynamicSharedMemorySize, GEMM_SMEM_F16);
    cudaFuncSetAttribute(attn_tc,   cudaFuncAttributeMaxDynamicSharedMemorySize, ATTN_SMEM);

    {
        int total = 2 * N8X + N8QW;
        cvt_all_v4<<<(total + 255) / 256, 256>>>(X, Xh, Wo, Wo16, Wq, Wk, Wv, Wqkv);
    }

    qkv_gemm<<<dim3(NQKV / QBN, S_LEN / QBM), 192, QKV_SMEM>>>(
        Xh, Wqkv, pid, q16, k16, v16);

    attn_tc<<<dim3(32, NH), 128, ATTN_SMEM>>>(q16, k16, v16, A16);

    oproj_gemm<<<dim3(HID / BN, S_LEN / BM), 128, GEMM_SMEM_F16>>>(
        A16, Wo16, out);
}